// round 4
// baseline (speedup 1.0000x reference)
#include <cuda_runtime.h>
#include <cuda_bf16.h>
#include <math.h>
#include <stdint.h>

// ---------------------------------------------------------------------------
// MiniTransformer forward: B=16, T=1024, D=512, H=8, HS=64, L=6, FF=2048, V=96
// Output: logits [16384, 96] (fp32) followed by scalar loss.
// ---------------------------------------------------------------------------

#define B_   16
#define T_   1024
#define D_   512
#define H_   8
#define HS_  64
#define L_   6
#define FF_  2048
#define V_   96
#define BT_  (B_ * T_)

// ------------------------- device scratch (no mallocs) ---------------------
__device__ float  g_x   [BT_ * D_];        // residual stream
__device__ float  g_h   [BT_ * D_];        // LN output
__device__ float  g_qkv [BT_ * 3 * D_];    // packed q|k|v per token
__device__ float  g_o   [BT_ * D_];        // attention output (concat heads)
__device__ float  g_ff  [BT_ * FF_];       // FFN hidden
__device__ float  g_wp  [L_ * D_ * 3 * D_];// packed QKV weights [l][d][3D]
__device__ double g_loss;

// ------------------------- small kernels -----------------------------------
__global__ void zero_loss_kernel(double* a) { *a = 0.0; }

__global__ void pack_qkv_kernel(const float* __restrict__ Wq,
                                const float* __restrict__ Wk,
                                const float* __restrict__ Wv,
                                float* __restrict__ out) {
    int i = blockIdx.x * blockDim.x + threadIdx.x;       // over L*D*3D
    if (i >= L_ * D_ * 3 * D_) return;
    int c = i % (3 * D_);
    int d = (i / (3 * D_)) % D_;
    int l = i / (3 * D_ * D_);
    int sel = c >> 9;              // 0=q 1=k 2=v (512 cols each)
    int hk  = c & 511;
    int h   = hk >> 6;
    int k   = hk & 63;
    const float* W = (sel == 0) ? Wq : (sel == 1) ? Wk : Wv;
    out[i] = W[(((size_t)l * H_ + h) * D_ + d) * HS_ + k];
}

__global__ void embed_kernel(const int* __restrict__ idx,
                             const float* __restrict__ tok,
                             const float* __restrict__ pos,
                             float* __restrict__ x) {
    int i = blockIdx.x * blockDim.x + threadIdx.x;       // over BT*D
    if (i >= BT_ * D_) return;
    int d  = i & (D_ - 1);
    int bt = i >> 9;
    int t  = bt & (T_ - 1);
    x[i] = tok[(size_t)idx[bt] * D_ + d] + pos[t * D_ + d];
}

// One block per row; D=512, 256 threads, 2 elems/thread.
__global__ __launch_bounds__(256) void ln_kernel(const float* __restrict__ x,
                                                 const float* __restrict__ s,
                                                 const float* __restrict__ b,
                                                 float* __restrict__ out) {
    int row = blockIdx.x;
    int t   = threadIdx.x;
    const float* xr = x + (size_t)row * D_;
    float v0 = xr[t], v1 = xr[t + 256];

    float sum = v0 + v1;
    #pragma unroll
    for (int o = 16; o; o >>= 1) sum += __shfl_xor_sync(0xffffffffu, sum, o);
    __shared__ float red1[8], red2[8];
    if ((t & 31) == 0) red1[t >> 5] = sum;
    __syncthreads();
    float mean = 0.f;
    #pragma unroll
    for (int i = 0; i < 8; i++) mean += red1[i];
    mean *= (1.0f / D_);

    float d0 = v0 - mean, d1 = v1 - mean;
    float vs = d0 * d0 + d1 * d1;
    #pragma unroll
    for (int o = 16; o; o >>= 1) vs += __shfl_xor_sync(0xffffffffu, vs, o);
    if ((t & 31) == 0) red2[t >> 5] = vs;
    __syncthreads();
    float var = 0.f;
    #pragma unroll
    for (int i = 0; i < 8; i++) var += red2[i];
    var *= (1.0f / D_);

    float inv = rsqrtf(var + 1e-5f);
    float* orow = out + (size_t)row * D_;
    orow[t]       = d0 * inv * s[t]       + b[t];
    orow[t + 256] = d1 * inv * s[t + 256] + b[t + 256];
}

// ------------------------- TF32 tensor-core GEMM ---------------------------
// C[M,N] = A[M,K] * B[K,N]  (+bias, +relu, +residual per `mode`)
// mode: 0 = none, 1 = +bias, 2 = +bias,relu, 3 = +bias,+res
// 128x128 tile, BK=16, 256 threads = 8 warps, warp tile 64(m) x 32(n).
// mma.sync.m16n8k8 tf32, fp32 accumulate.
// Requires M % 128 == 0, K % 16 == 0. N guarded.
#define GBK 16
#define ASTR 20    // A smem stride (m-major rows of K): banks (m*20+k)%32 distinct
#define BSTR 136   // B smem stride (k-major rows of N): banks (k*8+n)%32 distinct

__device__ __forceinline__ uint32_t f2tf32(float f) {
    uint32_t r;
    asm("cvt.rna.tf32.f32 %0, %1;" : "=r"(r) : "f"(f));
    return r;
}

__device__ __forceinline__ void mma_tf32(float* d, const uint32_t* a, const uint32_t* b) {
    asm volatile(
        "mma.sync.aligned.m16n8k8.row.col.f32.tf32.tf32.f32 "
        "{%0,%1,%2,%3}, {%4,%5,%6,%7}, {%8,%9}, {%0,%1,%2,%3};"
        : "+f"(d[0]), "+f"(d[1]), "+f"(d[2]), "+f"(d[3])
        : "r"(a[0]), "r"(a[1]), "r"(a[2]), "r"(a[3]), "r"(b[0]), "r"(b[1]));
}

__global__ __launch_bounds__(256) void tgemm_kernel(
    const float* __restrict__ A, const float* __restrict__ Bm,
    const float* __restrict__ bias, const float* __restrict__ res,
    float* __restrict__ C, int M, int N, int K, int mode)
{
    __shared__ uint32_t As[2][128][ASTR];   // [m][k] as tf32 bits
    __shared__ uint32_t Bs[2][GBK][BSTR];   // [k][n] as tf32 bits

    int tid  = threadIdx.x;
    int wid  = tid >> 5;
    int lane = tid & 31;
    int grp  = lane >> 2;          // 0..7
    int tig  = lane & 3;           // 0..3
    int warp_m = (wid & 1) * 64;   // 0 or 64
    int warp_n = (wid >> 1) * 32;  // 0,32,64,96

    // A gmem loads: 128 rows x 16 cols = 512 float4; 2/thread
    int arow = tid >> 2;           // 0..63 (+64)
    int acol = (tid & 3) << 2;     // 0,4,8,12
    // B gmem loads: 16 rows x 128 cols = 512 float4; 2/thread
    int brow = tid >> 5;           // 0..7 (+8)
    int bcol = (tid & 31) << 2;    // 0..124

    const float* Ap  = A + (size_t)(blockIdx.y * 128 + arow) * K + acol;
    const float* Ap2 = Ap + (size_t)64 * K;
    int gbc = blockIdx.x * 128 + bcol;

    float acc[4][4][4];
    #pragma unroll
    for (int i = 0; i < 4; i++)
        #pragma unroll
        for (int j = 0; j < 4; j++)
            #pragma unroll
            for (int r = 0; r < 4; r++) acc[i][j][r] = 0.f;

    float4 pa0, pa1, pb0, pb1;

    // load stage 0 into regs
    pa0 = *(const float4*)(Ap);
    pa1 = *(const float4*)(Ap2);
    {
        const float* Bp0 = Bm + (size_t)brow * N;
        const float* Bp1 = Bm + (size_t)(brow + 8) * N;
        if (gbc + 3 < N) {
            pb0 = *(const float4*)(Bp0 + gbc);
            pb1 = *(const float4*)(Bp1 + gbc);
        } else {
            pb0 = make_float4(0.f, 0.f, 0.f, 0.f);
            pb1 = make_float4(0.f, 0.f, 0.f, 0.f);
            if (gbc + 0 < N) { pb0.x = Bp0[gbc + 0]; pb1.x = Bp1[gbc + 0]; }
            if (gbc + 1 < N) { pb0.y = Bp0[gbc + 1]; pb1.y = Bp1[gbc + 1]; }
            if (gbc + 2 < N) { pb0.z = Bp0[gbc + 2]; pb1.z = Bp1[gbc + 2]; }
        }
    }
    // store stage 0 (cvt to tf32)
    {
        As[0][arow][acol + 0] = f2tf32(pa0.x); As[0][arow][acol + 1] = f2tf32(pa0.y);
        As[0][arow][acol + 2] = f2tf32(pa0.z); As[0][arow][acol + 3] = f2tf32(pa0.w);
        As[0][arow + 64][acol + 0] = f2tf32(pa1.x); As[0][arow + 64][acol + 1] = f2tf32(pa1.y);
        As[0][arow + 64][acol + 2] = f2tf32(pa1.z); As[0][arow + 64][acol + 3] = f2tf32(pa1.w);
        Bs[0][brow][bcol + 0] = f2tf32(pb0.x); Bs[0][brow][bcol + 1] = f2tf32(pb0.y);
        Bs[0][brow][bcol + 2] = f2tf32(pb0.z); Bs[0][brow][bcol + 3] = f2tf32(pb0.w);
        Bs[0][brow + 8][bcol + 0] = f2tf32(pb1.x); Bs[0][brow + 8][bcol + 1] = f2tf32(pb1.y);
        Bs[0][brow + 8][bcol + 2] = f2tf32(pb1.z); Bs[0][brow + 8][bcol + 3] = f2tf32(pb1.w);
    }
    __syncthreads();

    int nstage = K / GBK;
    int cur = 0;
    for (int s = 0; s < nstage; s++) {
        // prefetch next stage into registers
        if (s + 1 < nstage) {
            int k0 = (s + 1) * GBK;
            pa0 = *(const float4*)(Ap + k0);
            pa1 = *(const float4*)(Ap2 + k0);
            const float* Bp0 = Bm + (size_t)(k0 + brow) * N;
            const float* Bp1 = Bm + (size_t)(k0 + brow + 8) * N;
            if (gbc + 3 < N) {
                pb0 = *(const float4*)(Bp0 + gbc);
                pb1 = *(const float4*)(Bp1 + gbc);
            } else {
                pb0 = make_float4(0.f, 0.f, 0.f, 0.f);
                pb1 = make_float4(0.f, 0.f, 0.f, 0.f);
                if (gbc + 0 < N) { pb0.x = Bp0[gbc + 0]; pb1.x = Bp1[gbc + 0]; }
                if (gbc + 1 < N) { pb0.y = Bp0[gbc + 1]; pb1.y = Bp1[gbc + 1]; }
                if (gbc + 2 < N) { pb0.z = Bp0[gbc + 2]; pb1.z = Bp1[gbc + 2]; }
            }
        }

        // compute: 2 k8-steps, 4 m-subtiles x 4 n-subtiles
        #pragma unroll
        for (int ks = 0; ks < 2; ks++) {
            int k0 = ks * 8;
            uint32_t af[4][4];
            #pragma unroll
            for (int i = 0; i < 4; i++) {
                int mrow = warp_m + i * 16 + grp;
                af[i][0] = As[cur][mrow][k0 + tig];
                af[i][1] = As[cur][mrow + 8][k0 + tig];
                af[i][2] = As[cur][mrow][k0 + tig + 4];
                af[i][3] = As[cur][mrow + 8][k0 + tig + 4];
            }
            uint32_t bf[4][2];
            #pragma unroll
            for (int j = 0; j < 4; j++) {
                int ncol = warp_n + j * 8 + grp;
                bf[j][0] = Bs[cur][k0 + tig][ncol];
                bf[j][1] = Bs[cur][k0 + tig + 4][ncol];
            }
            #pragma unroll
            for (int i = 0; i < 4; i++)
                #pragma unroll
                for (int j = 0; j < 4; j++)
                    mma_tf32(acc[i][j], af[i], bf[j]);
        }

        // store prefetched regs into the other buffer
        if (s + 1 < nstage) {
            int nxt = cur ^ 1;
            As[nxt][arow][acol + 0] = f2tf32(pa0.x); As[nxt][arow][acol + 1] = f2tf32(pa0.y);
            As[nxt][arow][acol + 2] = f2tf32(pa0.z); As[nxt][arow][acol + 3] = f2tf32(pa0.w);
            As[nxt][arow + 64][acol + 0] = f2tf32(pa1.x); As[nxt][arow + 64][acol + 1] = f2tf32(pa1.y);
            As[nxt][arow + 64][acol + 2] = f2tf32(pa1.z); As[nxt][arow + 64][acol + 3] = f2tf32(pa1.w);
            Bs[nxt][brow][bcol + 0] = f2tf32(pb0.x); Bs[nxt][brow][bcol + 1] = f2tf32(pb0.y);
            Bs[nxt][brow][bcol + 2] = f2tf32(pb0.z); Bs[nxt][brow][bcol + 3] = f2tf32(pb0.w);
            Bs[nxt][brow + 8][bcol + 0] = f2tf32(pb1.x); Bs[nxt][brow + 8][bcol + 1] = f2tf32(pb1.y);
            Bs[nxt][brow + 8][bcol + 2] = f2tf32(pb1.z); Bs[nxt][brow + 8][bcol + 3] = f2tf32(pb1.w);
            __syncthreads();
            cur = nxt;
        }
    }

    // epilogue
    #pragma unroll
    for (int i = 0; i < 4; i++) {
        int row0 = blockIdx.y * 128 + warp_m + i * 16 + grp;
        #pragma unroll
        for (int j = 0; j < 4; j++) {
            int col = blockIdx.x * 128 + warp_n + j * 8 + 2 * tig;
            if (col < N) {
                #pragma unroll
                for (int half = 0; half < 2; half++) {
                    int r = row0 + half * 8;
                    size_t rb = (size_t)r * N;
                    float v0 = acc[i][j][half * 2 + 0];
                    float v1 = acc[i][j][half * 2 + 1];
                    if (mode >= 1) { v0 += bias[col]; v1 += bias[col + 1]; }
                    if (mode == 2) { v0 = fmaxf(v0, 0.f); v1 = fmaxf(v1, 0.f); }
                    if (mode == 3) { v0 += res[rb + col]; v1 += res[rb + col + 1]; }
                    *(float2*)(C + rb + col) = make_float2(v0, v1);
                }
            }
        }
    }
}

// ------------------------- flash attention ---------------------------------
// QKV [BT, 1536] per-token q|k|v; heads at h*64 within each 512 chunk.
// grid: (T/128, B*H), block 256 threads: 2 threads per query (each 32 dims).
#define AKT 32
#define KSTR 68

__global__ __launch_bounds__(256) void attn_kernel(const float* __restrict__ QKV,
                                                   float* __restrict__ O) {
    int b = blockIdx.y >> 3;
    int h = blockIdx.y & 7;
    int tid = threadIdx.x;
    int ql   = tid >> 1;            // 0..127 local query
    int half = tid & 1;             // dim half
    int q_idx = blockIdx.x * 128 + ql;
    const float scale = 0.04419417382415922f;  // 1/sqrt(512)

    const float* qrow = QKV + ((size_t)(b * T_ + q_idx)) * (3 * D_) + h * HS_ + half * 32;
    float q[32];
    #pragma unroll
    for (int d = 0; d < 32; d++) q[d] = qrow[d] * scale;
    float o[32];
    #pragma unroll
    for (int d = 0; d < 32; d++) o[d] = 0.f;
    float m = -1e30f, l = 0.f;

    __shared__ float Ks[AKT][KSTR];
    __shared__ float Vs[AKT][KSTR];

    int kend = blockIdx.x * 128 + 128;
    for (int k0 = 0; k0 < kend; k0 += AKT) {
        __syncthreads();
        for (int i = tid; i < AKT * (HS_ / 4); i += 256) {
            int r = i >> 4, c = (i & 15) << 2;
            const float* base = QKV + ((size_t)(b * T_ + k0 + r)) * (3 * D_) + h * HS_ + c;
            *(float4*)&Ks[r][c] = *(const float4*)(base + D_);
            *(float4*)&Vs[r][c] = *(const float4*)(base + 2 * D_);
        }
        __syncthreads();

        float s[AKT];
        float mnew = m;
        #pragma unroll
        for (int j = 0; j < AKT; j++) {
            float acc = 0.f;
            const float* kr = &Ks[j][half * 32];
            #pragma unroll
            for (int d = 0; d < 32; d++) acc += q[d] * kr[d];
            acc += __shfl_xor_sync(0xffffffffu, acc, 1);
            s[j] = (k0 + j <= q_idx) ? acc : -1e30f;
            mnew = fmaxf(mnew, s[j]);
        }
        float corr = __expf(m - mnew);
        l *= corr;
        #pragma unroll
        for (int d = 0; d < 32; d++) o[d] *= corr;
        #pragma unroll
        for (int j = 0; j < AKT; j++) {
            float p = __expf(s[j] - mnew);
            l += p;
            const float* vr = &Vs[j][half * 32];
            #pragma unroll
            for (int d = 0; d < 32; d++) o[d] += p * vr[d];
        }
        m = mnew;
    }

    float inv = 1.f / l;
    float* orow = O + ((size_t)(b * T_ + q_idx)) * D_ + h * HS_ + half * 32;
    #pragma unroll
    for (int d = 0; d < 32; d++) orow[d] = o[d] * inv;
}

// ------------------------- loss --------------------------------------------
// One warp per row of logits [BT, 96]; 3 values/lane.
__global__ __launch_bounds__(256) void loss_kernel(const float* __restrict__ logits,
                                                   const int* __restrict__ targets,
                                                   double* __restrict__ acc) {
    int warp = (blockIdx.x * blockDim.x + threadIdx.x) >> 5;
    int lane = threadIdx.x & 31;
    const float* lr = logits + (size_t)warp * V_;
    float v0 = lr[lane], v1 = lr[lane + 32], v2 = lr[lane + 64];
    float m = fmaxf(v0, fmaxf(v1, v2));
    #pragma unroll
    for (int o = 16; o; o >>= 1) m = fmaxf(m, __shfl_xor_sync(0xffffffffu, m, o));
    float se = expf(v0 - m) + expf(v1 - m) + expf(v2 - m);
    #pragma unroll
    for (int o = 16; o; o >>= 1) se += __shfl_xor_sync(0xffffffffu, se, o);

    __shared__ float part[8];
    if (lane == 0) part[threadIdx.x >> 5] = lr[targets[warp]] - m - logf(se);
    __syncthreads();
    if (threadIdx.x == 0) {
        float s = 0.f;
        #pragma unroll
        for (int i = 0; i < 8; i++) s += part[i];
        atomicAdd(acc, (double)s);
    }
}

__global__ void finalize_loss_kernel(float* out, const double* acc) {
    out[(size_t)BT_ * V_] = (float)(-(*acc) / (double)BT_);
}

// ------------------------- launcher ----------------------------------------
extern "C" void kernel_launch(void* const* d_in, const int* in_sizes, int n_in,
                              void* d_out, int out_size) {
    const int*   idx     = (const int*)  d_in[0];
    const int*   targets = (const int*)  d_in[1];
    const float* tok     = (const float*)d_in[2];
    const float* pos     = (const float*)d_in[3];
    const float* Wq      = (const float*)d_in[4];
    const float* Wk      = (const float*)d_in[5];
    const float* Wv      = (const float*)d_in[6];
    const float* Wproj   = (const float*)d_in[7];
    const float* bproj   = (const float*)d_in[8];
    const float* W1      = (const float*)d_in[9];
    const float* b1      = (const float*)d_in[10];
    const float* W2      = (const float*)d_in[11];
    const float* b2      = (const float*)d_in[12];
    const float* ln1_s   = (const float*)d_in[13];
    const float* ln1_b   = (const float*)d_in[14];
    const float* ln2_s   = (const float*)d_in[15];
    const float* ln2_b   = (const float*)d_in[16];
    const float* lnf_s   = (const float*)d_in[17];
    const float* lnf_b   = (const float*)d_in[18];
    const float* Wout    = (const float*)d_in[19];
    const float* bout    = (const float*)d_in[20];
    float* out = (float*)d_out;

    float *x, *h, *qkv, *o, *ff, *wp;
    double* lossAcc;
    cudaGetSymbolAddress((void**)&x,   g_x);
    cudaGetSymbolAddress((void**)&h,   g_h);
    cudaGetSymbolAddress((void**)&qkv, g_qkv);
    cudaGetSymbolAddress((void**)&o,   g_o);
    cudaGetSymbolAddress((void**)&ff,  g_ff);
    cudaGetSymbolAddress((void**)&wp,  g_wp);
    cudaGetSymbolAddress((void**)&lossAcc, g_loss);

    // pack QKV weights: [L][H][D][HS] -> [L][D][3D]
    {
        int total = L_ * D_ * 3 * D_;
        pack_qkv_kernel<<<(total + 255) / 256, 256>>>(Wq, Wk, Wv, wp);
    }
    // embedding
    {
        int total = BT_ * D_;
        embed_kernel<<<(total + 255) / 256, 256>>>(idx, tok, pos, x);
    }

    const int MT = BT_ / 128;  // 128 M-tiles
    for (int l = 0; l < L_; l++) {
        // LN1
        ln_kernel<<<BT_, 256>>>(x, ln1_s + l * D_, ln1_b + l * D_, h);
        // QKV: [BT,512] x [512,1536]
        tgemm_kernel<<<dim3(12, MT), 256>>>(h, wp + (size_t)l * D_ * 3 * D_,
                                            nullptr, nullptr, qkv,
                                            BT_, 3 * D_, D_, 0);
        // attention
        attn_kernel<<<dim3(T_ / 128, B_ * H_), 256>>>(qkv, o);
        // proj + bias + residual into x
        tgemm_kernel<<<dim3(4, MT), 256>>>(o, Wproj + (size_t)l * D_ * D_,
                                           bproj + l * D_, x, x,
                                           BT_, D_, D_, 3);
        // LN2
        ln_kernel<<<BT_, 256>>>(x, ln2_s + l * D_, ln2_b + l * D_, h);
        // FF1 + bias + relu
        tgemm_kernel<<<dim3(16, MT), 256>>>(h, W1 + (size_t)l * D_ * FF_,
                                            b1 + l * FF_, nullptr, ff,
                                            BT_, FF_, D_, 2);
        // FF2 + bias + residual into x
        tgemm_kernel<<<dim3(4, MT), 256>>>(ff, W2 + (size_t)l * FF_ * D_,
                                           b2 + l * D_, x, x,
                                           BT_, D_, FF_, 3);
    }

    // final LN
    ln_kernel<<<BT_, 256>>>(x, lnf_s, lnf_b, h);
    // logits: [BT,512] x [512,96] + bout -> d_out
    tgemm_kernel<<<dim3(1, MT), 256>>>(h, Wout, bout, nullptr, out,
                                       BT_, V_, D_, 1);

    // loss
    if (out_size > BT_ * V_) {
        zero_loss_kernel<<<1, 1>>>(lossAcc);
        loss_kernel<<<BT_ / 8, 256>>>(out, targets, lossAcc);
        finalize_loss_kernel<<<1, 1>>>(out, lossAcc);
    }
}

// round 5
// speedup vs baseline: 1.0314x; 1.0314x over previous
#include <cuda_runtime.h>
#include <cuda_bf16.h>
#include <math.h>
#include <stdint.h>

// ---------------------------------------------------------------------------
// MiniTransformer forward: B=16, T=1024, D=512, H=8, HS=64, L=6, FF=2048, V=96
// Output: logits [16384, 96] (fp32) followed by scalar loss.
// ---------------------------------------------------------------------------

#define B_   16
#define T_   1024
#define D_   512
#define H_   8
#define HS_  64
#define L_   6
#define FF_  2048
#define V_   96
#define BT_  (B_ * T_)

// ------------------------- device scratch (no mallocs) ---------------------
__device__ float  g_x   [BT_ * D_];        // residual stream
__device__ float  g_h   [BT_ * D_];        // LN output
__device__ float  g_qkv [BT_ * 3 * D_];    // packed q|k|v per token
__device__ float  g_o   [BT_ * D_];        // attention output (concat heads)
__device__ float  g_ff  [BT_ * FF_];       // FFN hidden
__device__ float  g_wp  [L_ * D_ * 3 * D_];// packed QKV weights [l][d][3D]
__device__ double g_loss;

// ------------------------- f32x2 packed math (sm_103a FFMA2) ---------------
typedef unsigned long long ull_t;

__device__ __forceinline__ ull_t pack2(float lo, float hi) {
    ull_t r;
    asm("mov.b64 %0, {%1, %2};" : "=l"(r) : "f"(lo), "f"(hi));
    return r;
}
__device__ __forceinline__ void unpack2(ull_t v, float& lo, float& hi) {
    asm("mov.b64 {%0, %1}, %2;" : "=f"(lo), "=f"(hi) : "l"(v));
}
__device__ __forceinline__ ull_t fma2(ull_t a, ull_t b, ull_t c) {
    ull_t d;
    asm("fma.rn.f32x2 %0, %1, %2, %3;" : "=l"(d) : "l"(a), "l"(b), "l"(c));
    return d;
}
__device__ __forceinline__ ull_t mul2(ull_t a, ull_t b) {
    ull_t d;
    asm("mul.rn.f32x2 %0, %1, %2;" : "=l"(d) : "l"(a), "l"(b));
    return d;
}

// ------------------------- small kernels -----------------------------------
__global__ void zero_loss_kernel(double* a) { *a = 0.0; }

__global__ void pack_qkv_kernel(const float* __restrict__ Wq,
                                const float* __restrict__ Wk,
                                const float* __restrict__ Wv,
                                float* __restrict__ out) {
    int i = blockIdx.x * blockDim.x + threadIdx.x;       // over L*D*3D
    if (i >= L_ * D_ * 3 * D_) return;
    int c = i % (3 * D_);
    int d = (i / (3 * D_)) % D_;
    int l = i / (3 * D_ * D_);
    int sel = c >> 9;              // 0=q 1=k 2=v (512 cols each)
    int hk  = c & 511;
    int h   = hk >> 6;
    int k   = hk & 63;
    const float* W = (sel == 0) ? Wq : (sel == 1) ? Wk : Wv;
    out[i] = W[(((size_t)l * H_ + h) * D_ + d) * HS_ + k];
}

__global__ void embed_kernel(const int* __restrict__ idx,
                             const float* __restrict__ tok,
                             const float* __restrict__ pos,
                             float* __restrict__ x) {
    int i = blockIdx.x * blockDim.x + threadIdx.x;       // over BT*D
    if (i >= BT_ * D_) return;
    int d  = i & (D_ - 1);
    int bt = i >> 9;
    int t  = bt & (T_ - 1);
    x[i] = tok[(size_t)idx[bt] * D_ + d] + pos[t * D_ + d];
}

// One block per row; D=512, 256 threads, 2 elems/thread.
__global__ __launch_bounds__(256) void ln_kernel(const float* __restrict__ x,
                                                 const float* __restrict__ s,
                                                 const float* __restrict__ b,
                                                 float* __restrict__ out) {
    int row = blockIdx.x;
    int t   = threadIdx.x;
    const float* xr = x + (size_t)row * D_;
    float v0 = xr[t], v1 = xr[t + 256];

    float sum = v0 + v1;
    #pragma unroll
    for (int o = 16; o; o >>= 1) sum += __shfl_xor_sync(0xffffffffu, sum, o);
    __shared__ float red1[8], red2[8];
    if ((t & 31) == 0) red1[t >> 5] = sum;
    __syncthreads();
    float mean = 0.f;
    #pragma unroll
    for (int i = 0; i < 8; i++) mean += red1[i];
    mean *= (1.0f / D_);

    float d0 = v0 - mean, d1 = v1 - mean;
    float vs = d0 * d0 + d1 * d1;
    #pragma unroll
    for (int o = 16; o; o >>= 1) vs += __shfl_xor_sync(0xffffffffu, vs, o);
    if ((t & 31) == 0) red2[t >> 5] = vs;
    __syncthreads();
    float var = 0.f;
    #pragma unroll
    for (int i = 0; i < 8; i++) var += red2[i];
    var *= (1.0f / D_);

    float inv = rsqrtf(var + 1e-5f);
    float* orow = out + (size_t)row * D_;
    orow[t]       = d0 * inv * s[t]       + b[t];
    orow[t + 256] = d1 * inv * s[t + 256] + b[t + 256];
}

// ------------------------- TF32 tensor-core GEMM ---------------------------
// C[M,N] = A[M,K] * B[K,N]  (+bias, +relu, +residual per `mode`)
// mode: 0 = none, 1 = +bias, 2 = +bias,relu, 3 = +bias,+res
// 128x128 tile, BK=16, 256 threads = 8 warps, warp tile 64(m) x 32(n).
#define GBK 16
#define ASTR 20
#define BSTR 136

__device__ __forceinline__ uint32_t f2tf32(float f) {
    uint32_t r;
    asm("cvt.rna.tf32.f32 %0, %1;" : "=r"(r) : "f"(f));
    return r;
}

__device__ __forceinline__ void mma_tf32(float* d, const uint32_t* a, const uint32_t* b) {
    asm volatile(
        "mma.sync.aligned.m16n8k8.row.col.f32.tf32.tf32.f32 "
        "{%0,%1,%2,%3}, {%4,%5,%6,%7}, {%8,%9}, {%0,%1,%2,%3};"
        : "+f"(d[0]), "+f"(d[1]), "+f"(d[2]), "+f"(d[3])
        : "r"(a[0]), "r"(a[1]), "r"(a[2]), "r"(a[3]), "r"(b[0]), "r"(b[1]));
}

__global__ __launch_bounds__(256) void tgemm_kernel(
    const float* __restrict__ A, const float* __restrict__ Bm,
    const float* __restrict__ bias, const float* __restrict__ res,
    float* __restrict__ C, int M, int N, int K, int mode)
{
    __shared__ uint32_t As[2][128][ASTR];   // [m][k] as tf32 bits
    __shared__ uint32_t Bs[2][GBK][BSTR];   // [k][n] as tf32 bits

    int tid  = threadIdx.x;
    int wid  = tid >> 5;
    int lane = tid & 31;
    int grp  = lane >> 2;          // 0..7
    int tig  = lane & 3;           // 0..3
    int warp_m = (wid & 1) * 64;   // 0 or 64
    int warp_n = (wid >> 1) * 32;  // 0,32,64,96

    int arow = tid >> 2;           // 0..63 (+64)
    int acol = (tid & 3) << 2;     // 0,4,8,12
    int brow = tid >> 5;           // 0..7 (+8)
    int bcol = (tid & 31) << 2;    // 0..124

    const float* Ap  = A + (size_t)(blockIdx.y * 128 + arow) * K + acol;
    const float* Ap2 = Ap + (size_t)64 * K;
    int gbc = blockIdx.x * 128 + bcol;

    float acc[4][4][4];
    #pragma unroll
    for (int i = 0; i < 4; i++)
        #pragma unroll
        for (int j = 0; j < 4; j++)
            #pragma unroll
            for (int r = 0; r < 4; r++) acc[i][j][r] = 0.f;

    float4 pa0, pa1, pb0, pb1;

    pa0 = *(const float4*)(Ap);
    pa1 = *(const float4*)(Ap2);
    {
        const float* Bp0 = Bm + (size_t)brow * N;
        const float* Bp1 = Bm + (size_t)(brow + 8) * N;
        if (gbc + 3 < N) {
            pb0 = *(const float4*)(Bp0 + gbc);
            pb1 = *(const float4*)(Bp1 + gbc);
        } else {
            pb0 = make_float4(0.f, 0.f, 0.f, 0.f);
            pb1 = make_float4(0.f, 0.f, 0.f, 0.f);
            if (gbc + 0 < N) { pb0.x = Bp0[gbc + 0]; pb1.x = Bp1[gbc + 0]; }
            if (gbc + 1 < N) { pb0.y = Bp0[gbc + 1]; pb1.y = Bp1[gbc + 1]; }
            if (gbc + 2 < N) { pb0.z = Bp0[gbc + 2]; pb1.z = Bp1[gbc + 2]; }
        }
    }
    {
        As[0][arow][acol + 0] = f2tf32(pa0.x); As[0][arow][acol + 1] = f2tf32(pa0.y);
        As[0][arow][acol + 2] = f2tf32(pa0.z); As[0][arow][acol + 3] = f2tf32(pa0.w);
        As[0][arow + 64][acol + 0] = f2tf32(pa1.x); As[0][arow + 64][acol + 1] = f2tf32(pa1.y);
        As[0][arow + 64][acol + 2] = f2tf32(pa1.z); As[0][arow + 64][acol + 3] = f2tf32(pa1.w);
        Bs[0][brow][bcol + 0] = f2tf32(pb0.x); Bs[0][brow][bcol + 1] = f2tf32(pb0.y);
        Bs[0][brow][bcol + 2] = f2tf32(pb0.z); Bs[0][brow][bcol + 3] = f2tf32(pb0.w);
        Bs[0][brow + 8][bcol + 0] = f2tf32(pb1.x); Bs[0][brow + 8][bcol + 1] = f2tf32(pb1.y);
        Bs[0][brow + 8][bcol + 2] = f2tf32(pb1.z); Bs[0][brow + 8][bcol + 3] = f2tf32(pb1.w);
    }
    __syncthreads();

    int nstage = K / GBK;
    int cur = 0;
    for (int s = 0; s < nstage; s++) {
        if (s + 1 < nstage) {
            int k0 = (s + 1) * GBK;
            pa0 = *(const float4*)(Ap + k0);
            pa1 = *(const float4*)(Ap2 + k0);
            const float* Bp0 = Bm + (size_t)(k0 + brow) * N;
            const float* Bp1 = Bm + (size_t)(k0 + brow + 8) * N;
            if (gbc + 3 < N) {
                pb0 = *(const float4*)(Bp0 + gbc);
                pb1 = *(const float4*)(Bp1 + gbc);
            } else {
                pb0 = make_float4(0.f, 0.f, 0.f, 0.f);
                pb1 = make_float4(0.f, 0.f, 0.f, 0.f);
                if (gbc + 0 < N) { pb0.x = Bp0[gbc + 0]; pb1.x = Bp1[gbc + 0]; }
                if (gbc + 1 < N) { pb0.y = Bp0[gbc + 1]; pb1.y = Bp1[gbc + 1]; }
                if (gbc + 2 < N) { pb0.z = Bp0[gbc + 2]; pb1.z = Bp1[gbc + 2]; }
            }
        }

        #pragma unroll
        for (int ks = 0; ks < 2; ks++) {
            int k0 = ks * 8;
            uint32_t af[4][4];
            #pragma unroll
            for (int i = 0; i < 4; i++) {
                int mrow = warp_m + i * 16 + grp;
                af[i][0] = As[cur][mrow][k0 + tig];
                af[i][1] = As[cur][mrow + 8][k0 + tig];
                af[i][2] = As[cur][mrow][k0 + tig + 4];
                af[i][3] = As[cur][mrow + 8][k0 + tig + 4];
            }
            uint32_t bf[4][2];
            #pragma unroll
            for (int j = 0; j < 4; j++) {
                int ncol = warp_n + j * 8 + grp;
                bf[j][0] = Bs[cur][k0 + tig][ncol];
                bf[j][1] = Bs[cur][k0 + tig + 4][ncol];
            }
            #pragma unroll
            for (int i = 0; i < 4; i++)
                #pragma unroll
                for (int j = 0; j < 4; j++)
                    mma_tf32(acc[i][j], af[i], bf[j]);
        }

        if (s + 1 < nstage) {
            int nxt = cur ^ 1;
            As[nxt][arow][acol + 0] = f2tf32(pa0.x); As[nxt][arow][acol + 1] = f2tf32(pa0.y);
            As[nxt][arow][acol + 2] = f2tf32(pa0.z); As[nxt][arow][acol + 3] = f2tf32(pa0.w);
            As[nxt][arow + 64][acol + 0] = f2tf32(pa1.x); As[nxt][arow + 64][acol + 1] = f2tf32(pa1.y);
            As[nxt][arow + 64][acol + 2] = f2tf32(pa1.z); As[nxt][arow + 64][acol + 3] = f2tf32(pa1.w);
            Bs[nxt][brow][bcol + 0] = f2tf32(pb0.x); Bs[nxt][brow][bcol + 1] = f2tf32(pb0.y);
            Bs[nxt][brow][bcol + 2] = f2tf32(pb0.z); Bs[nxt][brow][bcol + 3] = f2tf32(pb0.w);
            Bs[nxt][brow + 8][bcol + 0] = f2tf32(pb1.x); Bs[nxt][brow + 8][bcol + 1] = f2tf32(pb1.y);
            Bs[nxt][brow + 8][bcol + 2] = f2tf32(pb1.z); Bs[nxt][brow + 8][bcol + 3] = f2tf32(pb1.w);
            __syncthreads();
            cur = nxt;
        }
    }

    #pragma unroll
    for (int i = 0; i < 4; i++) {
        int row0 = blockIdx.y * 128 + warp_m + i * 16 + grp;
        #pragma unroll
        for (int j = 0; j < 4; j++) {
            int col = blockIdx.x * 128 + warp_n + j * 8 + 2 * tig;
            if (col < N) {
                #pragma unroll
                for (int half = 0; half < 2; half++) {
                    int r = row0 + half * 8;
                    size_t rb = (size_t)r * N;
                    float v0 = acc[i][j][half * 2 + 0];
                    float v1 = acc[i][j][half * 2 + 1];
                    if (mode >= 1) { v0 += bias[col]; v1 += bias[col + 1]; }
                    if (mode == 2) { v0 = fmaxf(v0, 0.f); v1 = fmaxf(v1, 0.f); }
                    if (mode == 3) { v0 += res[rb + col]; v1 += res[rb + col + 1]; }
                    *(float2*)(C + rb + col) = make_float2(v0, v1);
                }
            }
        }
    }
}

// ------------------------- flash attention (f32x2 packed) ------------------
// QKV [BT, 1536] per-token q|k|v; heads at h*64 within each 512 chunk.
// grid: (T/128, B*H), block 256 threads: 2 threads per query (32 dims each,
// held as 16 packed f32x2). Packed FFMA2 halves FFMA issue slots.
#define AKT 16
#define KSTR 68

__global__ __launch_bounds__(256, 2) void attn_kernel(const float* __restrict__ QKV,
                                                      float* __restrict__ O) {
    int b = blockIdx.y >> 3;
    int h = blockIdx.y & 7;
    int tid = threadIdx.x;
    int ql   = tid >> 1;            // 0..127 local query
    int half = tid & 1;             // dim half
    int qblock = blockIdx.x * 128;
    int q_idx = qblock + ql;
    const float scale = 0.04419417382415922f;  // 1/sqrt(512)

    const float* qrow = QKV + ((size_t)(b * T_ + q_idx)) * (3 * D_) + h * HS_ + half * 32;
    ull_t q2[16], o2[16];
    #pragma unroll
    for (int i = 0; i < 8; i++) {
        float4 v = *(const float4*)(qrow + 4 * i);
        q2[2 * i + 0] = pack2(v.x * scale, v.y * scale);
        q2[2 * i + 1] = pack2(v.z * scale, v.w * scale);
        o2[2 * i + 0] = 0ull;
        o2[2 * i + 1] = 0ull;
    }
    float m = -1e30f, l = 0.f;

    __shared__ float Ks[AKT][KSTR];
    __shared__ float Vs[AKT][KSTR];

    int kend = qblock + 128;
    for (int k0 = 0; k0 < kend; k0 += AKT) {
        __syncthreads();
        // 16 rows x 16 float4 x 2 arrays = 512 float4 for 256 threads: 2 each
        {
            int r = tid >> 4, c = (tid & 15) << 2;
            const float* base = QKV + ((size_t)(b * T_ + k0 + r)) * (3 * D_) + h * HS_ + c;
            *(float4*)&Ks[r][c] = *(const float4*)(base + D_);
            *(float4*)&Vs[r][c] = *(const float4*)(base + 2 * D_);
        }
        __syncthreads();

        float s[AKT];
        float mnew = m;
        bool fullTile = (k0 < qblock);
        #pragma unroll
        for (int j = 0; j < AKT; j++) {
            const ull_t* kr = (const ull_t*)&Ks[j][half * 32];
            ull_t a2 = mul2(q2[0], kr[0]);
            #pragma unroll
            for (int i = 1; i < 16; i++) a2 = fma2(q2[i], kr[i], a2);
            float alo, ahi;
            unpack2(a2, alo, ahi);
            float acc = alo + ahi;
            acc += __shfl_xor_sync(0xffffffffu, acc, 1);
            s[j] = (fullTile || (k0 + j <= q_idx)) ? acc : -1e30f;
            mnew = fmaxf(mnew, s[j]);
        }
        float corr = __expf(m - mnew);
        l *= corr;
        ull_t corr2 = pack2(corr, corr);
        #pragma unroll
        for (int i = 0; i < 16; i++) o2[i] = mul2(o2[i], corr2);
        #pragma unroll
        for (int j = 0; j < AKT; j++) {
            float p = __expf(s[j] - mnew);
            l += p;
            ull_t p2 = pack2(p, p);
            const ull_t* vr = (const ull_t*)&Vs[j][half * 32];
            #pragma unroll
            for (int i = 0; i < 16; i++) o2[i] = fma2(p2, vr[i], o2[i]);
        }
        m = mnew;
    }

    float inv = 1.f / l;
    float* orow = O + ((size_t)(b * T_ + q_idx)) * D_ + h * HS_ + half * 32;
    #pragma unroll
    for (int i = 0; i < 8; i++) {
        float x0, x1, x2, x3;
        unpack2(o2[2 * i + 0], x0, x1);
        unpack2(o2[2 * i + 1], x2, x3);
        *(float4*)(orow + 4 * i) = make_float4(x0 * inv, x1 * inv, x2 * inv, x3 * inv);
    }
}

// ------------------------- loss --------------------------------------------
__global__ __launch_bounds__(256) void loss_kernel(const float* __restrict__ logits,
                                                   const int* __restrict__ targets,
                                                   double* __restrict__ acc) {
    int warp = (blockIdx.x * blockDim.x + threadIdx.x) >> 5;
    int lane = threadIdx.x & 31;
    const float* lr = logits + (size_t)warp * V_;
    float v0 = lr[lane], v1 = lr[lane + 32], v2 = lr[lane + 64];
    float m = fmaxf(v0, fmaxf(v1, v2));
    #pragma unroll
    for (int o = 16; o; o >>= 1) m = fmaxf(m, __shfl_xor_sync(0xffffffffu, m, o));
    float se = expf(v0 - m) + expf(v1 - m) + expf(v2 - m);
    #pragma unroll
    for (int o = 16; o; o >>= 1) se += __shfl_xor_sync(0xffffffffu, se, o);

    __shared__ float part[8];
    if (lane == 0) part[threadIdx.x >> 5] = lr[targets[warp]] - m - logf(se);
    __syncthreads();
    if (threadIdx.x == 0) {
        float s = 0.f;
        #pragma unroll
        for (int i = 0; i < 8; i++) s += part[i];
        atomicAdd(acc, (double)s);
    }
}

__global__ void finalize_loss_kernel(float* out, const double* acc) {
    out[(size_t)BT_ * V_] = (float)(-(*acc) / (double)BT_);
}

// ------------------------- launcher ----------------------------------------
extern "C" void kernel_launch(void* const* d_in, const int* in_sizes, int n_in,
                              void* d_out, int out_size) {
    const int*   idx     = (const int*)  d_in[0];
    const int*   targets = (const int*)  d_in[1];
    const float* tok     = (const float*)d_in[2];
    const float* pos     = (const float*)d_in[3];
    const float* Wq      = (const float*)d_in[4];
    const float* Wk      = (const float*)d_in[5];
    const float* Wv      = (const float*)d_in[6];
    const float* Wproj   = (const float*)d_in[7];
    const float* bproj   = (const float*)d_in[8];
    const float* W1      = (const float*)d_in[9];
    const float* b1      = (const float*)d_in[10];
    const float* W2      = (const float*)d_in[11];
    const float* b2      = (const float*)d_in[12];
    const float* ln1_s   = (const float*)d_in[13];
    const float* ln1_b   = (const float*)d_in[14];
    const float* ln2_s   = (const float*)d_in[15];
    const float* ln2_b   = (const float*)d_in[16];
    const float* lnf_s   = (const float*)d_in[17];
    const float* lnf_b   = (const float*)d_in[18];
    const float* Wout    = (const float*)d_in[19];
    const float* bout    = (const float*)d_in[20];
    float* out = (float*)d_out;

    float *x, *h, *qkv, *o, *ff, *wp;
    double* lossAcc;
    cudaGetSymbolAddress((void**)&x,   g_x);
    cudaGetSymbolAddress((void**)&h,   g_h);
    cudaGetSymbolAddress((void**)&qkv, g_qkv);
    cudaGetSymbolAddress((void**)&o,   g_o);
    cudaGetSymbolAddress((void**)&ff,  g_ff);
    cudaGetSymbolAddress((void**)&wp,  g_wp);
    cudaGetSymbolAddress((void**)&lossAcc, g_loss);

    {
        int total = L_ * D_ * 3 * D_;
        pack_qkv_kernel<<<(total + 255) / 256, 256>>>(Wq, Wk, Wv, wp);
    }
    {
        int total = BT_ * D_;
        embed_kernel<<<(total + 255) / 256, 256>>>(idx, tok, pos, x);
    }

    const int MT = BT_ / 128;  // 128 M-tiles
    for (int l = 0; l < L_; l++) {
        ln_kernel<<<BT_, 256>>>(x, ln1_s + l * D_, ln1_b + l * D_, h);
        tgemm_kernel<<<dim3(12, MT), 256>>>(h, wp + (size_t)l * D_ * 3 * D_,
                                            nullptr, nullptr, qkv,
                                            BT_, 3 * D_, D_, 0);
        attn_kernel<<<dim3(T_ / 128, B_ * H_), 256>>>(qkv, o);
        tgemm_kernel<<<dim3(4, MT), 256>>>(o, Wproj + (size_t)l * D_ * D_,
                                           bproj + l * D_, x, x,
                                           BT_, D_, D_, 3);
        ln_kernel<<<BT_, 256>>>(x, ln2_s + l * D_, ln2_b + l * D_, h);
        tgemm_kernel<<<dim3(16, MT), 256>>>(h, W1 + (size_t)l * D_ * FF_,
                                            b1 + l * FF_, nullptr, ff,
                                            BT_, FF_, D_, 2);
        tgemm_kernel<<<dim3(4, MT), 256>>>(ff, W2 + (size_t)l * FF_ * D_,
                                           b2 + l * D_, x, x,
                                           BT_, D_, FF_, 3);
    }

    ln_kernel<<<BT_, 256>>>(x, lnf_s, lnf_b, h);
    tgemm_kernel<<<dim3(1, MT), 256>>>(h, Wout, bout, nullptr, out,
                                       BT_, V_, D_, 1);

    if (out_size > BT_ * V_) {
        zero_loss_kernel<<<1, 1>>>(lossAcc);
        loss_kernel<<<BT_ / 8, 256>>>(out, targets, lossAcc);
        finalize_loss_kernel<<<1, 1>>>(out, lossAcc);
    }
}

// round 6
// speedup vs baseline: 2.0308x; 1.9690x over previous
#include <cuda_runtime.h>
#include <cuda_bf16.h>
#include <math.h>
#include <stdint.h>

// ---------------------------------------------------------------------------
// MiniTransformer forward: B=16, T=1024, D=512, H=8, HS=64, L=6, FF=2048, V=96
// Output: logits [16384, 96] (fp32) followed by scalar loss.
// ---------------------------------------------------------------------------

#define B_   16
#define T_   1024
#define D_   512
#define H_   8
#define HS_  64
#define L_   6
#define FF_  2048
#define V_   96
#define BT_  (B_ * T_)

// ------------------------- device scratch (no mallocs) ---------------------
__device__ float  g_x   [BT_ * D_];        // residual stream
__device__ float  g_h   [BT_ * D_];        // LN output
__device__ float  g_qkv [BT_ * 3 * D_];    // packed q|k|v per token
__device__ float  g_o   [BT_ * D_];        // attention output (concat heads)
__device__ float  g_ff  [BT_ * FF_];       // FFN hidden
__device__ float  g_wp  [L_ * D_ * 3 * D_];// packed QKV weights [l][d][3D]
__device__ double g_loss;

// ------------------------- small kernels -----------------------------------
__global__ void zero_loss_kernel(double* a) { *a = 0.0; }

__global__ void pack_qkv_kernel(const float* __restrict__ Wq,
                                const float* __restrict__ Wk,
                                const float* __restrict__ Wv,
                                float* __restrict__ out) {
    int i = blockIdx.x * blockDim.x + threadIdx.x;       // over L*D*3D
    if (i >= L_ * D_ * 3 * D_) return;
    int c = i % (3 * D_);
    int d = (i / (3 * D_)) % D_;
    int l = i / (3 * D_ * D_);
    int sel = c >> 9;              // 0=q 1=k 2=v (512 cols each)
    int hk  = c & 511;
    int h   = hk >> 6;
    int k   = hk & 63;
    const float* W = (sel == 0) ? Wq : (sel == 1) ? Wk : Wv;
    out[i] = W[(((size_t)l * H_ + h) * D_ + d) * HS_ + k];
}

__global__ void embed_kernel(const int* __restrict__ idx,
                             const float* __restrict__ tok,
                             const float* __restrict__ pos,
                             float* __restrict__ x) {
    int i = blockIdx.x * blockDim.x + threadIdx.x;       // over BT*D
    if (i >= BT_ * D_) return;
    int d  = i & (D_ - 1);
    int bt = i >> 9;
    int t  = bt & (T_ - 1);
    x[i] = tok[(size_t)idx[bt] * D_ + d] + pos[t * D_ + d];
}

// One block per row; D=512, 256 threads, 2 elems/thread.
__global__ __launch_bounds__(256) void ln_kernel(const float* __restrict__ x,
                                                 const float* __restrict__ s,
                                                 const float* __restrict__ b,
                                                 float* __restrict__ out) {
    int row = blockIdx.x;
    int t   = threadIdx.x;
    const float* xr = x + (size_t)row * D_;
    float v0 = xr[t], v1 = xr[t + 256];

    float sum = v0 + v1;
    #pragma unroll
    for (int o = 16; o; o >>= 1) sum += __shfl_xor_sync(0xffffffffu, sum, o);
    __shared__ float red1[8], red2[8];
    if ((t & 31) == 0) red1[t >> 5] = sum;
    __syncthreads();
    float mean = 0.f;
    #pragma unroll
    for (int i = 0; i < 8; i++) mean += red1[i];
    mean *= (1.0f / D_);

    float d0 = v0 - mean, d1 = v1 - mean;
    float vs = d0 * d0 + d1 * d1;
    #pragma unroll
    for (int o = 16; o; o >>= 1) vs += __shfl_xor_sync(0xffffffffu, vs, o);
    if ((t & 31) == 0) red2[t >> 5] = vs;
    __syncthreads();
    float var = 0.f;
    #pragma unroll
    for (int i = 0; i < 8; i++) var += red2[i];
    var *= (1.0f / D_);

    float inv = rsqrtf(var + 1e-5f);
    float* orow = out + (size_t)row * D_;
    orow[t]       = d0 * inv * s[t]       + b[t];
    orow[t + 256] = d1 * inv * s[t + 256] + b[t + 256];
}

// ------------------------- TF32 helpers ------------------------------------
__device__ __forceinline__ uint32_t f2tf32(float f) {
    uint32_t r;
    asm("cvt.rna.tf32.f32 %0, %1;" : "=r"(r) : "f"(f));
    return r;
}

__device__ __forceinline__ void mma_tf32(float* d, const uint32_t* a, const uint32_t* b) {
    asm volatile(
        "mma.sync.aligned.m16n8k8.row.col.f32.tf32.tf32.f32 "
        "{%0,%1,%2,%3}, {%4,%5,%6,%7}, {%8,%9}, {%0,%1,%2,%3};"
        : "+f"(d[0]), "+f"(d[1]), "+f"(d[2]), "+f"(d[3])
        : "r"(a[0]), "r"(a[1]), "r"(a[2]), "r"(a[3]), "r"(b[0]), "r"(b[1]));
}

// ------------------------- TF32 tensor-core GEMM ---------------------------
// C[M,N] = A[M,K] * B[K,N]  (+bias, +relu, +residual per `mode`)
// mode: 0 = none, 1 = +bias, 2 = +bias,relu, 3 = +bias,+res
// 128x128 tile, BK=16, 256 threads = 8 warps, warp tile 64(m) x 32(n).
#define GBK 16
#define ASTR 20
#define BSTR 136

__global__ __launch_bounds__(256) void tgemm_kernel(
    const float* __restrict__ A, const float* __restrict__ Bm,
    const float* __restrict__ bias, const float* __restrict__ res,
    float* __restrict__ C, int M, int N, int K, int mode)
{
    __shared__ uint32_t As[2][128][ASTR];   // [m][k] as tf32 bits
    __shared__ uint32_t Bs[2][GBK][BSTR];   // [k][n] as tf32 bits

    int tid  = threadIdx.x;
    int wid  = tid >> 5;
    int lane = tid & 31;
    int grp  = lane >> 2;          // 0..7
    int tig  = lane & 3;           // 0..3
    int warp_m = (wid & 1) * 64;   // 0 or 64
    int warp_n = (wid >> 1) * 32;  // 0,32,64,96

    int arow = tid >> 2;           // 0..63 (+64)
    int acol = (tid & 3) << 2;     // 0,4,8,12
    int brow = tid >> 5;           // 0..7 (+8)
    int bcol = (tid & 31) << 2;    // 0..124

    const float* Ap  = A + (size_t)(blockIdx.y * 128 + arow) * K + acol;
    const float* Ap2 = Ap + (size_t)64 * K;
    int gbc = blockIdx.x * 128 + bcol;

    float acc[4][4][4];
    #pragma unroll
    for (int i = 0; i < 4; i++)
        #pragma unroll
        for (int j = 0; j < 4; j++)
            #pragma unroll
            for (int r = 0; r < 4; r++) acc[i][j][r] = 0.f;

    float4 pa0, pa1, pb0, pb1;

    pa0 = *(const float4*)(Ap);
    pa1 = *(const float4*)(Ap2);
    {
        const float* Bp0 = Bm + (size_t)brow * N;
        const float* Bp1 = Bm + (size_t)(brow + 8) * N;
        if (gbc + 3 < N) {
            pb0 = *(const float4*)(Bp0 + gbc);
            pb1 = *(const float4*)(Bp1 + gbc);
        } else {
            pb0 = make_float4(0.f, 0.f, 0.f, 0.f);
            pb1 = make_float4(0.f, 0.f, 0.f, 0.f);
            if (gbc + 0 < N) { pb0.x = Bp0[gbc + 0]; pb1.x = Bp1[gbc + 0]; }
            if (gbc + 1 < N) { pb0.y = Bp0[gbc + 1]; pb1.y = Bp1[gbc + 1]; }
            if (gbc + 2 < N) { pb0.z = Bp0[gbc + 2]; pb1.z = Bp1[gbc + 2]; }
        }
    }
    {
        As[0][arow][acol + 0] = f2tf32(pa0.x); As[0][arow][acol + 1] = f2tf32(pa0.y);
        As[0][arow][acol + 2] = f2tf32(pa0.z); As[0][arow][acol + 3] = f2tf32(pa0.w);
        As[0][arow + 64][acol + 0] = f2tf32(pa1.x); As[0][arow + 64][acol + 1] = f2tf32(pa1.y);
        As[0][arow + 64][acol + 2] = f2tf32(pa1.z); As[0][arow + 64][acol + 3] = f2tf32(pa1.w);
        Bs[0][brow][bcol + 0] = f2tf32(pb0.x); Bs[0][brow][bcol + 1] = f2tf32(pb0.y);
        Bs[0][brow][bcol + 2] = f2tf32(pb0.z); Bs[0][brow][bcol + 3] = f2tf32(pb0.w);
        Bs[0][brow + 8][bcol + 0] = f2tf32(pb1.x); Bs[0][brow + 8][bcol + 1] = f2tf32(pb1.y);
        Bs[0][brow + 8][bcol + 2] = f2tf32(pb1.z); Bs[0][brow + 8][bcol + 3] = f2tf32(pb1.w);
    }
    __syncthreads();

    int nstage = K / GBK;
    int cur = 0;
    for (int s = 0; s < nstage; s++) {
        if (s + 1 < nstage) {
            int k0 = (s + 1) * GBK;
            pa0 = *(const float4*)(Ap + k0);
            pa1 = *(const float4*)(Ap2 + k0);
            const float* Bp0 = Bm + (size_t)(k0 + brow) * N;
            const float* Bp1 = Bm + (size_t)(k0 + brow + 8) * N;
            if (gbc + 3 < N) {
                pb0 = *(const float4*)(Bp0 + gbc);
                pb1 = *(const float4*)(Bp1 + gbc);
            } else {
                pb0 = make_float4(0.f, 0.f, 0.f, 0.f);
                pb1 = make_float4(0.f, 0.f, 0.f, 0.f);
                if (gbc + 0 < N) { pb0.x = Bp0[gbc + 0]; pb1.x = Bp1[gbc + 0]; }
                if (gbc + 1 < N) { pb0.y = Bp0[gbc + 1]; pb1.y = Bp1[gbc + 1]; }
                if (gbc + 2 < N) { pb0.z = Bp0[gbc + 2]; pb1.z = Bp1[gbc + 2]; }
            }
        }

        #pragma unroll
        for (int ks = 0; ks < 2; ks++) {
            int k0 = ks * 8;
            uint32_t af[4][4];
            #pragma unroll
            for (int i = 0; i < 4; i++) {
                int mrow = warp_m + i * 16 + grp;
                af[i][0] = As[cur][mrow][k0 + tig];
                af[i][1] = As[cur][mrow + 8][k0 + tig];
                af[i][2] = As[cur][mrow][k0 + tig + 4];
                af[i][3] = As[cur][mrow + 8][k0 + tig + 4];
            }
            uint32_t bf[4][2];
            #pragma unroll
            for (int j = 0; j < 4; j++) {
                int ncol = warp_n + j * 8 + grp;
                bf[j][0] = Bs[cur][k0 + tig][ncol];
                bf[j][1] = Bs[cur][k0 + tig + 4][ncol];
            }
            #pragma unroll
            for (int i = 0; i < 4; i++)
                #pragma unroll
                for (int j = 0; j < 4; j++)
                    mma_tf32(acc[i][j], af[i], bf[j]);
        }

        if (s + 1 < nstage) {
            int nxt = cur ^ 1;
            As[nxt][arow][acol + 0] = f2tf32(pa0.x); As[nxt][arow][acol + 1] = f2tf32(pa0.y);
            As[nxt][arow][acol + 2] = f2tf32(pa0.z); As[nxt][arow][acol + 3] = f2tf32(pa0.w);
            As[nxt][arow + 64][acol + 0] = f2tf32(pa1.x); As[nxt][arow + 64][acol + 1] = f2tf32(pa1.y);
            As[nxt][arow + 64][acol + 2] = f2tf32(pa1.z); As[nxt][arow + 64][acol + 3] = f2tf32(pa1.w);
            Bs[nxt][brow][bcol + 0] = f2tf32(pb0.x); Bs[nxt][brow][bcol + 1] = f2tf32(pb0.y);
            Bs[nxt][brow][bcol + 2] = f2tf32(pb0.z); Bs[nxt][brow][bcol + 3] = f2tf32(pb0.w);
            Bs[nxt][brow + 8][bcol + 0] = f2tf32(pb1.x); Bs[nxt][brow + 8][bcol + 1] = f2tf32(pb1.y);
            Bs[nxt][brow + 8][bcol + 2] = f2tf32(pb1.z); Bs[nxt][brow + 8][bcol + 3] = f2tf32(pb1.w);
            __syncthreads();
            cur = nxt;
        }
    }

    #pragma unroll
    for (int i = 0; i < 4; i++) {
        int row0 = blockIdx.y * 128 + warp_m + i * 16 + grp;
        #pragma unroll
        for (int j = 0; j < 4; j++) {
            int col = blockIdx.x * 128 + warp_n + j * 8 + 2 * tig;
            if (col < N) {
                #pragma unroll
                for (int half = 0; half < 2; half++) {
                    int r = row0 + half * 8;
                    size_t rb = (size_t)r * N;
                    float v0 = acc[i][j][half * 2 + 0];
                    float v1 = acc[i][j][half * 2 + 1];
                    if (mode >= 1) { v0 += bias[col]; v1 += bias[col + 1]; }
                    if (mode == 2) { v0 = fmaxf(v0, 0.f); v1 = fmaxf(v1, 0.f); }
                    if (mode == 3) { v0 += res[rb + col]; v1 += res[rb + col + 1]; }
                    *(float2*)(C + rb + col) = make_float2(v0, v1);
                }
            }
        }
    }
}

// ------------------------- tensor-core flash attention ---------------------
// 128 queries/block, 8 warps x 16 query-rows, 64-key tiles.
// S = Q@K^T via tf32 mma (K smem [key][d]); online softmax in registers;
// P routed through warp-private smem tile; O += P@V via tf32 mma
// (V smem transposed [d][key]).
#define KVSTR 68

__global__ __launch_bounds__(256, 2) void attn_kernel(const float* __restrict__ QKV,
                                                      float* __restrict__ O) {
    extern __shared__ uint32_t sm[];
    uint32_t (*Ks)[KVSTR] = (uint32_t(*)[KVSTR])sm;                   // [64][68]
    uint32_t (*Vs)[KVSTR] = (uint32_t(*)[KVSTR])(sm + 64 * KVSTR);    // [64][68]
    uint32_t (*Ps)[KVSTR] = (uint32_t(*)[KVSTR])(sm + 2 * 64 * KVSTR);// [128][68]

    int b = blockIdx.y >> 3, h = blockIdx.y & 7;
    int qb = blockIdx.x * 128;
    int tid = threadIdx.x, wid = tid >> 5, lane = tid & 31;
    int grp = lane >> 2, tig = lane & 3;
    const float scale = 0.04419417382415922f;   // 1/sqrt(512)

    int lr0 = wid * 16 + grp;       // local query rows owned by this thread
    int lr1 = lr0 + 8;
    int gr0 = qb + lr0, gr1 = qb + lr1;  // global query rows

    // Q fragments (held in registers for the whole key sweep)
    const float* q0p = QKV + ((size_t)(b * T_) + gr0) * 1536 + h * 64;
    const float* q1p = QKV + ((size_t)(b * T_) + gr1) * 1536 + h * 64;
    uint32_t qa[8][4];
    #pragma unroll
    for (int k = 0; k < 8; k++) {
        int d = 8 * k + tig;
        qa[k][0] = f2tf32(q0p[d]     * scale);
        qa[k][1] = f2tf32(q1p[d]     * scale);
        qa[k][2] = f2tf32(q0p[d + 4] * scale);
        qa[k][3] = f2tf32(q1p[d + 4] * scale);
    }

    float o[8][4];
    #pragma unroll
    for (int j = 0; j < 8; j++) { o[j][0] = o[j][1] = o[j][2] = o[j][3] = 0.f; }
    float m0 = -1e30f, m1 = -1e30f, l0 = 0.f, l1 = 0.f;

    int key4 = tid >> 2, c4 = tid & 3;   // K/V loader mapping
    const float* kvb = QKV + (size_t)(b * T_) * 1536 + h * 64 + D_;  // K base

    int ntiles = (qb >> 6) + 2;
    for (int t = 0; t < ntiles; t++) {
        int k0 = t * 64;
        __syncthreads();
        // load K (natural) and V (transposed) into smem as tf32
        #pragma unroll
        for (int i = 0; i < 4; i++) {
            int d = 4 * c4 + 16 * i;
            const float* kp = kvb + (size_t)(k0 + key4) * 1536 + d;
            float4 kv = *(const float4*)kp;
            float4 vv = *(const float4*)(kp + D_);
            uint4 ku;
            ku.x = f2tf32(kv.x); ku.y = f2tf32(kv.y);
            ku.z = f2tf32(kv.z); ku.w = f2tf32(kv.w);
            *(uint4*)&Ks[key4][d] = ku;
            Vs[d + 0][key4] = f2tf32(vv.x);
            Vs[d + 1][key4] = f2tf32(vv.y);
            Vs[d + 2][key4] = f2tf32(vv.z);
            Vs[d + 3][key4] = f2tf32(vv.w);
        }
        __syncthreads();

        // S = Q @ K^T  (8 n-subtiles of 8 keys, 8 k-steps over d)
        float sc[8][4];
        #pragma unroll
        for (int j = 0; j < 8; j++) { sc[j][0] = sc[j][1] = sc[j][2] = sc[j][3] = 0.f; }
        #pragma unroll
        for (int j = 0; j < 8; j++) {
            int kr = 8 * j + grp;
            #pragma unroll
            for (int k = 0; k < 8; k++) {
                uint32_t bf[2] = { Ks[kr][8 * k + tig], Ks[kr][8 * k + tig + 4] };
                mma_tf32(sc[j], qa[k], bf);
            }
        }

        // causal mask (only tiles that can cross the diagonal for this warp)
        if (k0 + 63 > qb + wid * 16) {
            #pragma unroll
            for (int j = 0; j < 8; j++) {
                int key = k0 + 8 * j + 2 * tig;
                if (key     > gr0) sc[j][0] = -1e30f;
                if (key + 1 > gr0) sc[j][1] = -1e30f;
                if (key     > gr1) sc[j][2] = -1e30f;
                if (key + 1 > gr1) sc[j][3] = -1e30f;
            }
        }

        // online softmax (rows owned by quads; reduce over tig via shfl 1,2)
        float mx0 = -1e30f, mx1 = -1e30f;
        #pragma unroll
        for (int j = 0; j < 8; j++) {
            mx0 = fmaxf(mx0, fmaxf(sc[j][0], sc[j][1]));
            mx1 = fmaxf(mx1, fmaxf(sc[j][2], sc[j][3]));
        }
        mx0 = fmaxf(mx0, __shfl_xor_sync(0xffffffffu, mx0, 1));
        mx0 = fmaxf(mx0, __shfl_xor_sync(0xffffffffu, mx0, 2));
        mx1 = fmaxf(mx1, __shfl_xor_sync(0xffffffffu, mx1, 1));
        mx1 = fmaxf(mx1, __shfl_xor_sync(0xffffffffu, mx1, 2));
        float mn0 = fmaxf(m0, mx0), mn1 = fmaxf(m1, mx1);
        float c0 = __expf(m0 - mn0), c1 = __expf(m1 - mn1);
        m0 = mn0; m1 = mn1;

        float s0 = 0.f, s1 = 0.f;
        #pragma unroll
        for (int j = 0; j < 8; j++) {
            float p0 = __expf(sc[j][0] - m0);
            float p1 = __expf(sc[j][1] - m0);
            float p2 = __expf(sc[j][2] - m1);
            float p3 = __expf(sc[j][3] - m1);
            s0 += p0 + p1; s1 += p2 + p3;
            *(uint2*)&Ps[lr0][8 * j + 2 * tig] = make_uint2(f2tf32(p0), f2tf32(p1));
            *(uint2*)&Ps[lr1][8 * j + 2 * tig] = make_uint2(f2tf32(p2), f2tf32(p3));
        }
        s0 += __shfl_xor_sync(0xffffffffu, s0, 1);
        s0 += __shfl_xor_sync(0xffffffffu, s0, 2);
        s1 += __shfl_xor_sync(0xffffffffu, s1, 1);
        s1 += __shfl_xor_sync(0xffffffffu, s1, 2);
        l0 = l0 * c0 + s0;
        l1 = l1 * c1 + s1;
        #pragma unroll
        for (int j = 0; j < 8; j++) {
            o[j][0] *= c0; o[j][1] *= c0; o[j][2] *= c1; o[j][3] *= c1;
        }
        __syncwarp();   // P stores visible across lanes of this warp

        // O += P @ V   (A = P from warp-private smem rows, B = V transposed)
        #pragma unroll
        for (int k = 0; k < 8; k++) {
            uint32_t a[4] = { Ps[lr0][8 * k + tig],     Ps[lr1][8 * k + tig],
                              Ps[lr0][8 * k + tig + 4], Ps[lr1][8 * k + tig + 4] };
            #pragma unroll
            for (int j = 0; j < 8; j++) {
                int nr = 8 * j + grp;
                uint32_t bf[2] = { Vs[nr][8 * k + tig], Vs[nr][8 * k + tig + 4] };
                mma_tf32(o[j], a, bf);
            }
        }
    }

    float i0 = 1.f / l0, i1 = 1.f / l1;
    float* ob0 = O + ((size_t)(b * T_) + gr0) * D_ + h * 64;
    float* ob1 = O + ((size_t)(b * T_) + gr1) * D_ + h * 64;
    #pragma unroll
    for (int j = 0; j < 8; j++) {
        *(float2*)(ob0 + 8 * j + 2 * tig) = make_float2(o[j][0] * i0, o[j][1] * i0);
        *(float2*)(ob1 + 8 * j + 2 * tig) = make_float2(o[j][2] * i1, o[j][3] * i1);
    }
}

#define ATTN_SMEM ((2 * 64 * KVSTR + 128 * KVSTR) * 4)

// ------------------------- loss --------------------------------------------
__global__ __launch_bounds__(256) void loss_kernel(const float* __restrict__ logits,
                                                   const int* __restrict__ targets,
                                                   double* __restrict__ acc) {
    int warp = (blockIdx.x * blockDim.x + threadIdx.x) >> 5;
    int lane = threadIdx.x & 31;
    const float* lr = logits + (size_t)warp * V_;
    float v0 = lr[lane], v1 = lr[lane + 32], v2 = lr[lane + 64];
    float m = fmaxf(v0, fmaxf(v1, v2));
    #pragma unroll
    for (int o = 16; o; o >>= 1) m = fmaxf(m, __shfl_xor_sync(0xffffffffu, m, o));
    float se = expf(v0 - m) + expf(v1 - m) + expf(v2 - m);
    #pragma unroll
    for (int o = 16; o; o >>= 1) se += __shfl_xor_sync(0xffffffffu, se, o);

    __shared__ float part[8];
    if (lane == 0) part[threadIdx.x >> 5] = lr[targets[warp]] - m - logf(se);
    __syncthreads();
    if (threadIdx.x == 0) {
        float s = 0.f;
        #pragma unroll
        for (int i = 0; i < 8; i++) s += part[i];
        atomicAdd(acc, (double)s);
    }
}

__global__ void finalize_loss_kernel(float* out, const double* acc) {
    out[(size_t)BT_ * V_] = (float)(-(*acc) / (double)BT_);
}

// ------------------------- launcher ----------------------------------------
extern "C" void kernel_launch(void* const* d_in, const int* in_sizes, int n_in,
                              void* d_out, int out_size) {
    const int*   idx     = (const int*)  d_in[0];
    const int*   targets = (const int*)  d_in[1];
    const float* tok     = (const float*)d_in[2];
    const float* pos     = (const float*)d_in[3];
    const float* Wq      = (const float*)d_in[4];
    const float* Wk      = (const float*)d_in[5];
    const float* Wv      = (const float*)d_in[6];
    const float* Wproj   = (const float*)d_in[7];
    const float* bproj   = (const float*)d_in[8];
    const float* W1      = (const float*)d_in[9];
    const float* b1      = (const float*)d_in[10];
    const float* W2      = (const float*)d_in[11];
    const float* b2      = (const float*)d_in[12];
    const float* ln1_s   = (const float*)d_in[13];
    const float* ln1_b   = (const float*)d_in[14];
    const float* ln2_s   = (const float*)d_in[15];
    const float* ln2_b   = (const float*)d_in[16];
    const float* lnf_s   = (const float*)d_in[17];
    const float* lnf_b   = (const float*)d_in[18];
    const float* Wout    = (const float*)d_in[19];
    const float* bout    = (const float*)d_in[20];
    float* out = (float*)d_out;

    float *x, *h, *qkv, *o, *ff, *wp;
    double* lossAcc;
    cudaGetSymbolAddress((void**)&x,   g_x);
    cudaGetSymbolAddress((void**)&h,   g_h);
    cudaGetSymbolAddress((void**)&qkv, g_qkv);
    cudaGetSymbolAddress((void**)&o,   g_o);
    cudaGetSymbolAddress((void**)&ff,  g_ff);
    cudaGetSymbolAddress((void**)&wp,  g_wp);
    cudaGetSymbolAddress((void**)&lossAcc, g_loss);

    cudaFuncSetAttribute(attn_kernel,
                         cudaFuncAttributeMaxDynamicSharedMemorySize, ATTN_SMEM);

    {
        int total = L_ * D_ * 3 * D_;
        pack_qkv_kernel<<<(total + 255) / 256, 256>>>(Wq, Wk, Wv, wp);
    }
    {
        int total = BT_ * D_;
        embed_kernel<<<(total + 255) / 256, 256>>>(idx, tok, pos, x);
    }

    const int MT = BT_ / 128;  // 128 M-tiles
    for (int l = 0; l < L_; l++) {
        ln_kernel<<<BT_, 256>>>(x, ln1_s + l * D_, ln1_b + l * D_, h);
        tgemm_kernel<<<dim3(12, MT), 256>>>(h, wp + (size_t)l * D_ * 3 * D_,
                                            nullptr, nullptr, qkv,
                                            BT_, 3 * D_, D_, 0);
        attn_kernel<<<dim3(T_ / 128, B_ * H_), 256, ATTN_SMEM>>>(qkv, o);
        tgemm_kernel<<<dim3(4, MT), 256>>>(o, Wproj + (size_t)l * D_ * D_,
                                           bproj + l * D_, x, x,
                                           BT_, D_, D_, 3);
        ln_kernel<<<BT_, 256>>>(x, ln2_s + l * D_, ln2_b + l * D_, h);
        tgemm_kernel<<<dim3(16, MT), 256>>>(h, W1 + (size_t)l * D_ * FF_,
                                            b1 + l * FF_, nullptr, ff,
                                            BT_, FF_, D_, 2);
        tgemm_kernel<<<dim3(4, MT), 256>>>(ff, W2 + (size_t)l * FF_ * D_,
                                           b2 + l * D_, x, x,
                                           BT_, D_, FF_, 3);
    }

    ln_kernel<<<BT_, 256>>>(x, lnf_s, lnf_b, h);
    tgemm_kernel<<<dim3(1, MT), 256>>>(h, Wout, bout, nullptr, out,
                                       BT_, V_, D_, 1);

    if (out_size > BT_ * V_) {
        zero_loss_kernel<<<1, 1>>>(lossAcc);
        loss_kernel<<<BT_ / 8, 256>>>(out, targets, lossAcc);
        finalize_loss_kernel<<<1, 1>>>(out, lossAcc);
    }
}

// round 7
// speedup vs baseline: 2.1507x; 1.0591x over previous
#include <cuda_runtime.h>
#include <cuda_bf16.h>
#include <math.h>
#include <stdint.h>

// ---------------------------------------------------------------------------
// MiniTransformer forward: B=16, T=1024, D=512, H=8, HS=64, L=6, FF=2048, V=96
// Output: logits [16384, 96] (fp32) followed by scalar loss.
// ---------------------------------------------------------------------------

#define B_   16
#define T_   1024
#define D_   512
#define H_   8
#define HS_  64
#define L_   6
#define FF_  2048
#define V_   96
#define BT_  (B_ * T_)

// ------------------------- device scratch (no mallocs) ---------------------
__device__ float    g_x   [BT_ * D_];          // residual stream (fp32)
__device__ uint32_t g_h   [BT_ * D_];          // LN output (tf32 bits)
__device__ float    g_qkv [BT_ * 3 * D_];      // q|k|v per token (tf32-rounded fp32)
__device__ uint32_t g_o   [BT_ * D_];          // attention output (tf32 bits)
__device__ uint32_t g_ff  [BT_ * FF_];         // FFN hidden (tf32 bits)
__device__ uint32_t g_wp  [L_ * D_ * 3 * D_];  // packed QKV weights (tf32 bits)
__device__ uint32_t g_wproj_t[L_ * D_ * D_];   // tf32 weights
__device__ uint32_t g_w1_t[L_ * D_ * FF_];
__device__ uint32_t g_w2_t[L_ * FF_ * D_];
__device__ uint32_t g_wout_t[D_ * V_];
__device__ double   g_loss;

// ------------------------- helpers -----------------------------------------
__device__ __forceinline__ uint32_t f2tf32(float f) {
    uint32_t r;
    asm("cvt.rna.tf32.f32 %0, %1;" : "=r"(r) : "f"(f));
    return r;
}

__device__ __forceinline__ void mma_tf32(float* d, const uint32_t* a, const uint32_t* b) {
    asm volatile(
        "mma.sync.aligned.m16n8k8.row.col.f32.tf32.tf32.f32 "
        "{%0,%1,%2,%3}, {%4,%5,%6,%7}, {%8,%9}, {%0,%1,%2,%3};"
        : "+f"(d[0]), "+f"(d[1]), "+f"(d[2]), "+f"(d[3])
        : "r"(a[0]), "r"(a[1]), "r"(a[2]), "r"(a[3]), "r"(b[0]), "r"(b[1]));
}

__device__ __forceinline__ void cp16(uint32_t dst_smem, const void* src, bool pred) {
    int sz = pred ? 16 : 0;
    asm volatile("cp.async.ca.shared.global [%0], [%1], 16, %2;\n"
                 :: "r"(dst_smem), "l"(src), "r"(sz));
}
__device__ __forceinline__ void cp_commit() {
    asm volatile("cp.async.commit_group;\n");
}
__device__ __forceinline__ void cp_wait0() {
    asm volatile("cp.async.wait_group 0;\n");
}

// ------------------------- small kernels -----------------------------------
__global__ void zero_loss_kernel(double* a) { *a = 0.0; }

__global__ void cvt_tf32_kernel(const float* __restrict__ src,
                                uint32_t* __restrict__ dst, int n) {
    int i = blockIdx.x * blockDim.x + threadIdx.x;
    if (i < n) dst[i] = f2tf32(src[i]);
}

__global__ void pack_qkv_kernel(const float* __restrict__ Wq,
                                const float* __restrict__ Wk,
                                const float* __restrict__ Wv,
                                uint32_t* __restrict__ out) {
    int i = blockIdx.x * blockDim.x + threadIdx.x;       // over L*D*3D
    if (i >= L_ * D_ * 3 * D_) return;
    int c = i % (3 * D_);
    int d = (i / (3 * D_)) % D_;
    int l = i / (3 * D_ * D_);
    int sel = c >> 9;              // 0=q 1=k 2=v (512 cols each)
    int hk  = c & 511;
    int h   = hk >> 6;
    int k   = hk & 63;
    const float* W = (sel == 0) ? Wq : (sel == 1) ? Wk : Wv;
    out[i] = f2tf32(W[(((size_t)l * H_ + h) * D_ + d) * HS_ + k]);
}

__global__ void embed_kernel(const int* __restrict__ idx,
                             const float* __restrict__ tok,
                             const float* __restrict__ pos,
                             float* __restrict__ x) {
    int i = blockIdx.x * blockDim.x + threadIdx.x;       // over BT*D
    if (i >= BT_ * D_) return;
    int d  = i & (D_ - 1);
    int bt = i >> 9;
    int t  = bt & (T_ - 1);
    x[i] = tok[(size_t)idx[bt] * D_ + d] + pos[t * D_ + d];
}

// One block per row; D=512, 256 threads. Output: tf32 bits.
__global__ __launch_bounds__(256) void ln_kernel(const float* __restrict__ x,
                                                 const float* __restrict__ s,
                                                 const float* __restrict__ b,
                                                 uint32_t* __restrict__ out) {
    int row = blockIdx.x;
    int t   = threadIdx.x;
    const float* xr = x + (size_t)row * D_;
    float v0 = xr[t], v1 = xr[t + 256];

    float sum = v0 + v1;
    #pragma unroll
    for (int o = 16; o; o >>= 1) sum += __shfl_xor_sync(0xffffffffu, sum, o);
    __shared__ float red1[8], red2[8];
    if ((t & 31) == 0) red1[t >> 5] = sum;
    __syncthreads();
    float mean = 0.f;
    #pragma unroll
    for (int i = 0; i < 8; i++) mean += red1[i];
    mean *= (1.0f / D_);

    float d0 = v0 - mean, d1 = v1 - mean;
    float vs = d0 * d0 + d1 * d1;
    #pragma unroll
    for (int o = 16; o; o >>= 1) vs += __shfl_xor_sync(0xffffffffu, vs, o);
    if ((t & 31) == 0) red2[t >> 5] = vs;
    __syncthreads();
    float var = 0.f;
    #pragma unroll
    for (int i = 0; i < 8; i++) var += red2[i];
    var *= (1.0f / D_);

    float inv = rsqrtf(var + 1e-5f);
    uint32_t* orow = out + (size_t)row * D_;
    orow[t]       = f2tf32(d0 * inv * s[t]       + b[t]);
    orow[t + 256] = f2tf32(d1 * inv * s[t + 256] + b[t + 256]);
}

// ------------------------- TF32 tensor-core GEMM (cp.async) ----------------
// C[M,N] = A[M,K] * B[K,N]; A,B are pre-rounded tf32 bits.
// mode: 0 = tf32-rounded store (no bias)      [QKV]
//       1 = +bias, fp32 store                 [logits]
//       2 = +bias, relu, tf32-rounded store   [FF1]
//       3 = +bias, +residual, fp32 store      [proj, FF2]
// 128x128 tile, BK=16, 256 threads = 8 warps, warp tile 64(m) x 32(n).
#define GBK 16
#define ASTR 20
#define BSTR 136

__global__ __launch_bounds__(256) void tgemm_kernel(
    const uint32_t* __restrict__ A, const uint32_t* __restrict__ Bm,
    const float* __restrict__ bias, const float* __restrict__ res,
    float* __restrict__ C, int M, int N, int K, int mode)
{
    __shared__ __align__(16) uint32_t As[2][128][ASTR];   // [m][k]
    __shared__ __align__(16) uint32_t Bs[2][GBK][BSTR];   // [k][n]

    int tid  = threadIdx.x;
    int wid  = tid >> 5;
    int lane = tid & 31;
    int grp  = lane >> 2;          // 0..7
    int tig  = lane & 3;           // 0..3
    int warp_m = (wid & 1) * 64;   // 0 or 64
    int warp_n = (wid >> 1) * 32;  // 0,32,64,96

    int arow = tid >> 2;           // 0..63 (+64)
    int acol = (tid & 3) << 2;     // 0,4,8,12
    int brow = tid >> 5;           // 0..7 (+8)
    int bcol = (tid & 31) << 2;    // 0..124

    const uint32_t* Ap  = A + (size_t)(blockIdx.y * 128 + arow) * K + acol;
    const uint32_t* Ap2 = Ap + (size_t)64 * K;
    int gbc = blockIdx.x * 128 + bcol;
    bool bpred = (gbc < N);        // N multiple of 4 -> chunk all-or-nothing
    int gbc_c = bpred ? gbc : 0;

    // smem dst addresses for this thread's 4 async chunks, per buffer
    uint32_t aA0[2], aA1[2], bA0[2], bA1[2];
    #pragma unroll
    for (int bf = 0; bf < 2; bf++) {
        aA0[bf] = (uint32_t)__cvta_generic_to_shared(&As[bf][arow][acol]);
        aA1[bf] = (uint32_t)__cvta_generic_to_shared(&As[bf][arow + 64][acol]);
        bA0[bf] = (uint32_t)__cvta_generic_to_shared(&Bs[bf][brow][bcol]);
        bA1[bf] = (uint32_t)__cvta_generic_to_shared(&Bs[bf][brow + 8][bcol]);
    }

    float acc[4][4][4];
    #pragma unroll
    for (int i = 0; i < 4; i++)
        #pragma unroll
        for (int j = 0; j < 4; j++)
            #pragma unroll
            for (int r = 0; r < 4; r++) acc[i][j][r] = 0.f;

    // prologue: stage 0
    {
        cp16(aA0[0], Ap, true);
        cp16(aA1[0], Ap2, true);
        cp16(bA0[0], Bm + (size_t)brow * N + gbc_c, bpred);
        cp16(bA1[0], Bm + (size_t)(brow + 8) * N + gbc_c, bpred);
        cp_commit();
        cp_wait0();
    }
    __syncthreads();

    int nstage = K / GBK;
    int cur = 0;
    for (int s = 0; s < nstage; s++) {
        if (s + 1 < nstage) {
            int k0 = (s + 1) * GBK;
            int nxt = cur ^ 1;
            cp16(aA0[nxt], Ap + k0, true);
            cp16(aA1[nxt], Ap2 + k0, true);
            cp16(bA0[nxt], Bm + (size_t)(k0 + brow) * N + gbc_c, bpred);
            cp16(bA1[nxt], Bm + (size_t)(k0 + brow + 8) * N + gbc_c, bpred);
            cp_commit();
        }

        #pragma unroll
        for (int ks = 0; ks < 2; ks++) {
            int k0 = ks * 8;
            uint32_t af[4][4];
            #pragma unroll
            for (int i = 0; i < 4; i++) {
                int mrow = warp_m + i * 16 + grp;
                af[i][0] = As[cur][mrow][k0 + tig];
                af[i][1] = As[cur][mrow + 8][k0 + tig];
                af[i][2] = As[cur][mrow][k0 + tig + 4];
                af[i][3] = As[cur][mrow + 8][k0 + tig + 4];
            }
            uint32_t bfr[4][2];
            #pragma unroll
            for (int j = 0; j < 4; j++) {
                int ncol = warp_n + j * 8 + grp;
                bfr[j][0] = Bs[cur][k0 + tig][ncol];
                bfr[j][1] = Bs[cur][k0 + tig + 4][ncol];
            }
            #pragma unroll
            for (int i = 0; i < 4; i++)
                #pragma unroll
                for (int j = 0; j < 4; j++)
                    mma_tf32(acc[i][j], af[i], bfr[j]);
        }

        if (s + 1 < nstage) {
            cp_wait0();
            __syncthreads();
            cur ^= 1;
        }
    }

    bool tf32out = (mode == 0) || (mode == 2);
    #pragma unroll
    for (int i = 0; i < 4; i++) {
        int row0 = blockIdx.y * 128 + warp_m + i * 16 + grp;
        #pragma unroll
        for (int j = 0; j < 4; j++) {
            int col = blockIdx.x * 128 + warp_n + j * 8 + 2 * tig;
            if (col < N) {
                #pragma unroll
                for (int half = 0; half < 2; half++) {
                    int r = row0 + half * 8;
                    size_t rb = (size_t)r * N;
                    float v0 = acc[i][j][half * 2 + 0];
                    float v1 = acc[i][j][half * 2 + 1];
                    if (mode >= 1) { v0 += bias[col]; v1 += bias[col + 1]; }
                    if (mode == 2) { v0 = fmaxf(v0, 0.f); v1 = fmaxf(v1, 0.f); }
                    if (mode == 3) { v0 += res[rb + col]; v1 += res[rb + col + 1]; }
                    if (tf32out) {
                        v0 = __uint_as_float(f2tf32(v0));
                        v1 = __uint_as_float(f2tf32(v1));
                    }
                    *(float2*)(C + rb + col) = make_float2(v0, v1);
                }
            }
        }
    }
}

// ------------------------- tensor-core flash attention ---------------------
// 128 queries/block, 8 warps x 16 query-rows, 64-key tiles.
// QKV values are already tf32-rounded; K/V pass bits straight to smem.
#define KVSTR 68

__global__ __launch_bounds__(256, 2) void attn_kernel(const float* __restrict__ QKV,
                                                      uint32_t* __restrict__ O) {
    extern __shared__ uint32_t sm[];
    uint32_t (*Ks)[KVSTR] = (uint32_t(*)[KVSTR])sm;                   // [64][68]
    uint32_t (*Vs)[KVSTR] = (uint32_t(*)[KVSTR])(sm + 64 * KVSTR);    // [64][68]
    uint32_t (*Ps)[KVSTR] = (uint32_t(*)[KVSTR])(sm + 2 * 64 * KVSTR);// [128][68]

    int b = blockIdx.y >> 3, h = blockIdx.y & 7;
    int qb = blockIdx.x * 128;
    int tid = threadIdx.x, wid = tid >> 5, lane = tid & 31;
    int grp = lane >> 2, tig = lane & 3;
    const float scale = 0.04419417382415922f;   // 1/sqrt(512)

    int lr0 = wid * 16 + grp;
    int lr1 = lr0 + 8;
    int gr0 = qb + lr0, gr1 = qb + lr1;

    const float* q0p = QKV + ((size_t)(b * T_) + gr0) * 1536 + h * 64;
    const float* q1p = QKV + ((size_t)(b * T_) + gr1) * 1536 + h * 64;
    uint32_t qa[8][4];
    #pragma unroll
    for (int k = 0; k < 8; k++) {
        int d = 8 * k + tig;
        qa[k][0] = f2tf32(q0p[d]     * scale);
        qa[k][1] = f2tf32(q1p[d]     * scale);
        qa[k][2] = f2tf32(q0p[d + 4] * scale);
        qa[k][3] = f2tf32(q1p[d + 4] * scale);
    }

    float o[8][4];
    #pragma unroll
    for (int j = 0; j < 8; j++) { o[j][0] = o[j][1] = o[j][2] = o[j][3] = 0.f; }
    float m0 = -1e30f, m1 = -1e30f, l0 = 0.f, l1 = 0.f;

    int key4 = tid >> 2, c4 = tid & 3;
    const float* kvb = QKV + (size_t)(b * T_) * 1536 + h * 64 + D_;

    int ntiles = (qb >> 6) + 2;
    for (int t = 0; t < ntiles; t++) {
        int k0 = t * 64;
        __syncthreads();
        #pragma unroll
        for (int i = 0; i < 4; i++) {
            int d = 4 * c4 + 16 * i;
            const float* kp = kvb + (size_t)(k0 + key4) * 1536 + d;
            uint4 kv = *(const uint4*)kp;        // values already tf32-rounded
            uint4 vv = *(const uint4*)(kp + D_);
            *(uint4*)&Ks[key4][d] = kv;
            Vs[d + 0][key4] = vv.x;
            Vs[d + 1][key4] = vv.y;
            Vs[d + 2][key4] = vv.z;
            Vs[d + 3][key4] = vv.w;
        }
        __syncthreads();

        float sc[8][4];
        #pragma unroll
        for (int j = 0; j < 8; j++) { sc[j][0] = sc[j][1] = sc[j][2] = sc[j][3] = 0.f; }
        #pragma unroll
        for (int j = 0; j < 8; j++) {
            int kr = 8 * j + grp;
            #pragma unroll
            for (int k = 0; k < 8; k++) {
                uint32_t bfr[2] = { Ks[kr][8 * k + tig], Ks[kr][8 * k + tig + 4] };
                mma_tf32(sc[j], qa[k], bfr);
            }
        }

        if (k0 + 63 > qb + wid * 16) {
            #pragma unroll
            for (int j = 0; j < 8; j++) {
                int key = k0 + 8 * j + 2 * tig;
                if (key     > gr0) sc[j][0] = -1e30f;
                if (key + 1 > gr0) sc[j][1] = -1e30f;
                if (key     > gr1) sc[j][2] = -1e30f;
                if (key + 1 > gr1) sc[j][3] = -1e30f;
            }
        }

        float mx0 = -1e30f, mx1 = -1e30f;
        #pragma unroll
        for (int j = 0; j < 8; j++) {
            mx0 = fmaxf(mx0, fmaxf(sc[j][0], sc[j][1]));
            mx1 = fmaxf(mx1, fmaxf(sc[j][2], sc[j][3]));
        }
        mx0 = fmaxf(mx0, __shfl_xor_sync(0xffffffffu, mx0, 1));
        mx0 = fmaxf(mx0, __shfl_xor_sync(0xffffffffu, mx0, 2));
        mx1 = fmaxf(mx1, __shfl_xor_sync(0xffffffffu, mx1, 1));
        mx1 = fmaxf(mx1, __shfl_xor_sync(0xffffffffu, mx1, 2));
        float mn0 = fmaxf(m0, mx0), mn1 = fmaxf(m1, mx1);
        float c0 = __expf(m0 - mn0), c1 = __expf(m1 - mn1);
        m0 = mn0; m1 = mn1;

        float s0 = 0.f, s1 = 0.f;
        #pragma unroll
        for (int j = 0; j < 8; j++) {
            float p0 = __expf(sc[j][0] - m0);
            float p1 = __expf(sc[j][1] - m0);
            float p2 = __expf(sc[j][2] - m1);
            float p3 = __expf(sc[j][3] - m1);
            s0 += p0 + p1; s1 += p2 + p3;
            *(uint2*)&Ps[lr0][8 * j + 2 * tig] = make_uint2(f2tf32(p0), f2tf32(p1));
            *(uint2*)&Ps[lr1][8 * j + 2 * tig] = make_uint2(f2tf32(p2), f2tf32(p3));
        }
        s0 += __shfl_xor_sync(0xffffffffu, s0, 1);
        s0 += __shfl_xor_sync(0xffffffffu, s0, 2);
        s1 += __shfl_xor_sync(0xffffffffu, s1, 1);
        s1 += __shfl_xor_sync(0xffffffffu, s1, 2);
        l0 = l0 * c0 + s0;
        l1 = l1 * c1 + s1;
        #pragma unroll
        for (int j = 0; j < 8; j++) {
            o[j][0] *= c0; o[j][1] *= c0; o[j][2] *= c1; o[j][3] *= c1;
        }
        __syncwarp();

        #pragma unroll
        for (int k = 0; k < 8; k++) {
            uint32_t a[4] = { Ps[lr0][8 * k + tig],     Ps[lr1][8 * k + tig],
                              Ps[lr0][8 * k + tig + 4], Ps[lr1][8 * k + tig + 4] };
            #pragma unroll
            for (int j = 0; j < 8; j++) {
                int nr = 8 * j + grp;
                uint32_t bfr[2] = { Vs[nr][8 * k + tig], Vs[nr][8 * k + tig + 4] };
                mma_tf32(o[j], a, bfr);
            }
        }
    }

    float i0 = 1.f / l0, i1 = 1.f / l1;
    uint32_t* ob0 = O + ((size_t)(b * T_) + gr0) * D_ + h * 64;
    uint32_t* ob1 = O + ((size_t)(b * T_) + gr1) * D_ + h * 64;
    #pragma unroll
    for (int j = 0; j < 8; j++) {
        *(uint2*)(ob0 + 8 * j + 2 * tig) =
            make_uint2(f2tf32(o[j][0] * i0), f2tf32(o[j][1] * i0));
        *(uint2*)(ob1 + 8 * j + 2 * tig) =
            make_uint2(f2tf32(o[j][2] * i1), f2tf32(o[j][3] * i1));
    }
}

#define ATTN_SMEM ((2 * 64 * KVSTR + 128 * KVSTR) * 4)

// ------------------------- loss --------------------------------------------
__global__ __launch_bounds__(256) void loss_kernel(const float* __restrict__ logits,
                                                   const int* __restrict__ targets,
                                                   double* __restrict__ acc) {
    int warp = (blockIdx.x * blockDim.x + threadIdx.x) >> 5;
    int lane = threadIdx.x & 31;
    const float* lr = logits + (size_t)warp * V_;
    float v0 = lr[lane], v1 = lr[lane + 32], v2 = lr[lane + 64];
    float m = fmaxf(v0, fmaxf(v1, v2));
    #pragma unroll
    for (int o = 16; o; o >>= 1) m = fmaxf(m, __shfl_xor_sync(0xffffffffu, m, o));
    float se = expf(v0 - m) + expf(v1 - m) + expf(v2 - m);
    #pragma unroll
    for (int o = 16; o; o >>= 1) se += __shfl_xor_sync(0xffffffffu, se, o);

    __shared__ float part[8];
    if (lane == 0) part[threadIdx.x >> 5] = lr[targets[warp]] - m - logf(se);
    __syncthreads();
    if (threadIdx.x == 0) {
        float s = 0.f;
        #pragma unroll
        for (int i = 0; i < 8; i++) s += part[i];
        atomicAdd(acc, (double)s);
    }
}

__global__ void finalize_loss_kernel(float* out, const double* acc) {
    out[(size_t)BT_ * V_] = (float)(-(*acc) / (double)BT_);
}

// ------------------------- launcher ----------------------------------------
extern "C" void kernel_launch(void* const* d_in, const int* in_sizes, int n_in,
                              void* d_out, int out_size) {
    const int*   idx     = (const int*)  d_in[0];
    const int*   targets = (const int*)  d_in[1];
    const float* tok     = (const float*)d_in[2];
    const float* pos     = (const float*)d_in[3];
    const float* Wq      = (const float*)d_in[4];
    const float* Wk      = (const float*)d_in[5];
    const float* Wv      = (const float*)d_in[6];
    const float* Wproj   = (const float*)d_in[7];
    const float* bproj   = (const float*)d_in[8];
    const float* W1      = (const float*)d_in[9];
    const float* b1      = (const float*)d_in[10];
    const float* W2      = (const float*)d_in[11];
    const float* b2      = (const float*)d_in[12];
    const float* ln1_s   = (const float*)d_in[13];
    const float* ln1_b   = (const float*)d_in[14];
    const float* ln2_s   = (const float*)d_in[15];
    const float* ln2_b   = (const float*)d_in[16];
    const float* lnf_s   = (const float*)d_in[17];
    const float* lnf_b   = (const float*)d_in[18];
    const float* Wout    = (const float*)d_in[19];
    const float* bout    = (const float*)d_in[20];
    float* out = (float*)d_out;

    float *x, *qkv;
    uint32_t *h, *o, *ff, *wp, *wproj_t, *w1_t, *w2_t, *wout_t;
    double* lossAcc;
    cudaGetSymbolAddress((void**)&x,   g_x);
    cudaGetSymbolAddress((void**)&h,   g_h);
    cudaGetSymbolAddress((void**)&qkv, g_qkv);
    cudaGetSymbolAddress((void**)&o,   g_o);
    cudaGetSymbolAddress((void**)&ff,  g_ff);
    cudaGetSymbolAddress((void**)&wp,  g_wp);
    cudaGetSymbolAddress((void**)&wproj_t, g_wproj_t);
    cudaGetSymbolAddress((void**)&w1_t, g_w1_t);
    cudaGetSymbolAddress((void**)&w2_t, g_w2_t);
    cudaGetSymbolAddress((void**)&wout_t, g_wout_t);
    cudaGetSymbolAddress((void**)&lossAcc, g_loss);

    cudaFuncSetAttribute(attn_kernel,
                         cudaFuncAttributeMaxDynamicSharedMemorySize, ATTN_SMEM);

    // weight pre-conversion to tf32
    {
        int n = L_ * D_ * 3 * D_;
        pack_qkv_kernel<<<(n + 255) / 256, 256>>>(Wq, Wk, Wv, wp);
        n = L_ * D_ * D_;
        cvt_tf32_kernel<<<(n + 255) / 256, 256>>>(Wproj, wproj_t, n);
        n = L_ * D_ * FF_;
        cvt_tf32_kernel<<<(n + 255) / 256, 256>>>(W1, w1_t, n);
        n = L_ * FF_ * D_;
        cvt_tf32_kernel<<<(n + 255) / 256, 256>>>(W2, w2_t, n);
        n = D_ * V_;
        cvt_tf32_kernel<<<(n + 255) / 256, 256>>>(Wout, wout_t, n);
    }
    {
        int total = BT_ * D_;
        embed_kernel<<<(total + 255) / 256, 256>>>(idx, tok, pos, x);
    }

    const int MT = BT_ / 128;  // 128 M-tiles
    for (int l = 0; l < L_; l++) {
        ln_kernel<<<BT_, 256>>>(x, ln1_s + l * D_, ln1_b + l * D_, h);
        tgemm_kernel<<<dim3(12, MT), 256>>>(h, wp + (size_t)l * D_ * 3 * D_,
                                            nullptr, nullptr, qkv,
                                            BT_, 3 * D_, D_, 0);
        attn_kernel<<<dim3(T_ / 128, B_ * H_), 256, ATTN_SMEM>>>(qkv, o);
        tgemm_kernel<<<dim3(4, MT), 256>>>(o, wproj_t + (size_t)l * D_ * D_,
                                           bproj + l * D_, x, x,
                                           BT_, D_, D_, 3);
        ln_kernel<<<BT_, 256>>>(x, ln2_s + l * D_, ln2_b + l * D_, h);
        tgemm_kernel<<<dim3(16, MT), 256>>>(h, w1_t + (size_t)l * D_ * FF_,
                                            b1 + l * FF_, nullptr, (float*)ff,
                                            BT_, FF_, D_, 2);
        tgemm_kernel<<<dim3(4, MT), 256>>>(ff, w2_t + (size_t)l * FF_ * D_,
                                           b2 + l * D_, x, x,
                                           BT_, D_, FF_, 3);
    }

    ln_kernel<<<BT_, 256>>>(x, lnf_s, lnf_b, h);
    tgemm_kernel<<<dim3(1, MT), 256>>>(h, wout_t, bout, nullptr, out,
                                       BT_, V_, D_, 1);

    if (out_size > BT_ * V_) {
        zero_loss_kernel<<<1, 1>>>(lossAcc);
        loss_kernel<<<BT_ / 8, 256>>>(out, targets, lossAcc);
        finalize_loss_kernel<<<1, 1>>>(out, lossAcc);
    }
}

// round 9
// speedup vs baseline: 2.9410x; 1.3675x over previous
#include <cuda_runtime.h>
#include <cuda_fp16.h>
#include <math.h>
#include <stdint.h>

// ---------------------------------------------------------------------------
// MiniTransformer forward: B=16, T=1024, D=512, H=8, HS=64, L=6, FF=2048, V=96
// Output: logits [16384, 96] (fp32) followed by scalar loss.
// GEMMs: mma.sync m16n8k16 fp16 (same mantissa as tf32, 2x MACs/instr).
// ---------------------------------------------------------------------------

#define B_   16
#define T_   1024
#define D_   512
#define H_   8
#define HS_  64
#define L_   6
#define FF_  2048
#define V_   96
#define BT_  (B_ * T_)

// ------------------------- device scratch (no mallocs) ---------------------
__device__ float g_x   [BT_ * D_];          // residual stream (fp32)
__device__ half  g_h   [BT_ * D_];          // LN output (fp16)
__device__ float g_qkv [BT_ * 3 * D_];      // q|k|v per token (fp32)
__device__ half  g_o   [BT_ * D_];          // attention output (fp16)
__device__ half  g_ff  [BT_ * FF_];         // FFN hidden (fp16)
// weights transposed to [n][k], fp16
__device__ half  g_wqkv [L_ * 3 * D_ * D_];
__device__ half  g_wproj[L_ * D_ * D_];
__device__ half  g_w1   [L_ * FF_ * D_];
__device__ half  g_w2   [L_ * D_ * FF_];
__device__ half  g_wout [V_ * D_];
__device__ double g_loss;

// ------------------------- helpers -----------------------------------------
__device__ __forceinline__ uint32_t f2tf32(float f) {
    uint32_t r;
    asm("cvt.rna.tf32.f32 %0, %1;" : "=r"(r) : "f"(f));
    return r;
}
__device__ __forceinline__ void cp16(uint32_t dst, const void* src, bool pred) {
    int sz = pred ? 16 : 0;
    asm volatile("cp.async.ca.shared.global [%0], [%1], 16, %2;\n"
                 :: "r"(dst), "l"(src), "r"(sz));
}
__device__ __forceinline__ void cp_commit() { asm volatile("cp.async.commit_group;\n"); }
__device__ __forceinline__ void cp_wait0()  { asm volatile("cp.async.wait_group 0;\n"); }

__device__ __forceinline__ void mma_f16(float* d, const uint32_t* a, const uint32_t* b) {
    asm volatile(
        "mma.sync.aligned.m16n8k16.row.col.f32.f16.f16.f32 "
        "{%0,%1,%2,%3}, {%4,%5,%6,%7}, {%8,%9}, {%0,%1,%2,%3};"
        : "+f"(d[0]), "+f"(d[1]), "+f"(d[2]), "+f"(d[3])
        : "r"(a[0]), "r"(a[1]), "r"(a[2]), "r"(a[3]), "r"(b[0]), "r"(b[1]));
}
__device__ __forceinline__ void mma_tf32(float* d, const uint32_t* a, const uint32_t* b) {
    asm volatile(
        "mma.sync.aligned.m16n8k8.row.col.f32.tf32.tf32.f32 "
        "{%0,%1,%2,%3}, {%4,%5,%6,%7}, {%8,%9}, {%0,%1,%2,%3};"
        : "+f"(d[0]), "+f"(d[1]), "+f"(d[2]), "+f"(d[3])
        : "r"(a[0]), "r"(a[1]), "r"(a[2]), "r"(a[3]), "r"(b[0]), "r"(b[1]));
}

// ------------------------- small kernels -----------------------------------
__global__ void zero_loss_kernel(double* a) { *a = 0.0; }

// W [L][K][N] row-major fp32 -> out [L][N][K] fp16
__global__ void pack_wt_kernel(const float* __restrict__ W,
                               half* __restrict__ out, int Lc, int K, int N) {
    int i = blockIdx.x * blockDim.x + threadIdx.x;
    if (i >= Lc * N * K) return;
    int k = i % K;
    int n = (i / K) % N;
    int l = i / (K * N);
    out[i] = __float2half(W[((size_t)l * K + k) * N + n]);
}

// Wq/Wk/Wv [L][H][D][HS] -> packed transposed [L][3D(n)][D(k)] fp16
__global__ void pack_qkv_kernel(const float* __restrict__ Wq,
                                const float* __restrict__ Wk,
                                const float* __restrict__ Wv,
                                half* __restrict__ out) {
    int i = blockIdx.x * blockDim.x + threadIdx.x;   // over L*1536*512
    if (i >= L_ * 3 * D_ * D_) return;
    int k = i % D_;
    int n = (i / D_) % (3 * D_);
    int l = i / (D_ * 3 * D_);
    int sel = n >> 9;
    int h   = (n & 511) >> 6;
    int hs  = n & 63;
    const float* W = (sel == 0) ? Wq : (sel == 1) ? Wk : Wv;
    out[i] = __float2half(W[(((size_t)l * H_ + h) * D_ + k) * HS_ + hs]);
}

__global__ void embed_kernel(const int* __restrict__ idx,
                             const float* __restrict__ tok,
                             const float* __restrict__ pos,
                             float* __restrict__ x) {
    int i = blockIdx.x * blockDim.x + threadIdx.x;
    if (i >= BT_ * D_) return;
    int d  = i & (D_ - 1);
    int bt = i >> 9;
    int t  = bt & (T_ - 1);
    x[i] = tok[(size_t)idx[bt] * D_ + d] + pos[t * D_ + d];
}

// One block per row; outputs fp16.
__global__ __launch_bounds__(256) void ln_kernel(const float* __restrict__ x,
                                                 const float* __restrict__ s,
                                                 const float* __restrict__ b,
                                                 half* __restrict__ out) {
    int row = blockIdx.x;
    int t   = threadIdx.x;
    const float* xr = x + (size_t)row * D_;
    float v0 = xr[t], v1 = xr[t + 256];

    float sum = v0 + v1;
    #pragma unroll
    for (int o = 16; o; o >>= 1) sum += __shfl_xor_sync(0xffffffffu, sum, o);
    __shared__ float red1[8], red2[8];
    if ((t & 31) == 0) red1[t >> 5] = sum;
    __syncthreads();
    float mean = 0.f;
    #pragma unroll
    for (int i = 0; i < 8; i++) mean += red1[i];
    mean *= (1.0f / D_);

    float d0 = v0 - mean, d1 = v1 - mean;
    float vs = d0 * d0 + d1 * d1;
    #pragma unroll
    for (int o = 16; o; o >>= 1) vs += __shfl_xor_sync(0xffffffffu, vs, o);
    if ((t & 31) == 0) red2[t >> 5] = vs;
    __syncthreads();
    float var = 0.f;
    #pragma unroll
    for (int i = 0; i < 8; i++) var += red2[i];
    var *= (1.0f / D_);

    float inv = rsqrtf(var + 1e-5f);
    half* orow = out + (size_t)row * D_;
    orow[t]       = __float2half(d0 * inv * s[t]       + b[t]);
    orow[t + 256] = __float2half(d1 * inv * s[t + 256] + b[t + 256]);
}

// ------------------------- FP16 tensor-core GEMM ---------------------------
// C[M,N] = A[M,K] * B^T[N,K]   (A [m][k] fp16, B [n][k] fp16)
// mode: 0 = fp32 store (QKV)
//       1 = +bias, fp32 store (logits)
//       2 = +bias, relu, fp16 store (FF1)
//       3 = +bias, +residual, fp32 store (proj, FF2)
// 128x128 tile, BK=32, 256 threads = 8 warps, warp tile 64(m) x 32(n).
// smem rows padded to 40 halves (80B): fragment banks (row*20+tig)%32 distinct.
#define BK2 32

__global__ __launch_bounds__(256, 2) void tgemm_kernel(
    const half* __restrict__ A, const half* __restrict__ Bm,
    const float* __restrict__ bias, const float* __restrict__ res,
    float* __restrict__ Cf, half* __restrict__ Ch,
    int M, int N, int K, int mode)
{
    __shared__ __align__(16) half As[2][128][40];   // [m][k halves], 80B rows
    __shared__ __align__(16) half Bs[2][128][40];   // [n][k halves]

    int tid  = threadIdx.x;
    int wid  = tid >> 5;
    int lane = tid & 31;
    int grp  = lane >> 2;          // 0..7
    int tig  = lane & 3;           // 0..3
    int warp_m = (wid & 1) * 64;
    int warp_n = (wid >> 1) * 32;

    // loaders: 512 16B-chunks per tile; thread t handles (row, c) and (row+64, c)
    int lrow = tid >> 2;           // 0..63
    int lc   = tid & 3;            // chunk within row (8 halves each)

    const half* Ap  = A + (size_t)(blockIdx.y * 128 + lrow) * K + lc * 8;
    const half* Ap2 = Ap + (size_t)64 * K;
    int gn  = blockIdx.x * 128 + lrow;
    int gn2 = gn + 64;
    bool bp  = gn  < N;
    bool bp2 = gn2 < N;
    const half* Bp  = Bm + (size_t)(bp  ? gn  : 0) * K + lc * 8;
    const half* Bp2 = Bm + (size_t)(bp2 ? gn2 : 0) * K + lc * 8;

    uint32_t aD[2][2], bD[2][2];
    #pragma unroll
    for (int bf = 0; bf < 2; bf++) {
        aD[bf][0] = (uint32_t)__cvta_generic_to_shared(&As[bf][lrow][lc * 8]);
        aD[bf][1] = (uint32_t)__cvta_generic_to_shared(&As[bf][lrow + 64][lc * 8]);
        bD[bf][0] = (uint32_t)__cvta_generic_to_shared(&Bs[bf][lrow][lc * 8]);
        bD[bf][1] = (uint32_t)__cvta_generic_to_shared(&Bs[bf][lrow + 64][lc * 8]);
    }

    float acc[4][4][4];
    #pragma unroll
    for (int i = 0; i < 4; i++)
        #pragma unroll
        for (int j = 0; j < 4; j++)
            #pragma unroll
            for (int r = 0; r < 4; r++) acc[i][j][r] = 0.f;

    // prologue: stage 0 -> buf 0
    cp16(aD[0][0], Ap, true);
    cp16(aD[0][1], Ap2, true);
    cp16(bD[0][0], Bp, bp);
    cp16(bD[0][1], Bp2, bp2);
    cp_commit();
    cp_wait0();
    __syncthreads();

    int nstage = K / BK2;
    int cur = 0;
    for (int s = 0; s < nstage; s++) {
        if (s + 1 < nstage) {
            int k0 = (s + 1) * BK2;
            int nxt = cur ^ 1;
            cp16(aD[nxt][0], Ap + k0, true);
            cp16(aD[nxt][1], Ap2 + k0, true);
            cp16(bD[nxt][0], Bp + k0, bp);
            cp16(bD[nxt][1], Bp2 + k0, bp2);
            cp_commit();
        }

        #pragma unroll
        for (int ks = 0; ks < 2; ks++) {
            int kh = ks * 16;
            uint32_t af[4][4];
            #pragma unroll
            for (int i = 0; i < 4; i++) {
                int mrow = warp_m + i * 16 + grp;
                af[i][0] = *(const uint32_t*)&As[cur][mrow][kh + 2 * tig];
                af[i][1] = *(const uint32_t*)&As[cur][mrow + 8][kh + 2 * tig];
                af[i][2] = *(const uint32_t*)&As[cur][mrow][kh + 2 * tig + 8];
                af[i][3] = *(const uint32_t*)&As[cur][mrow + 8][kh + 2 * tig + 8];
            }
            uint32_t bfr[4][2];
            #pragma unroll
            for (int j = 0; j < 4; j++) {
                int ncol = warp_n + j * 8 + grp;
                bfr[j][0] = *(const uint32_t*)&Bs[cur][ncol][kh + 2 * tig];
                bfr[j][1] = *(const uint32_t*)&Bs[cur][ncol][kh + 2 * tig + 8];
            }
            #pragma unroll
            for (int i = 0; i < 4; i++)
                #pragma unroll
                for (int j = 0; j < 4; j++)
                    mma_f16(acc[i][j], af[i], bfr[j]);
        }

        if (s + 1 < nstage) {
            cp_wait0();
            __syncthreads();
            cur ^= 1;
        }
    }

    #pragma unroll
    for (int i = 0; i < 4; i++) {
        int row0 = blockIdx.y * 128 + warp_m + i * 16 + grp;
        #pragma unroll
        for (int j = 0; j < 4; j++) {
            int col = blockIdx.x * 128 + warp_n + j * 8 + 2 * tig;
            if (col < N) {
                #pragma unroll
                for (int half_i = 0; half_i < 2; half_i++) {
                    int r = row0 + half_i * 8;
                    size_t rb = (size_t)r * N;
                    float v0 = acc[i][j][half_i * 2 + 0];
                    float v1 = acc[i][j][half_i * 2 + 1];
                    if (mode >= 1) { v0 += bias[col]; v1 += bias[col + 1]; }
                    if (mode == 2) {
                        v0 = fmaxf(v0, 0.f); v1 = fmaxf(v1, 0.f);
                        Ch[rb + col]     = __float2half(v0);
                        Ch[rb + col + 1] = __float2half(v1);
                    } else {
                        if (mode == 3) { v0 += res[rb + col]; v1 += res[rb + col + 1]; }
                        *(float2*)(Cf + rb + col) = make_float2(v0, v1);
                    }
                }
            }
        }
    }
}

// ------------------------- tensor-core flash attention (tf32) --------------
#define KVSTR 68

__global__ __launch_bounds__(256, 2) void attn_kernel(const float* __restrict__ QKV,
                                                      half* __restrict__ O) {
    extern __shared__ uint32_t sm[];
    uint32_t (*Ks)[KVSTR] = (uint32_t(*)[KVSTR])sm;
    uint32_t (*Vs)[KVSTR] = (uint32_t(*)[KVSTR])(sm + 64 * KVSTR);
    uint32_t (*Ps)[KVSTR] = (uint32_t(*)[KVSTR])(sm + 2 * 64 * KVSTR);

    int b = blockIdx.y >> 3, h = blockIdx.y & 7;
    int qb = blockIdx.x * 128;
    int tid = threadIdx.x, wid = tid >> 5, lane = tid & 31;
    int grp = lane >> 2, tig = lane & 3;
    const float scale = 0.04419417382415922f;   // 1/sqrt(512)

    int lr0 = wid * 16 + grp;
    int lr1 = lr0 + 8;
    int gr0 = qb + lr0, gr1 = qb + lr1;

    const float* q0p = QKV + ((size_t)(b * T_) + gr0) * 1536 + h * 64;
    const float* q1p = QKV + ((size_t)(b * T_) + gr1) * 1536 + h * 64;
    uint32_t qa[8][4];
    #pragma unroll
    for (int k = 0; k < 8; k++) {
        int d = 8 * k + tig;
        qa[k][0] = f2tf32(q0p[d]     * scale);
        qa[k][1] = f2tf32(q1p[d]     * scale);
        qa[k][2] = f2tf32(q0p[d + 4] * scale);
        qa[k][3] = f2tf32(q1p[d + 4] * scale);
    }

    float o[8][4];
    #pragma unroll
    for (int j = 0; j < 8; j++) { o[j][0] = o[j][1] = o[j][2] = o[j][3] = 0.f; }
    float m0 = -1e30f, m1 = -1e30f, l0 = 0.f, l1 = 0.f;

    int key4 = tid >> 2, c4 = tid & 3;
    const float* kvb = QKV + (size_t)(b * T_) * 1536 + h * 64 + D_;

    int ntiles = (qb >> 6) + 2;
    for (int t = 0; t < ntiles; t++) {
        int k0 = t * 64;
        __syncthreads();
        #pragma unroll
        for (int i = 0; i < 4; i++) {
            int d = 4 * c4 + 16 * i;
            const float* kp = kvb + (size_t)(k0 + key4) * 1536 + d;
            uint4 kv = *(const uint4*)kp;
            uint4 vv = *(const uint4*)(kp + D_);
            *(uint4*)&Ks[key4][d] = kv;
            Vs[d + 0][key4] = vv.x;
            Vs[d + 1][key4] = vv.y;
            Vs[d + 2][key4] = vv.z;
            Vs[d + 3][key4] = vv.w;
        }
        __syncthreads();

        float sc[8][4];
        #pragma unroll
        for (int j = 0; j < 8; j++) { sc[j][0] = sc[j][1] = sc[j][2] = sc[j][3] = 0.f; }
        #pragma unroll
        for (int j = 0; j < 8; j++) {
            int kr = 8 * j + grp;
            #pragma unroll
            for (int k = 0; k < 8; k++) {
                uint32_t bfr[2] = { Ks[kr][8 * k + tig], Ks[kr][8 * k + tig + 4] };
                mma_tf32(sc[j], qa[k], bfr);
            }
        }

        if (k0 + 63 > qb + wid * 16) {
            #pragma unroll
            for (int j = 0; j < 8; j++) {
                int key = k0 + 8 * j + 2 * tig;
                if (key     > gr0) sc[j][0] = -1e30f;
                if (key + 1 > gr0) sc[j][1] = -1e30f;
                if (key     > gr1) sc[j][2] = -1e30f;
                if (key + 1 > gr1) sc[j][3] = -1e30f;
            }
        }

        float mx0 = -1e30f, mx1 = -1e30f;
        #pragma unroll
        for (int j = 0; j < 8; j++) {
            mx0 = fmaxf(mx0, fmaxf(sc[j][0], sc[j][1]));
            mx1 = fmaxf(mx1, fmaxf(sc[j][2], sc[j][3]));
        }
        mx0 = fmaxf(mx0, __shfl_xor_sync(0xffffffffu, mx0, 1));
        mx0 = fmaxf(mx0, __shfl_xor_sync(0xffffffffu, mx0, 2));
        mx1 = fmaxf(mx1, __shfl_xor_sync(0xffffffffu, mx1, 1));
        mx1 = fmaxf(mx1, __shfl_xor_sync(0xffffffffu, mx1, 2));
        float mn0 = fmaxf(m0, mx0), mn1 = fmaxf(m1, mx1);
        float c0 = __expf(m0 - mn0), c1 = __expf(m1 - mn1);
        m0 = mn0; m1 = mn1;

        float s0 = 0.f, s1 = 0.f;
        #pragma unroll
        for (int j = 0; j < 8; j++) {
            float p0 = __expf(sc[j][0] - m0);
            float p1 = __expf(sc[j][1] - m0);
            float p2 = __expf(sc[j][2] - m1);
            float p3 = __expf(sc[j][3] - m1);
            s0 += p0 + p1; s1 += p2 + p3;
            *(uint2*)&Ps[lr0][8 * j + 2 * tig] = make_uint2(f2tf32(p0), f2tf32(p1));
            *(uint2*)&Ps[lr1][8 * j + 2 * tig] = make_uint2(f2tf32(p2), f2tf32(p3));
        }
        s0 += __shfl_xor_sync(0xffffffffu, s0, 1);
        s0 += __shfl_xor_sync(0xffffffffu, s0, 2);
        s1 += __shfl_xor_sync(0xffffffffu, s1, 1);
        s1 += __shfl_xor_sync(0xffffffffu, s1, 2);
        l0 = l0 * c0 + s0;
        l1 = l1 * c1 + s1;
        #pragma unroll
        for (int j = 0; j < 8; j++) {
            o[j][0] *= c0; o[j][1] *= c0; o[j][2] *= c1; o[j][3] *= c1;
        }
        __syncwarp();

        #pragma unroll
        for (int k = 0; k < 8; k++) {
            uint32_t a[4] = { Ps[lr0][8 * k + tig],     Ps[lr1][8 * k + tig],
                              Ps[lr0][8 * k + tig + 4], Ps[lr1][8 * k + tig + 4] };
            #pragma unroll
            for (int j = 0; j < 8; j++) {
                int nr = 8 * j + grp;
                uint32_t bfr[2] = { Vs[nr][8 * k + tig], Vs[nr][8 * k + tig + 4] };
                mma_tf32(o[j], a, bfr);
            }
        }
    }

    float i0 = 1.f / l0, i1 = 1.f / l1;
    size_t ob0 = ((size_t)(b * T_) + gr0) * D_ + h * 64;
    size_t ob1 = ((size_t)(b * T_) + gr1) * D_ + h * 64;
    #pragma unroll
    for (int j = 0; j < 8; j++) {
        int c = 8 * j + 2 * tig;
        O[ob0 + c]     = __float2half(o[j][0] * i0);
        O[ob0 + c + 1] = __float2half(o[j][1] * i0);
        O[ob1 + c]     = __float2half(o[j][2] * i1);
        O[ob1 + c + 1] = __float2half(o[j][3] * i1);
    }
}

#define ATTN_SMEM ((2 * 64 * KVSTR + 128 * KVSTR) * 4)

// ------------------------- loss --------------------------------------------
__global__ __launch_bounds__(256) void loss_kernel(const float* __restrict__ logits,
                                                   const int* __restrict__ targets,
                                                   double* __restrict__ acc) {
    int warp = (blockIdx.x * blockDim.x + threadIdx.x) >> 5;
    int lane = threadIdx.x & 31;
    const float* lr = logits + (size_t)warp * V_;
    float v0 = lr[lane], v1 = lr[lane + 32], v2 = lr[lane + 64];
    float m = fmaxf(v0, fmaxf(v1, v2));
    #pragma unroll
    for (int o = 16; o; o >>= 1) m = fmaxf(m, __shfl_xor_sync(0xffffffffu, m, o));
    float se = expf(v0 - m) + expf(v1 - m) + expf(v2 - m);
    #pragma unroll
    for (int o = 16; o; o >>= 1) se += __shfl_xor_sync(0xffffffffu, se, o);

    __shared__ float part[8];
    if (lane == 0) part[threadIdx.x >> 5] = lr[targets[warp]] - m - logf(se);
    __syncthreads();
    if (threadIdx.x == 0) {
        float s = 0.f;
        #pragma unroll
        for (int i = 0; i < 8; i++) s += part[i];
        atomicAdd(acc, (double)s);
    }
}

__global__ void finalize_loss_kernel(float* out, const double* acc) {
    out[(size_t)BT_ * V_] = (float)(-(*acc) / (double)BT_);
}

// ------------------------- launcher ----------------------------------------
extern "C" void kernel_launch(void* const* d_in, const int* in_sizes, int n_in,
                              void* d_out, int out_size) {
    const int*   idx     = (const int*)  d_in[0];
    const int*   targets = (const int*)  d_in[1];
    const float* tok     = (const float*)d_in[2];
    const float* pos     = (const float*)d_in[3];
    const float* Wq      = (const float*)d_in[4];
    const float* Wk      = (const float*)d_in[5];
    const float* Wv      = (const float*)d_in[6];
    const float* Wproj   = (const float*)d_in[7];
    const float* bproj   = (const float*)d_in[8];
    const float* W1      = (const float*)d_in[9];
    const float* b1      = (const float*)d_in[10];
    const float* W2      = (const float*)d_in[11];
    const float* b2      = (const float*)d_in[12];
    const float* ln1_s   = (const float*)d_in[13];
    const float* ln1_b   = (const float*)d_in[14];
    const float* ln2_s   = (const float*)d_in[15];
    const float* ln2_b   = (const float*)d_in[16];
    const float* lnf_s   = (const float*)d_in[17];
    const float* lnf_b   = (const float*)d_in[18];
    const float* Wout    = (const float*)d_in[19];
    const float* bout    = (const float*)d_in[20];
    float* out = (float*)d_out;

    float *x, *qkv;
    half *h, *o, *ff, *wqkv, *wproj, *w1, *w2, *wout;
    double* lossAcc;
    cudaGetSymbolAddress((void**)&x,    g_x);
    cudaGetSymbolAddress((void**)&qkv,  g_qkv);
    cudaGetSymbolAddress((void**)&h,    g_h);
    cudaGetSymbolAddress((void**)&o,    g_o);
    cudaGetSymbolAddress((void**)&ff,   g_ff);
    cudaGetSymbolAddress((void**)&wqkv, g_wqkv);
    cudaGetSymbolAddress((void**)&wproj, g_wproj);
    cudaGetSymbolAddress((void**)&w1,   g_w1);
    cudaGetSymbolAddress((void**)&w2,   g_w2);
    cudaGetSymbolAddress((void**)&wout, g_wout);
    cudaGetSymbolAddress((void**)&lossAcc, g_loss);

    cudaFuncSetAttribute(attn_kernel,
                         cudaFuncAttributeMaxDynamicSharedMemorySize, ATTN_SMEM);

    // weight packing (transpose + fp16)
    {
        int n = L_ * 3 * D_ * D_;
        pack_qkv_kernel<<<(n + 255) / 256, 256>>>(Wq, Wk, Wv, wqkv);
        n = L_ * D_ * D_;
        pack_wt_kernel<<<(n + 255) / 256, 256>>>(Wproj, wproj, L_, D_, D_);
        n = L_ * FF_ * D_;
        pack_wt_kernel<<<(n + 255) / 256, 256>>>(W1, w1, L_, D_, FF_);
        pack_wt_kernel<<<(n + 255) / 256, 256>>>(W2, w2, L_, FF_, D_);
        n = V_ * D_;
        pack_wt_kernel<<<(n + 255) / 256, 256>>>(Wout, wout, 1, D_, V_);
    }
    {
        int total = BT_ * D_;
        embed_kernel<<<(total + 255) / 256, 256>>>(idx, tok, pos, x);
    }

    const int MT = BT_ / 128;  // 128 M-tiles
    for (int l = 0; l < L_; l++) {
        ln_kernel<<<BT_, 256>>>(x, ln1_s + l * D_, ln1_b + l * D_, h);
        tgemm_kernel<<<dim3(12, MT), 256>>>(
            h, wqkv + (size_t)l * 3 * D_ * D_,
            nullptr, nullptr, qkv, nullptr, BT_, 3 * D_, D_, 0);
        attn_kernel<<<dim3(T_ / 128, B_ * H_), 256, ATTN_SMEM>>>(qkv, o);
        tgemm_kernel<<<dim3(4, MT), 256>>>(
            o, wproj + (size_t)l * D_ * D_,
            bproj + l * D_, x, x, nullptr, BT_, D_, D_, 3);
        ln_kernel<<<BT_, 256>>>(x, ln2_s + l * D_, ln2_b + l * D_, h);
        tgemm_kernel<<<dim3(16, MT), 256>>>(
            h, w1 + (size_t)l * FF_ * D_,
            b1 + l * FF_, nullptr, nullptr, ff, BT_, FF_, D_, 2);
        tgemm_kernel<<<dim3(4, MT), 256>>>(
            ff, w2 + (size_t)l * D_ * FF_,
            b2 + l * D_, x, x, nullptr, BT_, D_, FF_, 3);
    }

    ln_kernel<<<BT_, 256>>>(x, lnf_s, lnf_b, h);
    tgemm_kernel<<<dim3(1, MT), 256>>>(
        h, wout, bout, nullptr, out, nullptr, BT_, V_, D_, 1);

    if (out_size > BT_ * V_) {
        zero_loss_kernel<<<1, 1>>>(lossAcc);
        loss_kernel<<<BT_ / 8, 256>>>(out, targets, lossAcc);
        finalize_loss_kernel<<<1, 1>>>(out, lossAcc);
    }
}

// round 10
// speedup vs baseline: 4.0440x; 1.3750x over previous
#include <cuda_runtime.h>
#include <cuda_fp16.h>
#include <math.h>
#include <stdint.h>

// ---------------------------------------------------------------------------
// MiniTransformer forward: B=16, T=1024, D=512, H=8, HS=64, L=6, FF=2048, V=96
// Output: logits [16384, 96] (fp32) followed by scalar loss.
// GEMMs + attention: fp16 m16n8k16 mma with ldmatrix fragment loads.
// ---------------------------------------------------------------------------

#define B_   16
#define T_   1024
#define D_   512
#define H_   8
#define HS_  64
#define L_   6
#define FF_  2048
#define V_   96
#define BT_  (B_ * T_)

// ------------------------- device scratch (no mallocs) ---------------------
__device__ float g_x   [BT_ * D_];          // residual stream (fp32)
__device__ half  g_h   [BT_ * D_];          // LN output (fp16)
__device__ half  g_qkv [BT_ * 3 * D_];      // q|k|v per token (fp16)
__device__ half  g_o   [BT_ * D_];          // attention output (fp16)
__device__ half  g_ff  [BT_ * FF_];         // FFN hidden (fp16)
// weights transposed to [n][k], fp16
__device__ half  g_wqkv [L_ * 3 * D_ * D_];
__device__ half  g_wproj[L_ * D_ * D_];
__device__ half  g_w1   [L_ * FF_ * D_];
__device__ half  g_w2   [L_ * D_ * FF_];
__device__ half  g_wout [V_ * D_];
__device__ double g_loss;

// ------------------------- helpers -----------------------------------------
__device__ __forceinline__ void cp16(uint32_t dst, const void* src, bool pred) {
    int sz = pred ? 16 : 0;
    asm volatile("cp.async.ca.shared.global [%0], [%1], 16, %2;\n"
                 :: "r"(dst), "l"(src), "r"(sz));
}
__device__ __forceinline__ void cp_commit() { asm volatile("cp.async.commit_group;\n"); }
__device__ __forceinline__ void cp_wait0()  { asm volatile("cp.async.wait_group 0;\n"); }

__device__ __forceinline__ void mma_f16(float* d, const uint32_t* a, const uint32_t* b) {
    asm volatile(
        "mma.sync.aligned.m16n8k16.row.col.f32.f16.f16.f32 "
        "{%0,%1,%2,%3}, {%4,%5,%6,%7}, {%8,%9}, {%0,%1,%2,%3};"
        : "+f"(d[0]), "+f"(d[1]), "+f"(d[2]), "+f"(d[3])
        : "r"(a[0]), "r"(a[1]), "r"(a[2]), "r"(a[3]), "r"(b[0]), "r"(b[1]));
}
__device__ __forceinline__ void ldsm_x4(uint32_t* r, uint32_t addr) {
    asm volatile("ldmatrix.sync.aligned.m8n8.x4.shared.b16 {%0,%1,%2,%3}, [%4];"
                 : "=r"(r[0]), "=r"(r[1]), "=r"(r[2]), "=r"(r[3]) : "r"(addr));
}
__device__ __forceinline__ void ldsm_x4_t(uint32_t* r, uint32_t addr) {
    asm volatile("ldmatrix.sync.aligned.m8n8.x4.trans.shared.b16 {%0,%1,%2,%3}, [%4];"
                 : "=r"(r[0]), "=r"(r[1]), "=r"(r[2]), "=r"(r[3]) : "r"(addr));
}

// ------------------------- small kernels -----------------------------------
__global__ void zero_loss_kernel(double* a) { *a = 0.0; }

// W [L][K][N] row-major fp32 -> out [L][N][K] fp16
__global__ void pack_wt_kernel(const float* __restrict__ W,
                               half* __restrict__ out, int Lc, int K, int N) {
    int i = blockIdx.x * blockDim.x + threadIdx.x;
    if (i >= Lc * N * K) return;
    int k = i % K;
    int n = (i / K) % N;
    int l = i / (K * N);
    out[i] = __float2half(W[((size_t)l * K + k) * N + n]);
}

// Wq/Wk/Wv [L][H][D][HS] -> packed transposed [L][3D(n)][D(k)] fp16
__global__ void pack_qkv_kernel(const float* __restrict__ Wq,
                                const float* __restrict__ Wk,
                                const float* __restrict__ Wv,
                                half* __restrict__ out) {
    int i = blockIdx.x * blockDim.x + threadIdx.x;   // over L*1536*512
    if (i >= L_ * 3 * D_ * D_) return;
    int k = i % D_;
    int n = (i / D_) % (3 * D_);
    int l = i / (D_ * 3 * D_);
    int sel = n >> 9;
    int h   = (n & 511) >> 6;
    int hs  = n & 63;
    const float* W = (sel == 0) ? Wq : (sel == 1) ? Wk : Wv;
    out[i] = __float2half(W[(((size_t)l * H_ + h) * D_ + k) * HS_ + hs]);
}

__global__ void embed_kernel(const int* __restrict__ idx,
                             const float* __restrict__ tok,
                             const float* __restrict__ pos,
                             float* __restrict__ x) {
    int i = blockIdx.x * blockDim.x + threadIdx.x;
    if (i >= BT_ * D_) return;
    int d  = i & (D_ - 1);
    int bt = i >> 9;
    int t  = bt & (T_ - 1);
    x[i] = tok[(size_t)idx[bt] * D_ + d] + pos[t * D_ + d];
}

// One block per row; outputs fp16.
__global__ __launch_bounds__(256) void ln_kernel(const float* __restrict__ x,
                                                 const float* __restrict__ s,
                                                 const float* __restrict__ b,
                                                 half* __restrict__ out) {
    int row = blockIdx.x;
    int t   = threadIdx.x;
    const float* xr = x + (size_t)row * D_;
    float v0 = xr[t], v1 = xr[t + 256];

    float sum = v0 + v1;
    #pragma unroll
    for (int o = 16; o; o >>= 1) sum += __shfl_xor_sync(0xffffffffu, sum, o);
    __shared__ float red1[8], red2[8];
    if ((t & 31) == 0) red1[t >> 5] = sum;
    __syncthreads();
    float mean = 0.f;
    #pragma unroll
    for (int i = 0; i < 8; i++) mean += red1[i];
    mean *= (1.0f / D_);

    float d0 = v0 - mean, d1 = v1 - mean;
    float vs = d0 * d0 + d1 * d1;
    #pragma unroll
    for (int o = 16; o; o >>= 1) vs += __shfl_xor_sync(0xffffffffu, vs, o);
    if ((t & 31) == 0) red2[t >> 5] = vs;
    __syncthreads();
    float var = 0.f;
    #pragma unroll
    for (int i = 0; i < 8; i++) var += red2[i];
    var *= (1.0f / D_);

    float inv = rsqrtf(var + 1e-5f);
    half* orow = out + (size_t)row * D_;
    orow[t]       = __float2half(d0 * inv * s[t]       + b[t]);
    orow[t + 256] = __float2half(d1 * inv * s[t + 256] + b[t + 256]);
}

// ------------------------- FP16 tensor-core GEMM (ldmatrix) ----------------
// C[M,N] = A[M,K] * B^T[N,K]   (A [m][k] fp16, B [n][k] fp16)
// mode: 0 = fp16 store (QKV)
//       1 = +bias, fp32 store (logits)
//       2 = +bias, relu, fp16 store (FF1)
//       3 = +bias, +residual, fp32 store (proj, FF2)
// 128x128 tile, BK=32, 256 threads = 8 warps, warp tile 64(m) x 32(n).
// smem rows 40 halves (80B): ldmatrix phase banks 20r%32 all distinct.
#define BK2 32
#define GROWB 80            // row stride bytes
#define GBUFB (128 * 80)    // buffer size bytes (per array)

__global__ __launch_bounds__(256, 2) void tgemm_kernel(
    const half* __restrict__ A, const half* __restrict__ Bm,
    const float* __restrict__ bias, const float* __restrict__ res,
    float* __restrict__ Cf, half* __restrict__ Ch,
    int M, int N, int K, int mode)
{
    __shared__ __align__(16) half As[2][128][40];
    __shared__ __align__(16) half Bs[2][128][40];

    int tid  = threadIdx.x;
    int wid  = tid >> 5;
    int lane = tid & 31;
    int grp  = lane >> 2;
    int tig  = lane & 3;
    int warp_m = (wid & 1) * 64;
    int warp_n = (wid >> 1) * 32;

    // gmem loaders (cp.async): thread -> rows lrow, lrow+64, chunk lc
    int lrow = tid >> 2;
    int lc   = tid & 3;

    const half* Ap  = A + (size_t)(blockIdx.y * 128 + lrow) * K + lc * 8;
    const half* Ap2 = Ap + (size_t)64 * K;
    int gn  = blockIdx.x * 128 + lrow;
    int gn2 = gn + 64;
    bool bp  = gn  < N;
    bool bp2 = gn2 < N;
    const half* Bp  = Bm + (size_t)(bp  ? gn  : 0) * K + lc * 8;
    const half* Bp2 = Bm + (size_t)(bp2 ? gn2 : 0) * K + lc * 8;

    uint32_t aD[2][2], bD[2][2];
    #pragma unroll
    for (int bf = 0; bf < 2; bf++) {
        aD[bf][0] = (uint32_t)__cvta_generic_to_shared(&As[bf][lrow][lc * 8]);
        aD[bf][1] = (uint32_t)__cvta_generic_to_shared(&As[bf][lrow + 64][lc * 8]);
        bD[bf][0] = (uint32_t)__cvta_generic_to_shared(&Bs[bf][lrow][lc * 8]);
        bD[bf][1] = (uint32_t)__cvta_generic_to_shared(&Bs[bf][lrow + 64][lc * 8]);
    }

    // ldmatrix base addrs (buf 0, k0 = 0)
    // A: row = warp_m + (l&7) + ((l>>3)&1)*8, col chunk = (l>>4)*8
    uint32_t aLd = (uint32_t)__cvta_generic_to_shared(
        &As[0][warp_m + (lane & 7) + ((lane >> 3) & 1) * 8][(lane >> 4) * 8]);
    // B: row = warp_n + (l&7) + (l>>4)*8, col chunk = ((l>>3)&1)*8
    uint32_t bLd = (uint32_t)__cvta_generic_to_shared(
        &Bs[0][warp_n + (lane & 7) + (lane >> 4) * 8][((lane >> 3) & 1) * 8]);

    float acc[4][4][4];
    #pragma unroll
    for (int i = 0; i < 4; i++)
        #pragma unroll
        for (int j = 0; j < 4; j++)
            #pragma unroll
            for (int r = 0; r < 4; r++) acc[i][j][r] = 0.f;

    // prologue: stage 0 -> buf 0
    cp16(aD[0][0], Ap, true);
    cp16(aD[0][1], Ap2, true);
    cp16(bD[0][0], Bp, bp);
    cp16(bD[0][1], Bp2, bp2);
    cp_commit();
    cp_wait0();
    __syncthreads();

    int nstage = K / BK2;
    int cur = 0;
    for (int s = 0; s < nstage; s++) {
        if (s + 1 < nstage) {
            int k0 = (s + 1) * BK2;
            int nxt = cur ^ 1;
            cp16(aD[nxt][0], Ap + k0, true);
            cp16(aD[nxt][1], Ap2 + k0, true);
            cp16(bD[nxt][0], Bp + k0, bp);
            cp16(bD[nxt][1], Bp2 + k0, bp2);
            cp_commit();
        }

        uint32_t bo = cur * GBUFB;
        #pragma unroll
        for (int ks = 0; ks < 2; ks++) {
            uint32_t af[4][4];
            #pragma unroll
            for (int i = 0; i < 4; i++)
                ldsm_x4(af[i], aLd + bo + i * (16 * GROWB) + ks * 32);
            uint32_t bq[2][4];
            #pragma unroll
            for (int jb = 0; jb < 2; jb++)
                ldsm_x4(bq[jb], bLd + bo + jb * (16 * GROWB) + ks * 32);
            #pragma unroll
            for (int i = 0; i < 4; i++)
                #pragma unroll
                for (int j = 0; j < 4; j++)
                    mma_f16(acc[i][j], af[i], &bq[j >> 1][2 * (j & 1)]);
        }

        if (s + 1 < nstage) {
            cp_wait0();
            __syncthreads();
            cur ^= 1;
        }
    }

    #pragma unroll
    for (int i = 0; i < 4; i++) {
        int row0 = blockIdx.y * 128 + warp_m + i * 16 + grp;
        #pragma unroll
        for (int j = 0; j < 4; j++) {
            int col = blockIdx.x * 128 + warp_n + j * 8 + 2 * tig;
            if (col < N) {
                #pragma unroll
                for (int hf = 0; hf < 2; hf++) {
                    int r = row0 + hf * 8;
                    size_t rb = (size_t)r * N;
                    float v0 = acc[i][j][hf * 2 + 0];
                    float v1 = acc[i][j][hf * 2 + 1];
                    if (mode >= 1) { v0 += bias[col]; v1 += bias[col + 1]; }
                    if (mode == 2) { v0 = fmaxf(v0, 0.f); v1 = fmaxf(v1, 0.f); }
                    if (mode == 0 || mode == 2) {
                        *(half2*)(Ch + rb + col) = __floats2half2_rn(v0, v1);
                    } else {
                        if (mode == 3) { v0 += res[rb + col]; v1 += res[rb + col + 1]; }
                        *(float2*)(Cf + rb + col) = make_float2(v0, v1);
                    }
                }
            }
        }
    }
}

// ------------------------- fp16 tensor-core flash attention ----------------
// 128 queries/block, 8 warps x 16 query-rows, 64-key tiles.
// K smem [key][d] (B-op non-trans ldmatrix), V smem [key][d] (B-op .trans),
// P smem [query][key] fp16 (A-op non-trans). Row stride 72 halves (144B):
// ldmatrix phase banks 36r%32 = 4r -> conflict-free.
#define KH_ 72
#define KROWB 144

__global__ __launch_bounds__(256, 2) void attn_kernel(const half* __restrict__ QKV,
                                                      half* __restrict__ O) {
    __shared__ __align__(16) half Ks[64][KH_];
    __shared__ __align__(16) half Vs[64][KH_];
    __shared__ __align__(16) half Ps[128][KH_];

    int b = blockIdx.y >> 3, h = blockIdx.y & 7;
    int qb = blockIdx.x * 128;
    int tid = threadIdx.x, wid = tid >> 5, lane = tid & 31;
    int grp = lane >> 2, tig = lane & 3;
    const float scale = 0.04419417382415922f;   // 1/sqrt(512)

    int lr0 = wid * 16 + grp;
    int lr1 = lr0 + 8;
    int gr0 = qb + lr0, gr1 = qb + lr1;

    // Q fragments (fp16 pairs, scaled)
    const half* q0p = QKV + ((size_t)(b * T_) + gr0) * 1536 + h * 64;
    const half* q1p = QKV + ((size_t)(b * T_) + gr1) * 1536 + h * 64;
    uint32_t qa[4][4];
    #pragma unroll
    for (int k = 0; k < 4; k++) {
        int dd = 16 * k + 2 * tig;
        #pragma unroll
        for (int r = 0; r < 4; r++) {
            const half* qp = (r & 1) ? q1p : q0p;
            int d2 = dd + (r >> 1) * 8;
            float2 f = __half22float2(*(const half2*)(qp + d2));
            half2 hv = __floats2half2_rn(f.x * scale, f.y * scale);
            qa[k][r] = *(uint32_t*)&hv;
        }
    }

    // ldmatrix bases
    uint32_t kLd = (uint32_t)__cvta_generic_to_shared(
        &Ks[(lane & 7) + (lane >> 4) * 8][((lane >> 3) & 1) * 8]);
    uint32_t vLd = (uint32_t)__cvta_generic_to_shared(
        &Vs[(lane & 7) + ((lane >> 3) & 1) * 8][(lane >> 4) * 8]);
    uint32_t pLd = (uint32_t)__cvta_generic_to_shared(
        &Ps[wid * 16 + (lane & 7) + ((lane >> 3) & 1) * 8][(lane >> 4) * 8]);

    float o[8][4];
    #pragma unroll
    for (int j = 0; j < 8; j++) { o[j][0] = o[j][1] = o[j][2] = o[j][3] = 0.f; }
    float m0 = -1e30f, m1 = -1e30f, l0 = 0.f, l1 = 0.f;

    int key4 = tid >> 2, c4 = tid & 3;
    const half* kvb = QKV + (size_t)(b * T_) * 1536 + h * 64 + D_;   // K base

    int ntiles = (qb >> 6) + 2;
    for (int t = 0; t < ntiles; t++) {
        int k0 = t * 64;
        __syncthreads();
        // load K and V tiles (fp16, key-major)
        {
            const half* kp = kvb + (size_t)(k0 + key4) * 1536;
            #pragma unroll
            for (int tt = 0; tt < 2; tt++) {
                int d = 8 * c4 + 32 * tt;
                *(uint4*)&Ks[key4][d] = *(const uint4*)(kp + d);
                *(uint4*)&Vs[key4][d] = *(const uint4*)(kp + 512 + d);
            }
        }
        __syncthreads();

        // S = Q @ K^T : 4 k16-steps over d, 8 key-subtiles
        float sc[8][4];
        #pragma unroll
        for (int j = 0; j < 8; j++) { sc[j][0] = sc[j][1] = sc[j][2] = sc[j][3] = 0.f; }
        #pragma unroll
        for (int kd = 0; kd < 4; kd++) {
            uint32_t kq[4][4];
            #pragma unroll
            for (int jp = 0; jp < 4; jp++)
                ldsm_x4(kq[jp], kLd + jp * (16 * KROWB) + kd * 32);
            #pragma unroll
            for (int j = 0; j < 8; j++)
                mma_f16(sc[j], qa[kd], &kq[j >> 1][2 * (j & 1)]);
        }

        if (k0 + 63 > qb + wid * 16) {
            #pragma unroll
            for (int j = 0; j < 8; j++) {
                int key = k0 + 8 * j + 2 * tig;
                if (key     > gr0) sc[j][0] = -1e30f;
                if (key + 1 > gr0) sc[j][1] = -1e30f;
                if (key     > gr1) sc[j][2] = -1e30f;
                if (key + 1 > gr1) sc[j][3] = -1e30f;
            }
        }

        // online softmax
        float mx0 = -1e30f, mx1 = -1e30f;
        #pragma unroll
        for (int j = 0; j < 8; j++) {
            mx0 = fmaxf(mx0, fmaxf(sc[j][0], sc[j][1]));
            mx1 = fmaxf(mx1, fmaxf(sc[j][2], sc[j][3]));
        }
        mx0 = fmaxf(mx0, __shfl_xor_sync(0xffffffffu, mx0, 1));
        mx0 = fmaxf(mx0, __shfl_xor_sync(0xffffffffu, mx0, 2));
        mx1 = fmaxf(mx1, __shfl_xor_sync(0xffffffffu, mx1, 1));
        mx1 = fmaxf(mx1, __shfl_xor_sync(0xffffffffu, mx1, 2));
        float mn0 = fmaxf(m0, mx0), mn1 = fmaxf(m1, mx1);
        float c0 = __expf(m0 - mn0), c1 = __expf(m1 - mn1);
        m0 = mn0; m1 = mn1;

        float s0 = 0.f, s1 = 0.f;
        #pragma unroll
        for (int j = 0; j < 8; j++) {
            float p0 = __expf(sc[j][0] - m0);
            float p1 = __expf(sc[j][1] - m0);
            float p2 = __expf(sc[j][2] - m1);
            float p3 = __expf(sc[j][3] - m1);
            s0 += p0 + p1; s1 += p2 + p3;
            *(half2*)&Ps[lr0][8 * j + 2 * tig] = __floats2half2_rn(p0, p1);
            *(half2*)&Ps[lr1][8 * j + 2 * tig] = __floats2half2_rn(p2, p3);
        }
        s0 += __shfl_xor_sync(0xffffffffu, s0, 1);
        s0 += __shfl_xor_sync(0xffffffffu, s0, 2);
        s1 += __shfl_xor_sync(0xffffffffu, s1, 1);
        s1 += __shfl_xor_sync(0xffffffffu, s1, 2);
        l0 = l0 * c0 + s0;
        l1 = l1 * c1 + s1;
        #pragma unroll
        for (int j = 0; j < 8; j++) {
            o[j][0] *= c0; o[j][1] *= c0; o[j][2] *= c1; o[j][3] *= c1;
        }
        __syncwarp();   // P visible within warp

        // O += P @ V : 4 k16-steps over keys, 8 d-subtiles
        #pragma unroll
        for (int kd = 0; kd < 4; kd++) {
            uint32_t pa[4];
            ldsm_x4(pa, pLd + kd * 32);
            uint32_t vq[4][4];
            #pragma unroll
            for (int jp = 0; jp < 4; jp++)
                ldsm_x4_t(vq[jp], vLd + kd * (16 * KROWB) + jp * 32);
            #pragma unroll
            for (int j = 0; j < 8; j++)
                mma_f16(o[j], pa, &vq[j >> 1][2 * (j & 1)]);
        }
    }

    float i0 = 1.f / l0, i1 = 1.f / l1;
    size_t ob0 = ((size_t)(b * T_) + gr0) * D_ + h * 64;
    size_t ob1 = ((size_t)(b * T_) + gr1) * D_ + h * 64;
    #pragma unroll
    for (int j = 0; j < 8; j++) {
        int c = 8 * j + 2 * tig;
        *(half2*)(O + ob0 + c) = __floats2half2_rn(o[j][0] * i0, o[j][1] * i0);
        *(half2*)(O + ob1 + c) = __floats2half2_rn(o[j][2] * i1, o[j][3] * i1);
    }
}

// ------------------------- loss --------------------------------------------
__global__ __launch_bounds__(256) void loss_kernel(const float* __restrict__ logits,
                                                   const int* __restrict__ targets,
                                                   double* __restrict__ acc) {
    int warp = (blockIdx.x * blockDim.x + threadIdx.x) >> 5;
    int lane = threadIdx.x & 31;
    const float* lr = logits + (size_t)warp * V_;
    float v0 = lr[lane], v1 = lr[lane + 32], v2 = lr[lane + 64];
    float m = fmaxf(v0, fmaxf(v1, v2));
    #pragma unroll
    for (int o = 16; o; o >>= 1) m = fmaxf(m, __shfl_xor_sync(0xffffffffu, m, o));
    float se = expf(v0 - m) + expf(v1 - m) + expf(v2 - m);
    #pragma unroll
    for (int o = 16; o; o >>= 1) se += __shfl_xor_sync(0xffffffffu, se, o);

    __shared__ float part[8];
    if (lane == 0) part[threadIdx.x >> 5] = lr[targets[warp]] - m - logf(se);
    __syncthreads();
    if (threadIdx.x == 0) {
        float s = 0.f;
        #pragma unroll
        for (int i = 0; i < 8; i++) s += part[i];
        atomicAdd(acc, (double)s);
    }
}

__global__ void finalize_loss_kernel(float* out, const double* acc) {
    out[(size_t)BT_ * V_] = (float)(-(*acc) / (double)BT_);
}

// ------------------------- launcher ----------------------------------------
extern "C" void kernel_launch(void* const* d_in, const int* in_sizes, int n_in,
                              void* d_out, int out_size) {
    const int*   idx     = (const int*)  d_in[0];
    const int*   targets = (const int*)  d_in[1];
    const float* tok     = (const float*)d_in[2];
    const float* pos     = (const float*)d_in[3];
    const float* Wq      = (const float*)d_in[4];
    const float* Wk      = (const float*)d_in[5];
    const float* Wv      = (const float*)d_in[6];
    const float* Wproj   = (const float*)d_in[7];
    const float* bproj   = (const float*)d_in[8];
    const float* W1      = (const float*)d_in[9];
    const float* b1      = (const float*)d_in[10];
    const float* W2      = (const float*)d_in[11];
    const float* b2      = (const float*)d_in[12];
    const float* ln1_s   = (const float*)d_in[13];
    const float* ln1_b   = (const float*)d_in[14];
    const float* ln2_s   = (const float*)d_in[15];
    const float* ln2_b   = (const float*)d_in[16];
    const float* lnf_s   = (const float*)d_in[17];
    const float* lnf_b   = (const float*)d_in[18];
    const float* Wout    = (const float*)d_in[19];
    const float* bout    = (const float*)d_in[20];
    float* out = (float*)d_out;

    float* x;
    half *h, *qkv, *o, *ff, *wqkv, *wproj, *w1, *w2, *wout;
    double* lossAcc;
    cudaGetSymbolAddress((void**)&x,    g_x);
    cudaGetSymbolAddress((void**)&qkv,  g_qkv);
    cudaGetSymbolAddress((void**)&h,    g_h);
    cudaGetSymbolAddress((void**)&o,    g_o);
    cudaGetSymbolAddress((void**)&ff,   g_ff);
    cudaGetSymbolAddress((void**)&wqkv, g_wqkv);
    cudaGetSymbolAddress((void**)&wproj, g_wproj);
    cudaGetSymbolAddress((void**)&w1,   g_w1);
    cudaGetSymbolAddress((void**)&w2,   g_w2);
    cudaGetSymbolAddress((void**)&wout, g_wout);
    cudaGetSymbolAddress((void**)&lossAcc, g_loss);

    // weight packing (transpose + fp16)
    {
        int n = L_ * 3 * D_ * D_;
        pack_qkv_kernel<<<(n + 255) / 256, 256>>>(Wq, Wk, Wv, wqkv);
        n = L_ * D_ * D_;
        pack_wt_kernel<<<(n + 255) / 256, 256>>>(Wproj, wproj, L_, D_, D_);
        n = L_ * FF_ * D_;
        pack_wt_kernel<<<(n + 255) / 256, 256>>>(W1, w1, L_, D_, FF_);
        pack_wt_kernel<<<(n + 255) / 256, 256>>>(W2, w2, L_, FF_, D_);
        n = V_ * D_;
        pack_wt_kernel<<<(n + 255) / 256, 256>>>(Wout, wout, 1, D_, V_);
    }
    {
        int total = BT_ * D_;
        embed_kernel<<<(total + 255) / 256, 256>>>(idx, tok, pos, x);
    }

    const int MT = BT_ / 128;  // 128 M-tiles
    for (int l = 0; l < L_; l++) {
        ln_kernel<<<BT_, 256>>>(x, ln1_s + l * D_, ln1_b + l * D_, h);
        tgemm_kernel<<<dim3(12, MT), 256>>>(
            h, wqkv + (size_t)l * 3 * D_ * D_,
            nullptr, nullptr, nullptr, qkv, BT_, 3 * D_, D_, 0);
        attn_kernel<<<dim3(T_ / 128, B_ * H_), 256>>>(qkv, o);
        tgemm_kernel<<<dim3(4, MT), 256>>>(
            o, wproj + (size_t)l * D_ * D_,
            bproj + l * D_, x, x, nullptr, BT_, D_, D_, 3);
        ln_kernel<<<BT_, 256>>>(x, ln2_s + l * D_, ln2_b + l * D_, h);
        tgemm_kernel<<<dim3(16, MT), 256>>>(
            h, w1 + (size_t)l * FF_ * D_,
            b1 + l * FF_, nullptr, nullptr, ff, BT_, FF_, D_, 2);
        tgemm_kernel<<<dim3(4, MT), 256>>>(
            ff, w2 + (size_t)l * D_ * FF_,
            b2 + l * D_, x, x, nullptr, BT_, D_, FF_, 3);
    }

    ln_kernel<<<BT_, 256>>>(x, lnf_s, lnf_b, h);
    tgemm_kernel<<<dim3(1, MT), 256>>>(
        h, wout, bout, nullptr, out, nullptr, BT_, V_, D_, 1);

    if (out_size > BT_ * V_) {
        zero_loss_kernel<<<1, 1>>>(lossAcc);
        loss_kernel<<<BT_ / 8, 256>>>(out, targets, lossAcc);
        finalize_loss_kernel<<<1, 1>>>(out, lossAcc);
    }
}

// round 11
// speedup vs baseline: 4.1495x; 1.0261x over previous
#include <cuda_runtime.h>
#include <cuda_fp16.h>
#include <math.h>
#include <stdint.h>

// ---------------------------------------------------------------------------
// MiniTransformer forward: B=16, T=1024, D=512, H=8, HS=64, L=6, FF=2048, V=96
// Output: logits [16384, 96] (fp32) followed by scalar loss.
// GEMMs + attention: fp16 m16n8k16 mma with ldmatrix fragment loads.
// ---------------------------------------------------------------------------

#define B_   16
#define T_   1024
#define D_   512
#define H_   8
#define HS_  64
#define L_   6
#define FF_  2048
#define V_   96
#define BT_  (B_ * T_)

// ------------------------- device scratch (no mallocs) ---------------------
__device__ float g_x   [BT_ * D_];          // residual stream (fp32)
__device__ half  g_h   [BT_ * D_];          // LN output (fp16)
__device__ half  g_qkv [BT_ * 3 * D_];      // q|k|v per token (fp16)
__device__ half  g_o   [BT_ * D_];          // attention output (fp16)
__device__ half  g_ff  [BT_ * FF_];         // FFN hidden (fp16)
// weights transposed to [n][k], fp16
__device__ half  g_wqkv [L_ * 3 * D_ * D_];
__device__ half  g_wproj[L_ * D_ * D_];
__device__ half  g_w1   [L_ * FF_ * D_];
__device__ half  g_w2   [L_ * D_ * FF_];
__device__ half  g_wout [V_ * D_];
__device__ double g_loss;

// ------------------------- helpers -----------------------------------------
__device__ __forceinline__ void cp16(uint32_t dst, const void* src, bool pred) {
    int sz = pred ? 16 : 0;
    asm volatile("cp.async.ca.shared.global [%0], [%1], 16, %2;\n"
                 :: "r"(dst), "l"(src), "r"(sz));
}
__device__ __forceinline__ void cp_commit() { asm volatile("cp.async.commit_group;\n"); }
__device__ __forceinline__ void cp_wait0()  { asm volatile("cp.async.wait_group 0;\n"); }

__device__ __forceinline__ void mma_f16(float* d, const uint32_t* a, const uint32_t* b) {
    asm volatile(
        "mma.sync.aligned.m16n8k16.row.col.f32.f16.f16.f32 "
        "{%0,%1,%2,%3}, {%4,%5,%6,%7}, {%8,%9}, {%0,%1,%2,%3};"
        : "+f"(d[0]), "+f"(d[1]), "+f"(d[2]), "+f"(d[3])
        : "r"(a[0]), "r"(a[1]), "r"(a[2]), "r"(a[3]), "r"(b[0]), "r"(b[1]));
}
__device__ __forceinline__ void ldsm_x4(uint32_t* r, uint32_t addr) {
    asm volatile("ldmatrix.sync.aligned.m8n8.x4.shared.b16 {%0,%1,%2,%3}, [%4];"
                 : "=r"(r[0]), "=r"(r[1]), "=r"(r[2]), "=r"(r[3]) : "r"(addr));
}
__device__ __forceinline__ void ldsm_x4_t(uint32_t* r, uint32_t addr) {
    asm volatile("ldmatrix.sync.aligned.m8n8.x4.trans.shared.b16 {%0,%1,%2,%3}, [%4];"
                 : "=r"(r[0]), "=r"(r[1]), "=r"(r[2]), "=r"(r[3]) : "r"(addr));
}

// ------------------------- small kernels -----------------------------------
__global__ void zero_loss_kernel(double* a) { *a = 0.0; }

// W [Lc][K][N] fp32 -> out [Lc][N][K] fp16, coalesced via 32x32 smem tiles.
// grid: (N/32, K/32, Lc), block (32, 8).
__global__ void pack_wt_kernel(const float* __restrict__ W,
                               half* __restrict__ out, int K, int N) {
    __shared__ float tile[32][33];
    int l  = blockIdx.z;
    int n0 = blockIdx.x * 32, k0 = blockIdx.y * 32;
    int tx = threadIdx.x, ty = threadIdx.y;
    const float* Wl = W + (size_t)l * K * N;
    #pragma unroll
    for (int i = 0; i < 4; i++)
        tile[ty + i * 8][tx] = Wl[(size_t)(k0 + ty + i * 8) * N + n0 + tx];
    __syncthreads();
    half* ol = out + (size_t)l * N * K;
    #pragma unroll
    for (int i = 0; i < 4; i++)
        ol[(size_t)(n0 + ty + i * 8) * K + k0 + tx] = __float2half(tile[tx][ty + i * 8]);
}

// Wq/Wk/Wv [L][H][D][HS] -> packed transposed [L][3D(n)][D(k)] fp16.
// grid: (D/32, HS/32, L*3*H), block (32, 8).
__global__ void pack_qkv_kernel(const float* __restrict__ Wq,
                                const float* __restrict__ Wk,
                                const float* __restrict__ Wv,
                                half* __restrict__ out) {
    __shared__ float tile[32][33];
    int bz  = blockIdx.z;               // l*24 + sel*8 + h
    int h   = bz & 7;
    int sel = (bz >> 3) % 3;
    int l   = bz / 24;
    const float* W = (sel == 0) ? Wq : (sel == 1) ? Wk : Wv;
    const float* Wb = W + (((size_t)l * H_ + h) * D_) * HS_;
    int k0 = blockIdx.x * 32, hs0 = blockIdx.y * 32;
    int tx = threadIdx.x, ty = threadIdx.y;
    #pragma unroll
    for (int i = 0; i < 4; i++)
        tile[ty + i * 8][tx] = Wb[(size_t)(k0 + ty + i * 8) * HS_ + hs0 + tx];
    __syncthreads();
    #pragma unroll
    for (int i = 0; i < 4; i++) {
        int n = sel * 512 + h * 64 + hs0 + ty + i * 8;
        out[((size_t)l * 1536 + n) * D_ + k0 + tx] = __float2half(tile[tx][ty + i * 8]);
    }
}

__global__ void embed_kernel(const int* __restrict__ idx,
                             const float* __restrict__ tok,
                             const float* __restrict__ pos,
                             float* __restrict__ x) {
    int i = blockIdx.x * blockDim.x + threadIdx.x;
    if (i >= BT_ * D_) return;
    int d  = i & (D_ - 1);
    int bt = i >> 9;
    int t  = bt & (T_ - 1);
    x[i] = tok[(size_t)idx[bt] * D_ + d] + pos[t * D_ + d];
}

// warp-per-row LN: 8 rows per 256-thread block, 16 elems/lane, shfl-only.
__global__ __launch_bounds__(256) void ln_kernel(const float* __restrict__ x,
                                                 const float* __restrict__ s,
                                                 const float* __restrict__ b,
                                                 half* __restrict__ out) {
    int warp = threadIdx.x >> 5, lane = threadIdx.x & 31;
    size_t row = (size_t)blockIdx.x * 8 + warp;
    const float4* xr = (const float4*)(x + row * D_);

    float4 v[4];
    #pragma unroll
    for (int i = 0; i < 4; i++) v[i] = xr[lane * 4 + i];

    float sum = 0.f;
    #pragma unroll
    for (int i = 0; i < 4; i++) sum += v[i].x + v[i].y + v[i].z + v[i].w;
    #pragma unroll
    for (int o = 16; o; o >>= 1) sum += __shfl_xor_sync(0xffffffffu, sum, o);
    float mean = sum * (1.0f / D_);

    float vs = 0.f;
    #pragma unroll
    for (int i = 0; i < 4; i++) {
        float dx = v[i].x - mean, dy = v[i].y - mean;
        float dz = v[i].z - mean, dw = v[i].w - mean;
        vs += dx * dx + dy * dy + dz * dz + dw * dw;
    }
    #pragma unroll
    for (int o = 16; o; o >>= 1) vs += __shfl_xor_sync(0xffffffffu, vs, o);
    float inv = rsqrtf(vs * (1.0f / D_) + 1e-5f);

    const float4* sp = (const float4*)s;
    const float4* bp = (const float4*)b;
    half2 h2[8];
    #pragma unroll
    for (int i = 0; i < 4; i++) {
        float4 sv = sp[lane * 4 + i];
        float4 bv = bp[lane * 4 + i];
        float y0 = (v[i].x - mean) * inv * sv.x + bv.x;
        float y1 = (v[i].y - mean) * inv * sv.y + bv.y;
        float y2 = (v[i].z - mean) * inv * sv.z + bv.z;
        float y3 = (v[i].w - mean) * inv * sv.w + bv.w;
        h2[2 * i + 0] = __floats2half2_rn(y0, y1);
        h2[2 * i + 1] = __floats2half2_rn(y2, y3);
    }
    uint4* orow = (uint4*)(out + row * D_ + lane * 16);
    orow[0] = *(uint4*)&h2[0];
    orow[1] = *(uint4*)&h2[4];
}

// ------------------------- FP16 tensor-core GEMM (ldmatrix) ----------------
// C[M,N] = A[M,K] * B^T[N,K]   (A [m][k] fp16, B [n][k] fp16)
// mode: 0 = fp16 store (QKV)
//       1 = +bias, fp32 store (logits)
//       2 = +bias, relu, fp16 store (FF1)
//       3 = +bias, +residual, fp32 store (proj, FF2)
#define BK2 32
#define GROWB 80            // row stride bytes
#define GBUFB (128 * 80)    // buffer size bytes (per array)

__global__ __launch_bounds__(256, 2) void tgemm_kernel(
    const half* __restrict__ A, const half* __restrict__ Bm,
    const float* __restrict__ bias, const float* __restrict__ res,
    float* __restrict__ Cf, half* __restrict__ Ch,
    int M, int N, int K, int mode)
{
    __shared__ __align__(16) half As[2][128][40];
    __shared__ __align__(16) half Bs[2][128][40];

    int tid  = threadIdx.x;
    int wid  = tid >> 5;
    int lane = tid & 31;
    int grp  = lane >> 2;
    int tig  = lane & 3;
    int warp_m = (wid & 1) * 64;
    int warp_n = (wid >> 1) * 32;

    int lrow = tid >> 2;
    int lc   = tid & 3;

    const half* Ap  = A + (size_t)(blockIdx.y * 128 + lrow) * K + lc * 8;
    const half* Ap2 = Ap + (size_t)64 * K;
    int gn  = blockIdx.x * 128 + lrow;
    int gn2 = gn + 64;
    bool bp  = gn  < N;
    bool bp2 = gn2 < N;
    const half* Bp  = Bm + (size_t)(bp  ? gn  : 0) * K + lc * 8;
    const half* Bp2 = Bm + (size_t)(bp2 ? gn2 : 0) * K + lc * 8;

    uint32_t aD[2][2], bD[2][2];
    #pragma unroll
    for (int bf = 0; bf < 2; bf++) {
        aD[bf][0] = (uint32_t)__cvta_generic_to_shared(&As[bf][lrow][lc * 8]);
        aD[bf][1] = (uint32_t)__cvta_generic_to_shared(&As[bf][lrow + 64][lc * 8]);
        bD[bf][0] = (uint32_t)__cvta_generic_to_shared(&Bs[bf][lrow][lc * 8]);
        bD[bf][1] = (uint32_t)__cvta_generic_to_shared(&Bs[bf][lrow + 64][lc * 8]);
    }

    uint32_t aLd = (uint32_t)__cvta_generic_to_shared(
        &As[0][warp_m + (lane & 7) + ((lane >> 3) & 1) * 8][(lane >> 4) * 8]);
    uint32_t bLd = (uint32_t)__cvta_generic_to_shared(
        &Bs[0][warp_n + (lane & 7) + (lane >> 4) * 8][((lane >> 3) & 1) * 8]);

    float acc[4][4][4];
    #pragma unroll
    for (int i = 0; i < 4; i++)
        #pragma unroll
        for (int j = 0; j < 4; j++)
            #pragma unroll
            for (int r = 0; r < 4; r++) acc[i][j][r] = 0.f;

    cp16(aD[0][0], Ap, true);
    cp16(aD[0][1], Ap2, true);
    cp16(bD[0][0], Bp, bp);
    cp16(bD[0][1], Bp2, bp2);
    cp_commit();
    cp_wait0();
    __syncthreads();

    int nstage = K / BK2;
    int cur = 0;
    for (int s = 0; s < nstage; s++) {
        if (s + 1 < nstage) {
            int k0 = (s + 1) * BK2;
            int nxt = cur ^ 1;
            cp16(aD[nxt][0], Ap + k0, true);
            cp16(aD[nxt][1], Ap2 + k0, true);
            cp16(bD[nxt][0], Bp + k0, bp);
            cp16(bD[nxt][1], Bp2 + k0, bp2);
            cp_commit();
        }

        uint32_t bo = cur * GBUFB;
        #pragma unroll
        for (int ks = 0; ks < 2; ks++) {
            uint32_t af[4][4];
            #pragma unroll
            for (int i = 0; i < 4; i++)
                ldsm_x4(af[i], aLd + bo + i * (16 * GROWB) + ks * 32);
            uint32_t bq[2][4];
            #pragma unroll
            for (int jb = 0; jb < 2; jb++)
                ldsm_x4(bq[jb], bLd + bo + jb * (16 * GROWB) + ks * 32);
            #pragma unroll
            for (int i = 0; i < 4; i++)
                #pragma unroll
                for (int j = 0; j < 4; j++)
                    mma_f16(acc[i][j], af[i], &bq[j >> 1][2 * (j & 1)]);
        }

        if (s + 1 < nstage) {
            cp_wait0();
            __syncthreads();
            cur ^= 1;
        }
    }

    #pragma unroll
    for (int i = 0; i < 4; i++) {
        int row0 = blockIdx.y * 128 + warp_m + i * 16 + grp;
        #pragma unroll
        for (int j = 0; j < 4; j++) {
            int col = blockIdx.x * 128 + warp_n + j * 8 + 2 * tig;
            if (col < N) {
                #pragma unroll
                for (int hf = 0; hf < 2; hf++) {
                    int r = row0 + hf * 8;
                    size_t rb = (size_t)r * N;
                    float v0 = acc[i][j][hf * 2 + 0];
                    float v1 = acc[i][j][hf * 2 + 1];
                    if (mode >= 1) { v0 += bias[col]; v1 += bias[col + 1]; }
                    if (mode == 2) { v0 = fmaxf(v0, 0.f); v1 = fmaxf(v1, 0.f); }
                    if (mode == 0 || mode == 2) {
                        *(half2*)(Ch + rb + col) = __floats2half2_rn(v0, v1);
                    } else {
                        if (mode == 3) { v0 += res[rb + col]; v1 += res[rb + col + 1]; }
                        *(float2*)(Cf + rb + col) = make_float2(v0, v1);
                    }
                }
            }
        }
    }
}

// ------------------------- fp16 tensor-core flash attention ----------------
#define KH_ 72
#define KROWB 144

__global__ __launch_bounds__(256, 2) void attn_kernel(const half* __restrict__ QKV,
                                                      half* __restrict__ O) {
    __shared__ __align__(16) half Ks[64][KH_];
    __shared__ __align__(16) half Vs[64][KH_];
    __shared__ __align__(16) half Ps[128][KH_];

    int b = blockIdx.y >> 3, h = blockIdx.y & 7;
    int qb = blockIdx.x * 128;
    int tid = threadIdx.x, wid = tid >> 5, lane = tid & 31;
    int grp = lane >> 2, tig = lane & 3;
    const float scale = 0.04419417382415922f;   // 1/sqrt(512)

    int lr0 = wid * 16 + grp;
    int lr1 = lr0 + 8;
    int gr0 = qb + lr0, gr1 = qb + lr1;

    const half* q0p = QKV + ((size_t)(b * T_) + gr0) * 1536 + h * 64;
    const half* q1p = QKV + ((size_t)(b * T_) + gr1) * 1536 + h * 64;
    uint32_t qa[4][4];
    #pragma unroll
    for (int k = 0; k < 4; k++) {
        int dd = 16 * k + 2 * tig;
        #pragma unroll
        for (int r = 0; r < 4; r++) {
            const half* qp = (r & 1) ? q1p : q0p;
            int d2 = dd + (r >> 1) * 8;
            float2 f = __half22float2(*(const half2*)(qp + d2));
            half2 hv = __floats2half2_rn(f.x * scale, f.y * scale);
            qa[k][r] = *(uint32_t*)&hv;
        }
    }

    uint32_t kLd = (uint32_t)__cvta_generic_to_shared(
        &Ks[(lane & 7) + (lane >> 4) * 8][((lane >> 3) & 1) * 8]);
    uint32_t vLd = (uint32_t)__cvta_generic_to_shared(
        &Vs[(lane & 7) + ((lane >> 3) & 1) * 8][(lane >> 4) * 8]);
    uint32_t pLd = (uint32_t)__cvta_generic_to_shared(
        &Ps[wid * 16 + (lane & 7) + ((lane >> 3) & 1) * 8][(lane >> 4) * 8]);

    float o[8][4];
    #pragma unroll
    for (int j = 0; j < 8; j++) { o[j][0] = o[j][1] = o[j][2] = o[j][3] = 0.f; }
    float m0 = -1e30f, m1 = -1e30f, l0 = 0.f, l1 = 0.f;

    int key4 = tid >> 2, c4 = tid & 3;
    const half* kvb = QKV + (size_t)(b * T_) * 1536 + h * 64 + D_;

    int ntiles = (qb >> 6) + 2;
    for (int t = 0; t < ntiles; t++) {
        int k0 = t * 64;
        __syncthreads();
        {
            const half* kp = kvb + (size_t)(k0 + key4) * 1536;
            #pragma unroll
            for (int tt = 0; tt < 2; tt++) {
                int d = 8 * c4 + 32 * tt;
                *(uint4*)&Ks[key4][d] = *(const uint4*)(kp + d);
                *(uint4*)&Vs[key4][d] = *(const uint4*)(kp + 512 + d);
            }
        }
        __syncthreads();

        float sc[8][4];
        #pragma unroll
        for (int j = 0; j < 8; j++) { sc[j][0] = sc[j][1] = sc[j][2] = sc[j][3] = 0.f; }
        #pragma unroll
        for (int kd = 0; kd < 4; kd++) {
            uint32_t kq[4][4];
            #pragma unroll
            for (int jp = 0; jp < 4; jp++)
                ldsm_x4(kq[jp], kLd + jp * (16 * KROWB) + kd * 32);
            #pragma unroll
            for (int j = 0; j < 8; j++)
                mma_f16(sc[j], qa[kd], &kq[j >> 1][2 * (j & 1)]);
        }

        if (k0 + 63 > qb + wid * 16) {
            #pragma unroll
            for (int j = 0; j < 8; j++) {
                int key = k0 + 8 * j + 2 * tig;
                if (key     > gr0) sc[j][0] = -1e30f;
                if (key + 1 > gr0) sc[j][1] = -1e30f;
                if (key     > gr1) sc[j][2] = -1e30f;
                if (key + 1 > gr1) sc[j][3] = -1e30f;
            }
        }

        float mx0 = -1e30f, mx1 = -1e30f;
        #pragma unroll
        for (int j = 0; j < 8; j++) {
            mx0 = fmaxf(mx0, fmaxf(sc[j][0], sc[j][1]));
            mx1 = fmaxf(mx1, fmaxf(sc[j][2], sc[j][3]));
        }
        mx0 = fmaxf(mx0, __shfl_xor_sync(0xffffffffu, mx0, 1));
        mx0 = fmaxf(mx0, __shfl_xor_sync(0xffffffffu, mx0, 2));
        mx1 = fmaxf(mx1, __shfl_xor_sync(0xffffffffu, mx1, 1));
        mx1 = fmaxf(mx1, __shfl_xor_sync(0xffffffffu, mx1, 2));
        float mn0 = fmaxf(m0, mx0), mn1 = fmaxf(m1, mx1);
        float c0 = __expf(m0 - mn0), c1 = __expf(m1 - mn1);
        m0 = mn0; m1 = mn1;

        float s0 = 0.f, s1 = 0.f;
        #pragma unroll
        for (int j = 0; j < 8; j++) {
            float p0 = __expf(sc[j][0] - m0);
            float p1 = __expf(sc[j][1] - m0);
            float p2 = __expf(sc[j][2] - m1);
            float p3 = __expf(sc[j][3] - m1);
            s0 += p0 + p1; s1 += p2 + p3;
            *(half2*)&Ps[lr0][8 * j + 2 * tig] = __floats2half2_rn(p0, p1);
            *(half2*)&Ps[lr1][8 * j + 2 * tig] = __floats2half2_rn(p2, p3);
        }
        s0 += __shfl_xor_sync(0xffffffffu, s0, 1);
        s0 += __shfl_xor_sync(0xffffffffu, s0, 2);
        s1 += __shfl_xor_sync(0xffffffffu, s1, 1);
        s1 += __shfl_xor_sync(0xffffffffu, s1, 2);
        l0 = l0 * c0 + s0;
        l1 = l1 * c1 + s1;
        #pragma unroll
        for (int j = 0; j < 8; j++) {
            o[j][0] *= c0; o[j][1] *= c0; o[j][2] *= c1; o[j][3] *= c1;
        }
        __syncwarp();

        #pragma unroll
        for (int kd = 0; kd < 4; kd++) {
            uint32_t pa[4];
            ldsm_x4(pa, pLd + kd * 32);
            uint32_t vq[4][4];
            #pragma unroll
            for (int jp = 0; jp < 4; jp++)
                ldsm_x4_t(vq[jp], vLd + kd * (16 * KROWB) + jp * 32);
            #pragma unroll
            for (int j = 0; j < 8; j++)
                mma_f16(o[j], pa, &vq[j >> 1][2 * (j & 1)]);
        }
    }

    float i0 = 1.f / l0, i1 = 1.f / l1;
    size_t ob0 = ((size_t)(b * T_) + gr0) * D_ + h * 64;
    size_t ob1 = ((size_t)(b * T_) + gr1) * D_ + h * 64;
    #pragma unroll
    for (int j = 0; j < 8; j++) {
        int c = 8 * j + 2 * tig;
        *(half2*)(O + ob0 + c) = __floats2half2_rn(o[j][0] * i0, o[j][1] * i0);
        *(half2*)(O + ob1 + c) = __floats2half2_rn(o[j][2] * i1, o[j][3] * i1);
    }
}

// ------------------------- loss --------------------------------------------
__global__ __launch_bounds__(256) void loss_kernel(const float* __restrict__ logits,
                                                   const int* __restrict__ targets,
                                                   double* __restrict__ acc) {
    int warp = (blockIdx.x * blockDim.x + threadIdx.x) >> 5;
    int lane = threadIdx.x & 31;
    const float* lr = logits + (size_t)warp * V_;
    float v0 = lr[lane], v1 = lr[lane + 32], v2 = lr[lane + 64];
    float m = fmaxf(v0, fmaxf(v1, v2));
    #pragma unroll
    for (int o = 16; o; o >>= 1) m = fmaxf(m, __shfl_xor_sync(0xffffffffu, m, o));
    float se = expf(v0 - m) + expf(v1 - m) + expf(v2 - m);
    #pragma unroll
    for (int o = 16; o; o >>= 1) se += __shfl_xor_sync(0xffffffffu, se, o);

    __shared__ float part[8];
    if (lane == 0) part[threadIdx.x >> 5] = lr[targets[warp]] - m - logf(se);
    __syncthreads();
    if (threadIdx.x == 0) {
        float s = 0.f;
        #pragma unroll
        for (int i = 0; i < 8; i++) s += part[i];
        atomicAdd(acc, (double)s);
    }
}

__global__ void finalize_loss_kernel(float* out, const double* acc) {
    out[(size_t)BT_ * V_] = (float)(-(*acc) / (double)BT_);
}

// ------------------------- launcher ----------------------------------------
extern "C" void kernel_launch(void* const* d_in, const int* in_sizes, int n_in,
                              void* d_out, int out_size) {
    const int*   idx     = (const int*)  d_in[0];
    const int*   targets = (const int*)  d_in[1];
    const float* tok     = (const float*)d_in[2];
    const float* pos     = (const float*)d_in[3];
    const float* Wq      = (const float*)d_in[4];
    const float* Wk      = (const float*)d_in[5];
    const float* Wv      = (const float*)d_in[6];
    const float* Wproj   = (const float*)d_in[7];
    const float* bproj   = (const float*)d_in[8];
    const float* W1      = (const float*)d_in[9];
    const float* b1      = (const float*)d_in[10];
    const float* W2      = (const float*)d_in[11];
    const float* b2      = (const float*)d_in[12];
    const float* ln1_s   = (const float*)d_in[13];
    const float* ln1_b   = (const float*)d_in[14];
    const float* ln2_s   = (const float*)d_in[15];
    const float* ln2_b   = (const float*)d_in[16];
    const float* lnf_s   = (const float*)d_in[17];
    const float* lnf_b   = (const float*)d_in[18];
    const float* Wout    = (const float*)d_in[19];
    const float* bout    = (const float*)d_in[20];
    float* out = (float*)d_out;

    float* x;
    half *h, *qkv, *o, *ff, *wqkv, *wproj, *w1, *w2, *wout;
    double* lossAcc;
    cudaGetSymbolAddress((void**)&x,    g_x);
    cudaGetSymbolAddress((void**)&qkv,  g_qkv);
    cudaGetSymbolAddress((void**)&h,    g_h);
    cudaGetSymbolAddress((void**)&o,    g_o);
    cudaGetSymbolAddress((void**)&ff,   g_ff);
    cudaGetSymbolAddress((void**)&wqkv, g_wqkv);
    cudaGetSymbolAddress((void**)&wproj, g_wproj);
    cudaGetSymbolAddress((void**)&w1,   g_w1);
    cudaGetSymbolAddress((void**)&w2,   g_w2);
    cudaGetSymbolAddress((void**)&wout, g_wout);
    cudaGetSymbolAddress((void**)&lossAcc, g_loss);

    // weight packing (coalesced transposes, fp16)
    {
        dim3 blk(32, 8);
        pack_qkv_kernel<<<dim3(D_ / 32, HS_ / 32, L_ * 3 * H_), blk>>>(Wq, Wk, Wv, wqkv);
        pack_wt_kernel<<<dim3(D_ / 32, D_ / 32, L_), blk>>>(Wproj, wproj, D_, D_);
        pack_wt_kernel<<<dim3(FF_ / 32, D_ / 32, L_), blk>>>(W1, w1, D_, FF_);
        pack_wt_kernel<<<dim3(D_ / 32, FF_ / 32, L_), blk>>>(W2, w2, FF_, D_);
        pack_wt_kernel<<<dim3(V_ / 32, D_ / 32, 1), blk>>>(Wout, wout, D_, V_);
    }
    {
        int total = BT_ * D_;
        embed_kernel<<<(total + 255) / 256, 256>>>(idx, tok, pos, x);
    }

    const int MT = BT_ / 128;  // 128 M-tiles
    const int LNG = BT_ / 8;   // LN grid (8 rows/block)
    for (int l = 0; l < L_; l++) {
        ln_kernel<<<LNG, 256>>>(x, ln1_s + l * D_, ln1_b + l * D_, h);
        tgemm_kernel<<<dim3(12, MT), 256>>>(
            h, wqkv + (size_t)l * 3 * D_ * D_,
            nullptr, nullptr, nullptr, qkv, BT_, 3 * D_, D_, 0);
        attn_kernel<<<dim3(T_ / 128, B_ * H_), 256>>>(qkv, o);
        tgemm_kernel<<<dim3(4, MT), 256>>>(
            o, wproj + (size_t)l * D_ * D_,
            bproj + l * D_, x, x, nullptr, BT_, D_, D_, 3);
        ln_kernel<<<LNG, 256>>>(x, ln2_s + l * D_, ln2_b + l * D_, h);
        tgemm_kernel<<<dim3(16, MT), 256>>>(
            h, w1 + (size_t)l * FF_ * D_,
            b1 + l * FF_, nullptr, nullptr, ff, BT_, FF_, D_, 2);
        tgemm_kernel<<<dim3(4, MT), 256>>>(
            ff, w2 + (size_t)l * D_ * FF_,
            b2 + l * D_, x, x, nullptr, BT_, D_, FF_, 3);
    }

    ln_kernel<<<LNG, 256>>>(x, lnf_s, lnf_b, h);
    tgemm_kernel<<<dim3(1, MT), 256>>>(
        h, wout, bout, nullptr, out, nullptr, BT_, V_, D_, 1);

    if (out_size > BT_ * V_) {
        zero_loss_kernel<<<1, 1>>>(lossAcc);
        loss_kernel<<<BT_ / 8, 256>>>(out, targets, lossAcc);
        finalize_loss_kernel<<<1, 1>>>(out, lossAcc);
    }
}

// round 12
// speedup vs baseline: 4.1945x; 1.0109x over previous
#include <cuda_runtime.h>
#include <cuda_fp16.h>
#include <math.h>
#include <stdint.h>

// ---------------------------------------------------------------------------
// MiniTransformer forward: B=16, T=1024, D=512, H=8, HS=64, L=6, FF=2048, V=96
// Output: logits [16384, 96] (fp32) followed by scalar loss.
// GEMMs + attention: fp16 m16n8k16 mma, ldmatrix fragments, deep cp.async pipes.
// ---------------------------------------------------------------------------

#define B_   16
#define T_   1024
#define D_   512
#define H_   8
#define HS_  64
#define L_   6
#define FF_  2048
#define V_   96
#define BT_  (B_ * T_)

// ------------------------- device scratch (no mallocs) ---------------------
__device__ float g_x   [BT_ * D_];          // residual stream (fp32)
__device__ half  g_h   [BT_ * D_];          // LN output (fp16)
__device__ half  g_qkv [BT_ * 3 * D_];      // q|k|v per token (fp16)
__device__ half  g_o   [BT_ * D_];          // attention output (fp16)
__device__ half  g_ff  [BT_ * FF_];         // FFN hidden (fp16)
// weights transposed to [n][k], fp16
__device__ half  g_wqkv [L_ * 3 * D_ * D_];
__device__ half  g_wproj[L_ * D_ * D_];
__device__ half  g_w1   [L_ * FF_ * D_];
__device__ half  g_w2   [L_ * D_ * FF_];
__device__ half  g_wout [V_ * D_];
__device__ double g_loss;

// ------------------------- helpers -----------------------------------------
__device__ __forceinline__ void cp16(uint32_t dst, const void* src, bool pred) {
    int sz = pred ? 16 : 0;
    asm volatile("cp.async.ca.shared.global [%0], [%1], 16, %2;\n"
                 :: "r"(dst), "l"(src), "r"(sz));
}
__device__ __forceinline__ void cp_commit() { asm volatile("cp.async.commit_group;\n"); }
__device__ __forceinline__ void cp_wait0()  { asm volatile("cp.async.wait_group 0;\n"); }
__device__ __forceinline__ void cp_wait1()  { asm volatile("cp.async.wait_group 1;\n"); }

__device__ __forceinline__ void mma_f16(float* d, const uint32_t* a, const uint32_t* b) {
    asm volatile(
        "mma.sync.aligned.m16n8k16.row.col.f32.f16.f16.f32 "
        "{%0,%1,%2,%3}, {%4,%5,%6,%7}, {%8,%9}, {%0,%1,%2,%3};"
        : "+f"(d[0]), "+f"(d[1]), "+f"(d[2]), "+f"(d[3])
        : "r"(a[0]), "r"(a[1]), "r"(a[2]), "r"(a[3]), "r"(b[0]), "r"(b[1]));
}
__device__ __forceinline__ void ldsm_x4(uint32_t* r, uint32_t addr) {
    asm volatile("ldmatrix.sync.aligned.m8n8.x4.shared.b16 {%0,%1,%2,%3}, [%4];"
                 : "=r"(r[0]), "=r"(r[1]), "=r"(r[2]), "=r"(r[3]) : "r"(addr));
}
__device__ __forceinline__ void ldsm_x4_t(uint32_t* r, uint32_t addr) {
    asm volatile("ldmatrix.sync.aligned.m8n8.x4.trans.shared.b16 {%0,%1,%2,%3}, [%4];"
                 : "=r"(r[0]), "=r"(r[1]), "=r"(r[2]), "=r"(r[3]) : "r"(addr));
}

// ------------------------- small kernels -----------------------------------
__global__ void zero_loss_kernel(double* a) { *a = 0.0; }

// W [Lc][K][N] fp32 -> out [Lc][N][K] fp16, coalesced via 32x32 smem tiles.
__global__ void pack_wt_kernel(const float* __restrict__ W,
                               half* __restrict__ out, int K, int N) {
    __shared__ float tile[32][33];
    int l  = blockIdx.z;
    int n0 = blockIdx.x * 32, k0 = blockIdx.y * 32;
    int tx = threadIdx.x, ty = threadIdx.y;
    const float* Wl = W + (size_t)l * K * N;
    #pragma unroll
    for (int i = 0; i < 4; i++)
        tile[ty + i * 8][tx] = Wl[(size_t)(k0 + ty + i * 8) * N + n0 + tx];
    __syncthreads();
    half* ol = out + (size_t)l * N * K;
    #pragma unroll
    for (int i = 0; i < 4; i++)
        ol[(size_t)(n0 + ty + i * 8) * K + k0 + tx] = __float2half(tile[tx][ty + i * 8]);
}

// Wq/Wk/Wv [L][H][D][HS] -> packed transposed [L][3D(n)][D(k)] fp16.
__global__ void pack_qkv_kernel(const float* __restrict__ Wq,
                                const float* __restrict__ Wk,
                                const float* __restrict__ Wv,
                                half* __restrict__ out) {
    __shared__ float tile[32][33];
    int bz  = blockIdx.z;               // l*24 + sel*8 + h
    int h   = bz & 7;
    int sel = (bz >> 3) % 3;
    int l   = bz / 24;
    const float* W = (sel == 0) ? Wq : (sel == 1) ? Wk : Wv;
    const float* Wb = W + (((size_t)l * H_ + h) * D_) * HS_;
    int k0 = blockIdx.x * 32, hs0 = blockIdx.y * 32;
    int tx = threadIdx.x, ty = threadIdx.y;
    #pragma unroll
    for (int i = 0; i < 4; i++)
        tile[ty + i * 8][tx] = Wb[(size_t)(k0 + ty + i * 8) * HS_ + hs0 + tx];
    __syncthreads();
    #pragma unroll
    for (int i = 0; i < 4; i++) {
        int n = sel * 512 + h * 64 + hs0 + ty + i * 8;
        out[((size_t)l * 1536 + n) * D_ + k0 + tx] = __float2half(tile[tx][ty + i * 8]);
    }
}

__global__ void embed_kernel(const int* __restrict__ idx,
                             const float* __restrict__ tok,
                             const float* __restrict__ pos,
                             float* __restrict__ x) {
    int i = blockIdx.x * blockDim.x + threadIdx.x;
    if (i >= BT_ * D_) return;
    int d  = i & (D_ - 1);
    int bt = i >> 9;
    int t  = bt & (T_ - 1);
    x[i] = tok[(size_t)idx[bt] * D_ + d] + pos[t * D_ + d];
}

// warp-per-row LN: 8 rows per 256-thread block, 16 elems/lane, shfl-only.
__global__ __launch_bounds__(256) void ln_kernel(const float* __restrict__ x,
                                                 const float* __restrict__ s,
                                                 const float* __restrict__ b,
                                                 half* __restrict__ out) {
    int warp = threadIdx.x >> 5, lane = threadIdx.x & 31;
    size_t row = (size_t)blockIdx.x * 8 + warp;
    const float4* xr = (const float4*)(x + row * D_);

    float4 v[4];
    #pragma unroll
    for (int i = 0; i < 4; i++) v[i] = xr[lane * 4 + i];

    float sum = 0.f;
    #pragma unroll
    for (int i = 0; i < 4; i++) sum += v[i].x + v[i].y + v[i].z + v[i].w;
    #pragma unroll
    for (int o = 16; o; o >>= 1) sum += __shfl_xor_sync(0xffffffffu, sum, o);
    float mean = sum * (1.0f / D_);

    float vs = 0.f;
    #pragma unroll
    for (int i = 0; i < 4; i++) {
        float dx = v[i].x - mean, dy = v[i].y - mean;
        float dz = v[i].z - mean, dw = v[i].w - mean;
        vs += dx * dx + dy * dy + dz * dz + dw * dw;
    }
    #pragma unroll
    for (int o = 16; o; o >>= 1) vs += __shfl_xor_sync(0xffffffffu, vs, o);
    float inv = rsqrtf(vs * (1.0f / D_) + 1e-5f);

    const float4* sp = (const float4*)s;
    const float4* bp = (const float4*)b;
    half2 h2[8];
    #pragma unroll
    for (int i = 0; i < 4; i++) {
        float4 sv = sp[lane * 4 + i];
        float4 bv = bp[lane * 4 + i];
        float y0 = (v[i].x - mean) * inv * sv.x + bv.x;
        float y1 = (v[i].y - mean) * inv * sv.y + bv.y;
        float y2 = (v[i].z - mean) * inv * sv.z + bv.z;
        float y3 = (v[i].w - mean) * inv * sv.w + bv.w;
        h2[2 * i + 0] = __floats2half2_rn(y0, y1);
        h2[2 * i + 1] = __floats2half2_rn(y2, y3);
    }
    uint4* orow = (uint4*)(out + row * D_ + lane * 16);
    orow[0] = *(uint4*)&h2[0];
    orow[1] = *(uint4*)&h2[4];
}

// ------------------------- FP16 tensor-core GEMM (3-stage cp.async) --------
// C[M,N] = A[M,K] * B^T[N,K]   (A [m][k] fp16, B [n][k] fp16)
// mode: 0 = fp16 store (QKV); 1 = +bias fp32 (logits);
//       2 = +bias relu fp16 (FF1); 3 = +bias +residual fp32 (proj, FF2)
// 128x128 tile, BK=32, 256 threads = 8 warps, warp tile 64(m) x 32(n).
// smem rows 40 halves (80B); 3 staging buffers, dynamic smem.
#define BK2 32
#define GROWB 80                 // row stride bytes
#define GBUFB (128 * 80)         // one buffer (one array) bytes = 10240
#define GEMM_SMEM (6 * GBUFB)    // 3 stages x (A + B) = 61440

__global__ __launch_bounds__(256, 2) void tgemm_kernel(
    const half* __restrict__ A, const half* __restrict__ Bm,
    const float* __restrict__ bias, const float* __restrict__ res,
    float* __restrict__ Cf, half* __restrict__ Ch,
    int M, int N, int K, int mode)
{
    extern __shared__ __align__(16) half smg[];
    uint32_t smBase = (uint32_t)__cvta_generic_to_shared(smg);
    const uint32_t BOFF = 3 * GBUFB;    // B arrays after 3 A buffers

    int tid  = threadIdx.x;
    int wid  = tid >> 5;
    int lane = tid & 31;
    int grp  = lane >> 2;
    int tig  = lane & 3;
    int warp_m = (wid & 1) * 64;
    int warp_n = (wid >> 1) * 32;

    int lrow = tid >> 2;
    int lc   = tid & 3;

    const half* Ap  = A + (size_t)(blockIdx.y * 128 + lrow) * K + lc * 8;
    const half* Ap2 = Ap + (size_t)64 * K;
    int gn  = blockIdx.x * 128 + lrow;
    int gn2 = gn + 64;
    bool bp  = gn  < N;
    bool bp2 = gn2 < N;
    const half* Bp  = Bm + (size_t)(bp  ? gn  : 0) * K + lc * 8;
    const half* Bp2 = Bm + (size_t)(bp2 ? gn2 : 0) * K + lc * 8;

    uint32_t aDst  = smBase + lrow * GROWB + lc * 16;
    uint32_t aDst2 = aDst + 64 * GROWB;
    uint32_t bDst  = smBase + BOFF + lrow * GROWB + lc * 16;
    uint32_t bDst2 = bDst + 64 * GROWB;

    uint32_t aLd = smBase + (warp_m + (lane & 7) + ((lane >> 3) & 1) * 8) * GROWB
                 + (lane >> 4) * 16;
    uint32_t bLd = smBase + BOFF + (warp_n + (lane & 7) + (lane >> 4) * 8) * GROWB
                 + ((lane >> 3) & 1) * 16;

    float acc[4][4][4];
    #pragma unroll
    for (int i = 0; i < 4; i++)
        #pragma unroll
        for (int j = 0; j < 4; j++)
            #pragma unroll
            for (int r = 0; r < 4; r++) acc[i][j][r] = 0.f;

    int nstage = K / BK2;

    // prologue: issue stages 0, 1
    {
        cp16(aDst, Ap, true);  cp16(aDst2, Ap2, true);
        cp16(bDst, Bp, bp);    cp16(bDst2, Bp2, bp2);
        cp_commit();
        if (nstage > 1) {
            cp16(aDst + GBUFB, Ap + BK2, true);  cp16(aDst2 + GBUFB, Ap2 + BK2, true);
            cp16(bDst + GBUFB, Bp + BK2, bp);    cp16(bDst2 + GBUFB, Bp2 + BK2, bp2);
            cp_commit();
        }
    }

    int cur = 0;    // buffer of stage s
    for (int s = 0; s < nstage; s++) {
        if (s + 1 < nstage) cp_wait1(); else cp_wait0();
        __syncthreads();

        if (s + 2 < nstage) {
            int ib = cur + 2; if (ib >= 3) ib -= 3;
            uint32_t io = ib * GBUFB;
            int k0 = (s + 2) * BK2;
            cp16(aDst + io, Ap + k0, true);  cp16(aDst2 + io, Ap2 + k0, true);
            cp16(bDst + io, Bp + k0, bp);    cp16(bDst2 + io, Bp2 + k0, bp2);
            cp_commit();
        }

        uint32_t bo = cur * GBUFB;
        #pragma unroll
        for (int ks = 0; ks < 2; ks++) {
            uint32_t af[4][4];
            #pragma unroll
            for (int i = 0; i < 4; i++)
                ldsm_x4(af[i], aLd + bo + i * (16 * GROWB) + ks * 32);
            uint32_t bq[2][4];
            #pragma unroll
            for (int jb = 0; jb < 2; jb++)
                ldsm_x4(bq[jb], bLd + bo + jb * (16 * GROWB) + ks * 32);
            #pragma unroll
            for (int i = 0; i < 4; i++)
                #pragma unroll
                for (int j = 0; j < 4; j++)
                    mma_f16(acc[i][j], af[i], &bq[j >> 1][2 * (j & 1)]);
        }

        cur = (cur == 2) ? 0 : cur + 1;
    }

    #pragma unroll
    for (int i = 0; i < 4; i++) {
        int row0 = blockIdx.y * 128 + warp_m + i * 16 + grp;
        #pragma unroll
        for (int j = 0; j < 4; j++) {
            int col = blockIdx.x * 128 + warp_n + j * 8 + 2 * tig;
            if (col < N) {
                #pragma unroll
                for (int hf = 0; hf < 2; hf++) {
                    int r = row0 + hf * 8;
                    size_t rb = (size_t)r * N;
                    float v0 = acc[i][j][hf * 2 + 0];
                    float v1 = acc[i][j][hf * 2 + 1];
                    if (mode >= 1) { v0 += bias[col]; v1 += bias[col + 1]; }
                    if (mode == 2) { v0 = fmaxf(v0, 0.f); v1 = fmaxf(v1, 0.f); }
                    if (mode == 0 || mode == 2) {
                        *(half2*)(Ch + rb + col) = __floats2half2_rn(v0, v1);
                    } else {
                        if (mode == 3) { v0 += res[rb + col]; v1 += res[rb + col + 1]; }
                        *(float2*)(Cf + rb + col) = make_float2(v0, v1);
                    }
                }
            }
        }
    }
}

// ------------------------- fp16 flash attention (cp.async K/V) -------------
// 128 queries/block, 8 warps x 16 query-rows, 64-key tiles double-buffered.
// smem layout (bytes): K buf b at b*9216; V buf b at 18432 + b*9216; P at 36864.
#define KH_ 72
#define KROWB 144
#define KVBUF (64 * KROWB)                 // 9216
#define ATTN_SMEM (4 * KVBUF + 128 * KROWB)  // 55296

__global__ __launch_bounds__(256, 2) void attn_kernel(const half* __restrict__ QKV,
                                                      half* __restrict__ O) {
    extern __shared__ __align__(16) half sma[];
    uint32_t smBase = (uint32_t)__cvta_generic_to_shared(sma);
    half* Ps = sma + (4 * KVBUF) / 2;   // halves offset

    int b = blockIdx.y >> 3, h = blockIdx.y & 7;
    int qb = blockIdx.x * 128;
    int tid = threadIdx.x, wid = tid >> 5, lane = tid & 31;
    int grp = lane >> 2, tig = lane & 3;
    const float scale = 0.04419417382415922f;   // 1/sqrt(512)

    int lr0 = wid * 16 + grp;
    int lr1 = lr0 + 8;
    int gr0 = qb + lr0, gr1 = qb + lr1;

    const half* q0p = QKV + ((size_t)(b * T_) + gr0) * 1536 + h * 64;
    const half* q1p = QKV + ((size_t)(b * T_) + gr1) * 1536 + h * 64;
    uint32_t qa[4][4];
    #pragma unroll
    for (int k = 0; k < 4; k++) {
        int dd = 16 * k + 2 * tig;
        #pragma unroll
        for (int r = 0; r < 4; r++) {
            const half* qp = (r & 1) ? q1p : q0p;
            int d2 = dd + (r >> 1) * 8;
            float2 f = __half22float2(*(const half2*)(qp + d2));
            half2 hv = __floats2half2_rn(f.x * scale, f.y * scale);
            qa[k][r] = *(uint32_t*)&hv;
        }
    }

    // ldmatrix bases (buffer 0)
    uint32_t kLd = smBase + ((lane & 7) + (lane >> 4) * 8) * KROWB
                 + ((lane >> 3) & 1) * 16;
    uint32_t vLd = smBase + 2 * KVBUF + ((lane & 7) + ((lane >> 3) & 1) * 8) * KROWB
                 + (lane >> 4) * 16;
    uint32_t pLd = smBase + 4 * KVBUF
                 + (wid * 16 + (lane & 7) + ((lane >> 3) & 1) * 8) * KROWB
                 + (lane >> 4) * 16;

    // cp.async dst for K/V loader: thread -> key row key4, chunks d, d+32 halves
    int key4 = tid >> 2, c4 = tid & 3;
    int dh = 8 * c4;
    uint32_t kDst = smBase + key4 * KROWB + dh * 2;
    uint32_t vDst = kDst + 2 * KVBUF;
    const half* kvb = QKV + (size_t)(b * T_) * 1536 + h * 64 + D_;
    const half* kRow = kvb + (size_t)key4 * 1536 + dh;

    float o[8][4];
    #pragma unroll
    for (int j = 0; j < 8; j++) { o[j][0] = o[j][1] = o[j][2] = o[j][3] = 0.f; }
    float m0 = -1e30f, m1 = -1e30f, l0 = 0.f, l1 = 0.f;

    int ntiles = (qb >> 6) + 2;

    // prologue: tile 0 into buffer 0
    {
        cp16(kDst,      kRow,        true);
        cp16(kDst + 64, kRow + 32,   true);
        cp16(vDst,      kRow + 512,  true);
        cp16(vDst + 64, kRow + 544,  true);
        cp_commit();
    }

    for (int t = 0; t < ntiles; t++) {
        cp_wait0();
        __syncthreads();

        if (t + 1 < ntiles) {
            uint32_t io = ((t + 1) & 1) * KVBUF;
            const half* kr = kRow + (size_t)(t + 1) * 64 * 1536;
            cp16(kDst + io,      kr,       true);
            cp16(kDst + io + 64, kr + 32,  true);
            cp16(vDst + io,      kr + 512, true);
            cp16(vDst + io + 64, kr + 544, true);
            cp_commit();
        }

        uint32_t bo = (t & 1) * KVBUF;
        int k0 = t * 64;

        float sc[8][4];
        #pragma unroll
        for (int j = 0; j < 8; j++) { sc[j][0] = sc[j][1] = sc[j][2] = sc[j][3] = 0.f; }
        #pragma unroll
        for (int kd = 0; kd < 4; kd++) {
            uint32_t kq[4][4];
            #pragma unroll
            for (int jp = 0; jp < 4; jp++)
                ldsm_x4(kq[jp], kLd + bo + jp * (16 * KROWB) + kd * 32);
            #pragma unroll
            for (int j = 0; j < 8; j++)
                mma_f16(sc[j], qa[kd], &kq[j >> 1][2 * (j & 1)]);
        }

        if (k0 + 63 > qb + wid * 16) {
            #pragma unroll
            for (int j = 0; j < 8; j++) {
                int key = k0 + 8 * j + 2 * tig;
                if (key     > gr0) sc[j][0] = -1e30f;
                if (key + 1 > gr0) sc[j][1] = -1e30f;
                if (key     > gr1) sc[j][2] = -1e30f;
                if (key + 1 > gr1) sc[j][3] = -1e30f;
            }
        }

        float mx0 = -1e30f, mx1 = -1e30f;
        #pragma unroll
        for (int j = 0; j < 8; j++) {
            mx0 = fmaxf(mx0, fmaxf(sc[j][0], sc[j][1]));
            mx1 = fmaxf(mx1, fmaxf(sc[j][2], sc[j][3]));
        }
        mx0 = fmaxf(mx0, __shfl_xor_sync(0xffffffffu, mx0, 1));
        mx0 = fmaxf(mx0, __shfl_xor_sync(0xffffffffu, mx0, 2));
        mx1 = fmaxf(mx1, __shfl_xor_sync(0xffffffffu, mx1, 1));
        mx1 = fmaxf(mx1, __shfl_xor_sync(0xffffffffu, mx1, 2));
        float mn0 = fmaxf(m0, mx0), mn1 = fmaxf(m1, mx1);
        float c0 = __expf(m0 - mn0), c1 = __expf(m1 - mn1);
        m0 = mn0; m1 = mn1;

        float s0 = 0.f, s1 = 0.f;
        #pragma unroll
        for (int j = 0; j < 8; j++) {
            float p0 = __expf(sc[j][0] - m0);
            float p1 = __expf(sc[j][1] - m0);
            float p2 = __expf(sc[j][2] - m1);
            float p3 = __expf(sc[j][3] - m1);
            s0 += p0 + p1; s1 += p2 + p3;
            *(half2*)&Ps[lr0 * KH_ + 8 * j + 2 * tig] = __floats2half2_rn(p0, p1);
            *(half2*)&Ps[lr1 * KH_ + 8 * j + 2 * tig] = __floats2half2_rn(p2, p3);
        }
        s0 += __shfl_xor_sync(0xffffffffu, s0, 1);
        s0 += __shfl_xor_sync(0xffffffffu, s0, 2);
        s1 += __shfl_xor_sync(0xffffffffu, s1, 1);
        s1 += __shfl_xor_sync(0xffffffffu, s1, 2);
        l0 = l0 * c0 + s0;
        l1 = l1 * c1 + s1;
        #pragma unroll
        for (int j = 0; j < 8; j++) {
            o[j][0] *= c0; o[j][1] *= c0; o[j][2] *= c1; o[j][3] *= c1;
        }
        __syncwarp();

        #pragma unroll
        for (int kd = 0; kd < 4; kd++) {
            uint32_t pa[4];
            ldsm_x4(pa, pLd + kd * 32);
            uint32_t vq[4][4];
            #pragma unroll
            for (int jp = 0; jp < 4; jp++)
                ldsm_x4_t(vq[jp], vLd + bo + kd * (16 * KROWB) + jp * 32);
            #pragma unroll
            for (int j = 0; j < 8; j++)
                mma_f16(o[j], pa, &vq[j >> 1][2 * (j & 1)]);
        }
    }

    float i0 = 1.f / l0, i1 = 1.f / l1;
    size_t ob0 = ((size_t)(b * T_) + gr0) * D_ + h * 64;
    size_t ob1 = ((size_t)(b * T_) + gr1) * D_ + h * 64;
    #pragma unroll
    for (int j = 0; j < 8; j++) {
        int c = 8 * j + 2 * tig;
        *(half2*)(O + ob0 + c) = __floats2half2_rn(o[j][0] * i0, o[j][1] * i0);
        *(half2*)(O + ob1 + c) = __floats2half2_rn(o[j][2] * i1, o[j][3] * i1);
    }
}

// ------------------------- loss --------------------------------------------
__global__ __launch_bounds__(256) void loss_kernel(const float* __restrict__ logits,
                                                   const int* __restrict__ targets,
                                                   double* __restrict__ acc) {
    int warp = (blockIdx.x * blockDim.x + threadIdx.x) >> 5;
    int lane = threadIdx.x & 31;
    const float* lr = logits + (size_t)warp * V_;
    float v0 = lr[lane], v1 = lr[lane + 32], v2 = lr[lane + 64];
    float m = fmaxf(v0, fmaxf(v1, v2));
    #pragma unroll
    for (int o = 16; o; o >>= 1) m = fmaxf(m, __shfl_xor_sync(0xffffffffu, m, o));
    float se = expf(v0 - m) + expf(v1 - m) + expf(v2 - m);
    #pragma unroll
    for (int o = 16; o; o >>= 1) se += __shfl_xor_sync(0xffffffffu, se, o);

    __shared__ float part[8];
    if (lane == 0) part[threadIdx.x >> 5] = lr[targets[warp]] - m - logf(se);
    __syncthreads();
    if (threadIdx.x == 0) {
        float s = 0.f;
        #pragma unroll
        for (int i = 0; i < 8; i++) s += part[i];
        atomicAdd(acc, (double)s);
    }
}

__global__ void finalize_loss_kernel(float* out, const double* acc) {
    out[(size_t)BT_ * V_] = (float)(-(*acc) / (double)BT_);
}

// ------------------------- launcher ----------------------------------------
extern "C" void kernel_launch(void* const* d_in, const int* in_sizes, int n_in,
                              void* d_out, int out_size) {
    const int*   idx     = (const int*)  d_in[0];
    const int*   targets = (const int*)  d_in[1];
    const float* tok     = (const float*)d_in[2];
    const float* pos     = (const float*)d_in[3];
    const float* Wq      = (const float*)d_in[4];
    const float* Wk      = (const float*)d_in[5];
    const float* Wv      = (const float*)d_in[6];
    const float* Wproj   = (const float*)d_in[7];
    const float* bproj   = (const float*)d_in[8];
    const float* W1      = (const float*)d_in[9];
    const float* b1      = (const float*)d_in[10];
    const float* W2      = (const float*)d_in[11];
    const float* b2      = (const float*)d_in[12];
    const float* ln1_s   = (const float*)d_in[13];
    const float* ln1_b   = (const float*)d_in[14];
    const float* ln2_s   = (const float*)d_in[15];
    const float* ln2_b   = (const float*)d_in[16];
    const float* lnf_s   = (const float*)d_in[17];
    const float* lnf_b   = (const float*)d_in[18];
    const float* Wout    = (const float*)d_in[19];
    const float* bout    = (const float*)d_in[20];
    float* out = (float*)d_out;

    float* x;
    half *h, *qkv, *o, *ff, *wqkv, *wproj, *w1, *w2, *wout;
    double* lossAcc;
    cudaGetSymbolAddress((void**)&x,    g_x);
    cudaGetSymbolAddress((void**)&qkv,  g_qkv);
    cudaGetSymbolAddress((void**)&h,    g_h);
    cudaGetSymbolAddress((void**)&o,    g_o);
    cudaGetSymbolAddress((void**)&ff,   g_ff);
    cudaGetSymbolAddress((void**)&wqkv, g_wqkv);
    cudaGetSymbolAddress((void**)&wproj, g_wproj);
    cudaGetSymbolAddress((void**)&w1,   g_w1);
    cudaGetSymbolAddress((void**)&w2,   g_w2);
    cudaGetSymbolAddress((void**)&wout, g_wout);
    cudaGetSymbolAddress((void**)&lossAcc, g_loss);

    cudaFuncSetAttribute(tgemm_kernel,
                         cudaFuncAttributeMaxDynamicSharedMemorySize, GEMM_SMEM);
    cudaFuncSetAttribute(attn_kernel,
                         cudaFuncAttributeMaxDynamicSharedMemorySize, ATTN_SMEM);

    // weight packing (coalesced transposes, fp16)
    {
        dim3 blk(32, 8);
        pack_qkv_kernel<<<dim3(D_ / 32, HS_ / 32, L_ * 3 * H_), blk>>>(Wq, Wk, Wv, wqkv);
        pack_wt_kernel<<<dim3(D_ / 32, D_ / 32, L_), blk>>>(Wproj, wproj, D_, D_);
        pack_wt_kernel<<<dim3(FF_ / 32, D_ / 32, L_), blk>>>(W1, w1, D_, FF_);
        pack_wt_kernel<<<dim3(D_ / 32, FF_ / 32, L_), blk>>>(W2, w2, FF_, D_);
        pack_wt_kernel<<<dim3(V_ / 32, D_ / 32, 1), blk>>>(Wout, wout, D_, V_);
    }
    {
        int total = BT_ * D_;
        embed_kernel<<<(total + 255) / 256, 256>>>(idx, tok, pos, x);
    }

    const int MT = BT_ / 128;  // 128 M-tiles
    const int LNG = BT_ / 8;   // LN grid (8 rows/block)
    for (int l = 0; l < L_; l++) {
        ln_kernel<<<LNG, 256>>>(x, ln1_s + l * D_, ln1_b + l * D_, h);
        tgemm_kernel<<<dim3(12, MT), 256, GEMM_SMEM>>>(
            h, wqkv + (size_t)l * 3 * D_ * D_,
            nullptr, nullptr, nullptr, qkv, BT_, 3 * D_, D_, 0);
        attn_kernel<<<dim3(T_ / 128, B_ * H_), 256, ATTN_SMEM>>>(qkv, o);
        tgemm_kernel<<<dim3(4, MT), 256, GEMM_SMEM>>>(
            o, wproj + (size_t)l * D_ * D_,
            bproj + l * D_, x, x, nullptr, BT_, D_, D_, 3);
        ln_kernel<<<LNG, 256>>>(x, ln2_s + l * D_, ln2_b + l * D_, h);
        tgemm_kernel<<<dim3(16, MT), 256, GEMM_SMEM>>>(
            h, w1 + (size_t)l * FF_ * D_,
            b1 + l * FF_, nullptr, nullptr, ff, BT_, FF_, D_, 2);
        tgemm_kernel<<<dim3(4, MT), 256, GEMM_SMEM>>>(
            ff, w2 + (size_t)l * D_ * FF_,
            b2 + l * D_, x, x, nullptr, BT_, D_, FF_, 3);
    }

    ln_kernel<<<LNG, 256>>>(x, lnf_s, lnf_b, h);
    tgemm_kernel<<<dim3(1, MT), 256, GEMM_SMEM>>>(
        h, wout, bout, nullptr, out, nullptr, BT_, V_, D_, 1);

    if (out_size > BT_ * V_) {
        zero_loss_kernel<<<1, 1>>>(lossAcc);
        loss_kernel<<<BT_ / 8, 256>>>(out, targets, lossAcc);
        finalize_loss_kernel<<<1, 1>>>(out, lossAcc);
    }
}

// round 13
// speedup vs baseline: 4.3098x; 1.0275x over previous
#include <cuda_runtime.h>
#include <cuda_fp16.h>
#include <math.h>
#include <stdint.h>

// ---------------------------------------------------------------------------
// MiniTransformer forward: B=16, T=1024, D=512, H=8, HS=64, L=6, FF=2048, V=96
// Output: logits [16384, 96] (fp32) followed by scalar loss.
// GEMMs + attention: fp16 m16n8k16 mma, ldmatrix fragments, cp.async pipes.
// Attention keeps P entirely in registers (QK accum frags == PV A frags).
// ---------------------------------------------------------------------------

#define B_   16
#define T_   1024
#define D_   512
#define H_   8
#define HS_  64
#define L_   6
#define FF_  2048
#define V_   96
#define BT_  (B_ * T_)

// ------------------------- device scratch (no mallocs) ---------------------
__device__ float g_x   [BT_ * D_];          // residual stream (fp32)
__device__ half  g_h   [BT_ * D_];          // LN output (fp16)
__device__ half  g_qkv [BT_ * 3 * D_];      // q|k|v per token (fp16)
__device__ half  g_o   [BT_ * D_];          // attention output (fp16)
__device__ half  g_ff  [BT_ * FF_];         // FFN hidden (fp16)
// weights transposed to [n][k], fp16
__device__ half  g_wqkv [L_ * 3 * D_ * D_];
__device__ half  g_wproj[L_ * D_ * D_];
__device__ half  g_w1   [L_ * FF_ * D_];
__device__ half  g_w2   [L_ * D_ * FF_];
__device__ half  g_wout [V_ * D_];
__device__ double g_loss;

// ------------------------- helpers -----------------------------------------
__device__ __forceinline__ void cp16(uint32_t dst, const void* src, bool pred) {
    int sz = pred ? 16 : 0;
    asm volatile("cp.async.ca.shared.global [%0], [%1], 16, %2;\n"
                 :: "r"(dst), "l"(src), "r"(sz));
}
__device__ __forceinline__ void cp_commit() { asm volatile("cp.async.commit_group;\n"); }
__device__ __forceinline__ void cp_wait0()  { asm volatile("cp.async.wait_group 0;\n"); }
__device__ __forceinline__ void cp_wait1()  { asm volatile("cp.async.wait_group 1;\n"); }

__device__ __forceinline__ void mma_f16(float* d, const uint32_t* a, const uint32_t* b) {
    asm volatile(
        "mma.sync.aligned.m16n8k16.row.col.f32.f16.f16.f32 "
        "{%0,%1,%2,%3}, {%4,%5,%6,%7}, {%8,%9}, {%0,%1,%2,%3};"
        : "+f"(d[0]), "+f"(d[1]), "+f"(d[2]), "+f"(d[3])
        : "r"(a[0]), "r"(a[1]), "r"(a[2]), "r"(a[3]), "r"(b[0]), "r"(b[1]));
}
__device__ __forceinline__ void ldsm_x4(uint32_t* r, uint32_t addr) {
    asm volatile("ldmatrix.sync.aligned.m8n8.x4.shared.b16 {%0,%1,%2,%3}, [%4];"
                 : "=r"(r[0]), "=r"(r[1]), "=r"(r[2]), "=r"(r[3]) : "r"(addr));
}
__device__ __forceinline__ void ldsm_x4_t(uint32_t* r, uint32_t addr) {
    asm volatile("ldmatrix.sync.aligned.m8n8.x4.trans.shared.b16 {%0,%1,%2,%3}, [%4];"
                 : "=r"(r[0]), "=r"(r[1]), "=r"(r[2]), "=r"(r[3]) : "r"(addr));
}

// ------------------------- small kernels -----------------------------------
__global__ void zero_loss_kernel(double* a) { *a = 0.0; }

// W [Lc][K][N] fp32 -> out [Lc][N][K] fp16, coalesced via 32x32 smem tiles.
__global__ void pack_wt_kernel(const float* __restrict__ W,
                               half* __restrict__ out, int K, int N) {
    __shared__ float tile[32][33];
    int l  = blockIdx.z;
    int n0 = blockIdx.x * 32, k0 = blockIdx.y * 32;
    int tx = threadIdx.x, ty = threadIdx.y;
    const float* Wl = W + (size_t)l * K * N;
    #pragma unroll
    for (int i = 0; i < 4; i++)
        tile[ty + i * 8][tx] = Wl[(size_t)(k0 + ty + i * 8) * N + n0 + tx];
    __syncthreads();
    half* ol = out + (size_t)l * N * K;
    #pragma unroll
    for (int i = 0; i < 4; i++)
        ol[(size_t)(n0 + ty + i * 8) * K + k0 + tx] = __float2half(tile[tx][ty + i * 8]);
}

// Wq/Wk/Wv [L][H][D][HS] -> packed transposed [L][3D(n)][D(k)] fp16.
__global__ void pack_qkv_kernel(const float* __restrict__ Wq,
                                const float* __restrict__ Wk,
                                const float* __restrict__ Wv,
                                half* __restrict__ out) {
    __shared__ float tile[32][33];
    int bz  = blockIdx.z;               // l*24 + sel*8 + h
    int h   = bz & 7;
    int sel = (bz >> 3) % 3;
    int l   = bz / 24;
    const float* W = (sel == 0) ? Wq : (sel == 1) ? Wk : Wv;
    const float* Wb = W + (((size_t)l * H_ + h) * D_) * HS_;
    int k0 = blockIdx.x * 32, hs0 = blockIdx.y * 32;
    int tx = threadIdx.x, ty = threadIdx.y;
    #pragma unroll
    for (int i = 0; i < 4; i++)
        tile[ty + i * 8][tx] = Wb[(size_t)(k0 + ty + i * 8) * HS_ + hs0 + tx];
    __syncthreads();
    #pragma unroll
    for (int i = 0; i < 4; i++) {
        int n = sel * 512 + h * 64 + hs0 + ty + i * 8;
        out[((size_t)l * 1536 + n) * D_ + k0 + tx] = __float2half(tile[tx][ty + i * 8]);
    }
}

__global__ void embed_kernel(const int* __restrict__ idx,
                             const float* __restrict__ tok,
                             const float* __restrict__ pos,
                             float* __restrict__ x) {
    int i = blockIdx.x * blockDim.x + threadIdx.x;
    if (i >= BT_ * D_) return;
    int d  = i & (D_ - 1);
    int bt = i >> 9;
    int t  = bt & (T_ - 1);
    x[i] = tok[(size_t)idx[bt] * D_ + d] + pos[t * D_ + d];
}

// warp-per-row LN: 8 rows per 256-thread block, 16 elems/lane, shfl-only.
__global__ __launch_bounds__(256) void ln_kernel(const float* __restrict__ x,
                                                 const float* __restrict__ s,
                                                 const float* __restrict__ b,
                                                 half* __restrict__ out) {
    int warp = threadIdx.x >> 5, lane = threadIdx.x & 31;
    size_t row = (size_t)blockIdx.x * 8 + warp;
    const float4* xr = (const float4*)(x + row * D_);

    float4 v[4];
    #pragma unroll
    for (int i = 0; i < 4; i++) v[i] = xr[lane * 4 + i];

    float sum = 0.f;
    #pragma unroll
    for (int i = 0; i < 4; i++) sum += v[i].x + v[i].y + v[i].z + v[i].w;
    #pragma unroll
    for (int o = 16; o; o >>= 1) sum += __shfl_xor_sync(0xffffffffu, sum, o);
    float mean = sum * (1.0f / D_);

    float vs = 0.f;
    #pragma unroll
    for (int i = 0; i < 4; i++) {
        float dx = v[i].x - mean, dy = v[i].y - mean;
        float dz = v[i].z - mean, dw = v[i].w - mean;
        vs += dx * dx + dy * dy + dz * dz + dw * dw;
    }
    #pragma unroll
    for (int o = 16; o; o >>= 1) vs += __shfl_xor_sync(0xffffffffu, vs, o);
    float inv = rsqrtf(vs * (1.0f / D_) + 1e-5f);

    const float4* sp = (const float4*)s;
    const float4* bp = (const float4*)b;
    half2 h2[8];
    #pragma unroll
    for (int i = 0; i < 4; i++) {
        float4 sv = sp[lane * 4 + i];
        float4 bv = bp[lane * 4 + i];
        float y0 = (v[i].x - mean) * inv * sv.x + bv.x;
        float y1 = (v[i].y - mean) * inv * sv.y + bv.y;
        float y2 = (v[i].z - mean) * inv * sv.z + bv.z;
        float y3 = (v[i].w - mean) * inv * sv.w + bv.w;
        h2[2 * i + 0] = __floats2half2_rn(y0, y1);
        h2[2 * i + 1] = __floats2half2_rn(y2, y3);
    }
    uint4* orow = (uint4*)(out + row * D_ + lane * 16);
    orow[0] = *(uint4*)&h2[0];
    orow[1] = *(uint4*)&h2[4];
}

// ------------------------- FP16 tensor-core GEMM (3-stage cp.async) --------
// C[M,N] = A[M,K] * B^T[N,K]   (A [m][k] fp16, B [n][k] fp16)
// mode: 0 = fp16 store (QKV); 1 = +bias fp32 (logits);
//       2 = +bias relu fp16 (FF1); 3 = +bias +residual fp32 (proj, FF2)
#define BK2 32
#define GROWB 80                 // row stride bytes
#define GBUFB (128 * 80)         // one buffer (one array) bytes = 10240
#define GEMM_SMEM (6 * GBUFB)    // 3 stages x (A + B) = 61440

__global__ __launch_bounds__(256, 2) void tgemm_kernel(
    const half* __restrict__ A, const half* __restrict__ Bm,
    const float* __restrict__ bias, const float* __restrict__ res,
    float* __restrict__ Cf, half* __restrict__ Ch,
    int M, int N, int K, int mode)
{
    extern __shared__ __align__(16) half smg[];
    uint32_t smBase = (uint32_t)__cvta_generic_to_shared(smg);
    const uint32_t BOFF = 3 * GBUFB;

    int tid  = threadIdx.x;
    int wid  = tid >> 5;
    int lane = tid & 31;
    int grp  = lane >> 2;
    int tig  = lane & 3;
    int warp_m = (wid & 1) * 64;
    int warp_n = (wid >> 1) * 32;

    int lrow = tid >> 2;
    int lc   = tid & 3;

    const half* Ap  = A + (size_t)(blockIdx.y * 128 + lrow) * K + lc * 8;
    const half* Ap2 = Ap + (size_t)64 * K;
    int gn  = blockIdx.x * 128 + lrow;
    int gn2 = gn + 64;
    bool bp  = gn  < N;
    bool bp2 = gn2 < N;
    const half* Bp  = Bm + (size_t)(bp  ? gn  : 0) * K + lc * 8;
    const half* Bp2 = Bm + (size_t)(bp2 ? gn2 : 0) * K + lc * 8;

    uint32_t aDst  = smBase + lrow * GROWB + lc * 16;
    uint32_t aDst2 = aDst + 64 * GROWB;
    uint32_t bDst  = smBase + BOFF + lrow * GROWB + lc * 16;
    uint32_t bDst2 = bDst + 64 * GROWB;

    uint32_t aLd = smBase + (warp_m + (lane & 7) + ((lane >> 3) & 1) * 8) * GROWB
                 + (lane >> 4) * 16;
    uint32_t bLd = smBase + BOFF + (warp_n + (lane & 7) + (lane >> 4) * 8) * GROWB
                 + ((lane >> 3) & 1) * 16;

    float acc[4][4][4];
    #pragma unroll
    for (int i = 0; i < 4; i++)
        #pragma unroll
        for (int j = 0; j < 4; j++)
            #pragma unroll
            for (int r = 0; r < 4; r++) acc[i][j][r] = 0.f;

    int nstage = K / BK2;

    {
        cp16(aDst, Ap, true);  cp16(aDst2, Ap2, true);
        cp16(bDst, Bp, bp);    cp16(bDst2, Bp2, bp2);
        cp_commit();
        if (nstage > 1) {
            cp16(aDst + GBUFB, Ap + BK2, true);  cp16(aDst2 + GBUFB, Ap2 + BK2, true);
            cp16(bDst + GBUFB, Bp + BK2, bp);    cp16(bDst2 + GBUFB, Bp2 + BK2, bp2);
            cp_commit();
        }
    }

    int cur = 0;
    for (int s = 0; s < nstage; s++) {
        if (s + 1 < nstage) cp_wait1(); else cp_wait0();
        __syncthreads();

        if (s + 2 < nstage) {
            int ib = cur + 2; if (ib >= 3) ib -= 3;
            uint32_t io = ib * GBUFB;
            int k0 = (s + 2) * BK2;
            cp16(aDst + io, Ap + k0, true);  cp16(aDst2 + io, Ap2 + k0, true);
            cp16(bDst + io, Bp + k0, bp);    cp16(bDst2 + io, Bp2 + k0, bp2);
            cp_commit();
        }

        uint32_t bo = cur * GBUFB;
        #pragma unroll
        for (int ks = 0; ks < 2; ks++) {
            uint32_t af[4][4];
            #pragma unroll
            for (int i = 0; i < 4; i++)
                ldsm_x4(af[i], aLd + bo + i * (16 * GROWB) + ks * 32);
            uint32_t bq[2][4];
            #pragma unroll
            for (int jb = 0; jb < 2; jb++)
                ldsm_x4(bq[jb], bLd + bo + jb * (16 * GROWB) + ks * 32);
            #pragma unroll
            for (int i = 0; i < 4; i++)
                #pragma unroll
                for (int j = 0; j < 4; j++)
                    mma_f16(acc[i][j], af[i], &bq[j >> 1][2 * (j & 1)]);
        }

        cur = (cur == 2) ? 0 : cur + 1;
    }

    #pragma unroll
    for (int i = 0; i < 4; i++) {
        int row0 = blockIdx.y * 128 + warp_m + i * 16 + grp;
        #pragma unroll
        for (int j = 0; j < 4; j++) {
            int col = blockIdx.x * 128 + warp_n + j * 8 + 2 * tig;
            if (col < N) {
                #pragma unroll
                for (int hf = 0; hf < 2; hf++) {
                    int r = row0 + hf * 8;
                    size_t rb = (size_t)r * N;
                    float v0 = acc[i][j][hf * 2 + 0];
                    float v1 = acc[i][j][hf * 2 + 1];
                    if (mode >= 1) { v0 += bias[col]; v1 += bias[col + 1]; }
                    if (mode == 2) { v0 = fmaxf(v0, 0.f); v1 = fmaxf(v1, 0.f); }
                    if (mode == 0 || mode == 2) {
                        *(half2*)(Ch + rb + col) = __floats2half2_rn(v0, v1);
                    } else {
                        if (mode == 3) { v0 += res[rb + col]; v1 += res[rb + col + 1]; }
                        *(float2*)(Cf + rb + col) = make_float2(v0, v1);
                    }
                }
            }
        }
    }
}

// ------------------------- fp16 flash attention (P in registers) -----------
// 128 queries/block, 8 warps x 16 query-rows, 64-key tiles double-buffered.
// K buf b at b*9216; V buf b at 18432 + b*9216. No P smem: QK accumulator
// fragments convert directly into PV A-operand registers.
#define KROWB 144
#define KVBUF (64 * KROWB)            // 9216
#define ATTN_SMEM (4 * KVBUF)         // 36864

__global__ __launch_bounds__(256, 2) void attn_kernel(const half* __restrict__ QKV,
                                                      half* __restrict__ O) {
    extern __shared__ __align__(16) half sma[];
    uint32_t smBase = (uint32_t)__cvta_generic_to_shared(sma);

    int b = blockIdx.y >> 3, h = blockIdx.y & 7;
    int qb = blockIdx.x * 128;
    int tid = threadIdx.x, wid = tid >> 5, lane = tid & 31;
    int grp = lane >> 2, tig = lane & 3;
    // scale * log2(e): softmax computed in exp2 domain
    const float scale2 = 0.04419417382415922f * 1.4426950408889634f;

    int lr0 = wid * 16 + grp;
    int lr1 = lr0 + 8;
    int gr0 = qb + lr0, gr1 = qb + lr1;

    const half* q0p = QKV + ((size_t)(b * T_) + gr0) * 1536 + h * 64;
    const half* q1p = QKV + ((size_t)(b * T_) + gr1) * 1536 + h * 64;
    uint32_t qa[4][4];
    #pragma unroll
    for (int k = 0; k < 4; k++) {
        int dd = 16 * k + 2 * tig;
        #pragma unroll
        for (int r = 0; r < 4; r++) {
            const half* qp = (r & 1) ? q1p : q0p;
            int d2 = dd + (r >> 1) * 8;
            float2 f = __half22float2(*(const half2*)(qp + d2));
            half2 hv = __floats2half2_rn(f.x * scale2, f.y * scale2);
            qa[k][r] = *(uint32_t*)&hv;
        }
    }

    uint32_t kLd = smBase + ((lane & 7) + (lane >> 4) * 8) * KROWB
                 + ((lane >> 3) & 1) * 16;
    uint32_t vLd = smBase + 2 * KVBUF + ((lane & 7) + ((lane >> 3) & 1) * 8) * KROWB
                 + (lane >> 4) * 16;

    int key4 = tid >> 2, c4 = tid & 3;
    int dh = 8 * c4;
    uint32_t kDst = smBase + key4 * KROWB + dh * 2;
    uint32_t vDst = kDst + 2 * KVBUF;
    const half* kvb = QKV + (size_t)(b * T_) * 1536 + h * 64 + D_;
    const half* kRow = kvb + (size_t)key4 * 1536 + dh;

    float o[8][4];
    #pragma unroll
    for (int j = 0; j < 8; j++) { o[j][0] = o[j][1] = o[j][2] = o[j][3] = 0.f; }
    float m0 = -1e30f, m1 = -1e30f, l0 = 0.f, l1 = 0.f;

    int ntiles = (qb >> 6) + 2;

    {
        cp16(kDst,      kRow,        true);
        cp16(kDst + 64, kRow + 32,   true);
        cp16(vDst,      kRow + 512,  true);
        cp16(vDst + 64, kRow + 544,  true);
        cp_commit();
    }

    for (int t = 0; t < ntiles; t++) {
        cp_wait0();
        __syncthreads();

        if (t + 1 < ntiles) {
            uint32_t io = ((t + 1) & 1) * KVBUF;
            const half* kr = kRow + (size_t)(t + 1) * 64 * 1536;
            cp16(kDst + io,      kr,       true);
            cp16(kDst + io + 64, kr + 32,  true);
            cp16(vDst + io,      kr + 512, true);
            cp16(vDst + io + 64, kr + 544, true);
            cp_commit();
        }

        uint32_t bo = (t & 1) * KVBUF;
        int k0 = t * 64;

        // S = Q @ K^T (exp2-scaled)
        float sc[8][4];
        #pragma unroll
        for (int j = 0; j < 8; j++) { sc[j][0] = sc[j][1] = sc[j][2] = sc[j][3] = 0.f; }
        #pragma unroll
        for (int kd = 0; kd < 4; kd++) {
            uint32_t kq[4][4];
            #pragma unroll
            for (int jp = 0; jp < 4; jp++)
                ldsm_x4(kq[jp], kLd + bo + jp * (16 * KROWB) + kd * 32);
            #pragma unroll
            for (int j = 0; j < 8; j++)
                mma_f16(sc[j], qa[kd], &kq[j >> 1][2 * (j & 1)]);
        }

        if (k0 + 63 > qb + wid * 16) {
            #pragma unroll
            for (int j = 0; j < 8; j++) {
                int key = k0 + 8 * j + 2 * tig;
                if (key     > gr0) sc[j][0] = -1e30f;
                if (key + 1 > gr0) sc[j][1] = -1e30f;
                if (key     > gr1) sc[j][2] = -1e30f;
                if (key + 1 > gr1) sc[j][3] = -1e30f;
            }
        }

        // online softmax (exp2 domain)
        float mx0 = -1e30f, mx1 = -1e30f;
        #pragma unroll
        for (int j = 0; j < 8; j++) {
            mx0 = fmaxf(mx0, fmaxf(sc[j][0], sc[j][1]));
            mx1 = fmaxf(mx1, fmaxf(sc[j][2], sc[j][3]));
        }
        mx0 = fmaxf(mx0, __shfl_xor_sync(0xffffffffu, mx0, 1));
        mx0 = fmaxf(mx0, __shfl_xor_sync(0xffffffffu, mx0, 2));
        mx1 = fmaxf(mx1, __shfl_xor_sync(0xffffffffu, mx1, 1));
        mx1 = fmaxf(mx1, __shfl_xor_sync(0xffffffffu, mx1, 2));
        float mn0 = fmaxf(m0, mx0), mn1 = fmaxf(m1, mx1);
        float c0 = exp2f(m0 - mn0), c1 = exp2f(m1 - mn1);
        m0 = mn0; m1 = mn1;

        // p = exp2(s - m), packed DIRECTLY into PV A-operand fragments:
        // pf[k] covers keys 16k..16k+15 = quadrants of sc[2k], sc[2k+1].
        uint32_t pf[4][4];
        float s0 = 0.f, s1 = 0.f;
        #pragma unroll
        for (int k = 0; k < 4; k++) {
            float p00 = exp2f(sc[2 * k][0] - m0);
            float p01 = exp2f(sc[2 * k][1] - m0);
            float p02 = exp2f(sc[2 * k][2] - m1);
            float p03 = exp2f(sc[2 * k][3] - m1);
            float p10 = exp2f(sc[2 * k + 1][0] - m0);
            float p11 = exp2f(sc[2 * k + 1][1] - m0);
            float p12 = exp2f(sc[2 * k + 1][2] - m1);
            float p13 = exp2f(sc[2 * k + 1][3] - m1);
            s0 += p00 + p01 + p10 + p11;
            s1 += p02 + p03 + p12 + p13;
            half2 h0 = __floats2half2_rn(p00, p01);
            half2 h1 = __floats2half2_rn(p02, p03);
            half2 h2 = __floats2half2_rn(p10, p11);
            half2 h3 = __floats2half2_rn(p12, p13);
            pf[k][0] = *(uint32_t*)&h0;
            pf[k][1] = *(uint32_t*)&h1;
            pf[k][2] = *(uint32_t*)&h2;
            pf[k][3] = *(uint32_t*)&h3;
        }
        s0 += __shfl_xor_sync(0xffffffffu, s0, 1);
        s0 += __shfl_xor_sync(0xffffffffu, s0, 2);
        s1 += __shfl_xor_sync(0xffffffffu, s1, 1);
        s1 += __shfl_xor_sync(0xffffffffu, s1, 2);
        l0 = l0 * c0 + s0;
        l1 = l1 * c1 + s1;
        #pragma unroll
        for (int j = 0; j < 8; j++) {
            o[j][0] *= c0; o[j][1] *= c0; o[j][2] *= c1; o[j][3] *= c1;
        }

        // O += P @ V (A = pf registers, B = V via ldmatrix.trans)
        #pragma unroll
        for (int kd = 0; kd < 4; kd++) {
            uint32_t vq[4][4];
            #pragma unroll
            for (int jp = 0; jp < 4; jp++)
                ldsm_x4_t(vq[jp], vLd + bo + kd * (16 * KROWB) + jp * 32);
            #pragma unroll
            for (int j = 0; j < 8; j++)
                mma_f16(o[j], pf[kd], &vq[j >> 1][2 * (j & 1)]);
        }
    }

    float i0 = 1.f / l0, i1 = 1.f / l1;
    size_t ob0 = ((size_t)(b * T_) + gr0) * D_ + h * 64;
    size_t ob1 = ((size_t)(b * T_) + gr1) * D_ + h * 64;
    #pragma unroll
    for (int j = 0; j < 8; j++) {
        int c = 8 * j + 2 * tig;
        *(half2*)(O + ob0 + c) = __floats2half2_rn(o[j][0] * i0, o[j][1] * i0);
        *(half2*)(O + ob1 + c) = __floats2half2_rn(o[j][2] * i1, o[j][3] * i1);
    }
}

// ------------------------- loss --------------------------------------------
__global__ __launch_bounds__(256) void loss_kernel(const float* __restrict__ logits,
                                                   const int* __restrict__ targets,
                                                   double* __restrict__ acc) {
    int warp = (blockIdx.x * blockDim.x + threadIdx.x) >> 5;
    int lane = threadIdx.x & 31;
    const float* lr = logits + (size_t)warp * V_;
    float v0 = lr[lane], v1 = lr[lane + 32], v2 = lr[lane + 64];
    float m = fmaxf(v0, fmaxf(v1, v2));
    #pragma unroll
    for (int o = 16; o; o >>= 1) m = fmaxf(m, __shfl_xor_sync(0xffffffffu, m, o));
    float se = expf(v0 - m) + expf(v1 - m) + expf(v2 - m);
    #pragma unroll
    for (int o = 16; o; o >>= 1) se += __shfl_xor_sync(0xffffffffu, se, o);

    __shared__ float part[8];
    if (lane == 0) part[threadIdx.x >> 5] = lr[targets[warp]] - m - logf(se);
    __syncthreads();
    if (threadIdx.x == 0) {
        float s = 0.f;
        #pragma unroll
        for (int i = 0; i < 8; i++) s += part[i];
        atomicAdd(acc, (double)s);
    }
}

__global__ void finalize_loss_kernel(float* out, const double* acc) {
    out[(size_t)BT_ * V_] = (float)(-(*acc) / (double)BT_);
}

// ------------------------- launcher ----------------------------------------
extern "C" void kernel_launch(void* const* d_in, const int* in_sizes, int n_in,
                              void* d_out, int out_size) {
    const int*   idx     = (const int*)  d_in[0];
    const int*   targets = (const int*)  d_in[1];
    const float* tok     = (const float*)d_in[2];
    const float* pos     = (const float*)d_in[3];
    const float* Wq      = (const float*)d_in[4];
    const float* Wk      = (const float*)d_in[5];
    const float* Wv      = (const float*)d_in[6];
    const float* Wproj   = (const float*)d_in[7];
    const float* bproj   = (const float*)d_in[8];
    const float* W1      = (const float*)d_in[9];
    const float* b1      = (const float*)d_in[10];
    const float* W2      = (const float*)d_in[11];
    const float* b2      = (const float*)d_in[12];
    const float* ln1_s   = (const float*)d_in[13];
    const float* ln1_b   = (const float*)d_in[14];
    const float* ln2_s   = (const float*)d_in[15];
    const float* ln2_b   = (const float*)d_in[16];
    const float* lnf_s   = (const float*)d_in[17];
    const float* lnf_b   = (const float*)d_in[18];
    const float* Wout    = (const float*)d_in[19];
    const float* bout    = (const float*)d_in[20];
    float* out = (float*)d_out;

    float* x;
    half *h, *qkv, *o, *ff, *wqkv, *wproj, *w1, *w2, *wout;
    double* lossAcc;
    cudaGetSymbolAddress((void**)&x,    g_x);
    cudaGetSymbolAddress((void**)&qkv,  g_qkv);
    cudaGetSymbolAddress((void**)&h,    g_h);
    cudaGetSymbolAddress((void**)&o,    g_o);
    cudaGetSymbolAddress((void**)&ff,   g_ff);
    cudaGetSymbolAddress((void**)&wqkv, g_wqkv);
    cudaGetSymbolAddress((void**)&wproj, g_wproj);
    cudaGetSymbolAddress((void**)&w1,   g_w1);
    cudaGetSymbolAddress((void**)&w2,   g_w2);
    cudaGetSymbolAddress((void**)&wout, g_wout);
    cudaGetSymbolAddress((void**)&lossAcc, g_loss);

    cudaFuncSetAttribute(tgemm_kernel,
                         cudaFuncAttributeMaxDynamicSharedMemorySize, GEMM_SMEM);
    cudaFuncSetAttribute(attn_kernel,
                         cudaFuncAttributeMaxDynamicSharedMemorySize, ATTN_SMEM);

    // weight packing (coalesced transposes, fp16)
    {
        dim3 blk(32, 8);
        pack_qkv_kernel<<<dim3(D_ / 32, HS_ / 32, L_ * 3 * H_), blk>>>(Wq, Wk, Wv, wqkv);
        pack_wt_kernel<<<dim3(D_ / 32, D_ / 32, L_), blk>>>(Wproj, wproj, D_, D_);
        pack_wt_kernel<<<dim3(FF_ / 32, D_ / 32, L_), blk>>>(W1, w1, D_, FF_);
        pack_wt_kernel<<<dim3(D_ / 32, FF_ / 32, L_), blk>>>(W2, w2, FF_, D_);
        pack_wt_kernel<<<dim3(V_ / 32, D_ / 32, 1), blk>>>(Wout, wout, D_, V_);
    }
    {
        int total = BT_ * D_;
        embed_kernel<<<(total + 255) / 256, 256>>>(idx, tok, pos, x);
    }

    const int MT = BT_ / 128;  // 128 M-tiles
    const int LNG = BT_ / 8;   // LN grid (8 rows/block)
    for (int l = 0; l < L_; l++) {
        ln_kernel<<<LNG, 256>>>(x, ln1_s + l * D_, ln1_b + l * D_, h);
        tgemm_kernel<<<dim3(12, MT), 256, GEMM_SMEM>>>(
            h, wqkv + (size_t)l * 3 * D_ * D_,
            nullptr, nullptr, nullptr, qkv, BT_, 3 * D_, D_, 0);
        attn_kernel<<<dim3(T_ / 128, B_ * H_), 256, ATTN_SMEM>>>(qkv, o);
        tgemm_kernel<<<dim3(4, MT), 256, GEMM_SMEM>>>(
            o, wproj + (size_t)l * D_ * D_,
            bproj + l * D_, x, x, nullptr, BT_, D_, D_, 3);
        ln_kernel<<<LNG, 256>>>(x, ln2_s + l * D_, ln2_b + l * D_, h);
        tgemm_kernel<<<dim3(16, MT), 256, GEMM_SMEM>>>(
            h, w1 + (size_t)l * FF_ * D_,
            b1 + l * FF_, nullptr, nullptr, ff, BT_, FF_, D_, 2);
        tgemm_kernel<<<dim3(4, MT), 256, GEMM_SMEM>>>(
            ff, w2 + (size_t)l * D_ * FF_,
            b2 + l * D_, x, x, nullptr, BT_, D_, FF_, 3);
    }

    ln_kernel<<<LNG, 256>>>(x, lnf_s, lnf_b, h);
    tgemm_kernel<<<dim3(1, MT), 256, GEMM_SMEM>>>(
        h, wout, bout, nullptr, out, nullptr, BT_, V_, D_, 1);

    if (out_size > BT_ * V_) {
        zero_loss_kernel<<<1, 1>>>(lossAcc);
        loss_kernel<<<BT_ / 8, 256>>>(out, targets, lossAcc);
        finalize_loss_kernel<<<1, 1>>>(out, lossAcc);
    }
}